// round 7
// baseline (speedup 1.0000x reference)
#include <cuda_runtime.h>
#include <cuda_bf16.h>
#include <math.h>
#include <stdint.h>

// Problem dims
#define SEQ_LEN 12
#define BATCH   512
#define NG      16
#define GROUP   32
#define HD      128      // H
#define ED      64       // E
#define PRE     512
#define BOTTLE  1024
#define MLPD    1024
#define GATES   (4*HD)   // 512
#define KCAT    (ED+HD)  // 192
#define ROWS_PN (NG*GROUP*GROUP)  // 16384
#define DHK     (HD+BOTTLE)       // 1152

// ---------------- scratch (device globals; no allocation) ----------------
__device__ float g_h[BATCH*HD];
__device__ float g_c[BATCH*HD];
__device__ float g_pos[BATCH*2];
__device__ float g_decin[BATCH*ED];
__device__ float g_acat[BATCH*KCAT];
__device__ float g_Wcat[GATES*KCAT];
__device__ float g_bsum[GATES];
__device__ float g_gates[BATCH*GATES];
__device__ __align__(16) __nv_bfloat16 g_embhi[ROWS_PN*ED];
__device__ __align__(16) __nv_bfloat16 g_emblo[ROWS_PN*ED];
__device__ __align__(16) __nv_bfloat16 g_W1ehi[PRE*ED];
__device__ __align__(16) __nv_bfloat16 g_W1elo[PRE*ED];
__device__ float g_hW1h[BATCH*PRE];
__device__ __align__(16) float  g_X1f[ROWS_PN*PRE];        // fp32 X1
__device__ __align__(16) int8_t g_qAhi[ROWS_PN*PRE];       // X1 16-bit fixed: hi limb
__device__ __align__(16) int8_t g_qAlo[ROWS_PN*PRE];       // lo limb
__device__ __align__(16) int8_t g_qBhi[BOTTLE*PRE];        // W2 limbs
__device__ __align__(16) int8_t g_qBlo[BOTTLE*PRE];
__device__ float g_sB[BOTTLE];                             // per-row W2 scale units
__device__ unsigned g_scaleA_u;                            // X1 max (fp32 bits, >=0)
__device__ float g_pool[BATCH*BOTTLE];
__device__ float g_dcat[BATCH*DHK];
__device__ float g_D1[BATCH*MLPD];
__device__ float g_loss;

__device__ __forceinline__ float sigmoidf(float x) { return 1.0f / (1.0f + expf(-x)); }

// ---------------- PTX helpers (base-arch only: sm_80+ features) ----------------
__device__ __forceinline__ uint32_t smem_u32(const void* p) {
    uint32_t a;
    asm("{ .reg .u64 t; cvta.to.shared.u64 t, %1; cvt.u32.u64 %0, t; }" : "=r"(a) : "l"(p));
    return a;
}
__device__ __forceinline__ void cp_async16(uint32_t s, const void* g) {
    asm volatile("cp.async.cg.shared.global [%0], [%1], 16;" :: "r"(s), "l"(g));
}
#define CP_COMMIT() asm volatile("cp.async.commit_group;" ::: "memory")
#define CP_WAIT1()  asm volatile("cp.async.wait_group 1;" ::: "memory")
#define CP_WAIT0()  asm volatile("cp.async.wait_group 0;" ::: "memory")

__device__ __forceinline__ void ldmatrix_x4(uint32_t* r, uint32_t addr) {
    asm volatile("ldmatrix.sync.aligned.m8n8.x4.shared.b16 {%0,%1,%2,%3}, [%4];"
                 : "=r"(r[0]), "=r"(r[1]), "=r"(r[2]), "=r"(r[3]) : "r"(addr));
}
__device__ __forceinline__ void mma_bf16(float* c, const uint32_t* a, uint32_t b0, uint32_t b1) {
    asm volatile("mma.sync.aligned.m16n8k16.row.col.f32.bf16.bf16.f32 "
                 "{%0,%1,%2,%3}, {%4,%5,%6,%7}, {%8,%9}, {%0,%1,%2,%3};"
                 : "+f"(c[0]), "+f"(c[1]), "+f"(c[2]), "+f"(c[3])
                 : "r"(a[0]), "r"(a[1]), "r"(a[2]), "r"(a[3]), "r"(b0), "r"(b1));
}
__device__ __forceinline__ void mma_s8(int* c, const uint32_t* a, uint32_t b0, uint32_t b1) {
    asm volatile("mma.sync.aligned.m16n8k32.row.col.s32.s8.s8.s32 "
                 "{%0,%1,%2,%3}, {%4,%5,%6,%7}, {%8,%9}, {%0,%1,%2,%3};"
                 : "+r"(c[0]), "+r"(c[1]), "+r"(c[2]), "+r"(c[3])
                 : "r"(a[0]), "r"(a[1]), "r"(a[2]), "r"(a[3]), "r"(b0), "r"(b1));
}

// ---------------- init ----------------
__global__ void init_kernel(const float* __restrict__ hh, const float* __restrict__ ch,
                            const float* __restrict__ last_pos, const float* __restrict__ last_pos_rel,
                            const float* __restrict__ Wih, const float* __restrict__ Whh,
                            const float* __restrict__ bih, const float* __restrict__ bhh,
                            const float* __restrict__ Wse, const float* __restrict__ bse,
                            const float* __restrict__ W1) {
    int idx = blockIdx.x * blockDim.x + threadIdx.x;
    if (idx < BATCH*HD) { g_h[idx] = hh[idx]; g_c[idx] = ch[idx]; }
    if (idx < BATCH*2)  g_pos[idx] = last_pos[idx];
    if (idx < BATCH*ED) {
        int b = idx / ED, e = idx % ED;
        g_decin[idx] = last_pos_rel[b*2] * Wse[e*2] + last_pos_rel[b*2+1] * Wse[e*2+1] + bse[e];
    }
    if (idx < GATES) g_bsum[idx] = bih[idx] + bhh[idx];
    if (idx < GATES*KCAT) {
        int n = idx / KCAT, k = idx % KCAT;
        g_Wcat[idx] = (k < ED) ? Wih[n*ED + k] : Whh[n*HD + (k - ED)];
    }
    if (idx < PRE*ED) {
        int n = idx >> 6, k = idx & 63;
        float w = W1[n*KCAT + k];
        __nv_bfloat16 hi = __float2bfloat16(w);
        g_W1ehi[idx] = hi;
        g_W1elo[idx] = __float2bfloat16(w - __bfloat162float(hi));
    }
    if (idx == 0) g_loss = 0.0f;
}

// W2 int8 16-bit fixed-point quantization: one warp per output row n.
__global__ void w2q_kernel(const float* __restrict__ W2) {
    int n = blockIdx.x * 8 + (threadIdx.x >> 5);
    int lane = threadIdx.x & 31;
    const float* row = W2 + (size_t)n * PRE;
    float m = 0.0f;
    for (int k = lane; k < PRE; k += 32) m = fmaxf(m, fabsf(row[k]));
    #pragma unroll
    for (int d = 16; d > 0; d >>= 1) m = fmaxf(m, __shfl_xor_sync(0xffffffffu, m, d));
    float inv = (m > 0.0f) ? 32512.0f / m : 0.0f;
    if (lane == 0) g_sB[n] = m / 32512.0f;
    for (int k = lane; k < PRE; k += 32) {
        int q = __float2int_rn(row[k] * inv);
        int hi = (q + 128) >> 8;               // round(q/256) in [-127,127]
        g_qBhi[(size_t)n*PRE + k] = (int8_t)hi;
        g_qBlo[(size_t)n*PRE + k] = (int8_t)(q - (hi << 8));
    }
}

// ---------------- packs ----------------
__global__ void pack_lstm_kernel() {
    int idx = blockIdx.x * blockDim.x + threadIdx.x;
    if (idx >= BATCH*KCAT) return;
    int b = idx / KCAT, k = idx % KCAT;
    g_acat[idx] = (k < ED) ? g_decin[b*ED + k] : g_h[b*HD + (k - ED)];
}

__global__ void pack_dh_kernel() {
    int idx = blockIdx.x * blockDim.x + threadIdx.x;
    if (idx >= BATCH*DHK) return;
    int b = idx / DHK, k = idx % DHK;
    g_dcat[idx] = (k < HD) ? g_h[b*HD + k] : g_pool[b*BOTTLE + (k - HD)];
}

// ---------------- LSTM elementwise ----------------
__global__ void lstm_elem_kernel() {
    int idx = blockIdx.x * blockDim.x + threadIdx.x;
    if (idx >= BATCH*HD) return;
    int b = idx / HD, j = idx % HD;
    const float* gr = g_gates + b*GATES;
    float ig = gr[j], fg = gr[HD + j], gg = gr[2*HD + j], og = gr[3*HD + j];
    float c = sigmoidf(fg) * g_c[idx] + sigmoidf(ig) * tanhf(gg);
    g_c[idx] = c;
    g_h[idx] = sigmoidf(og) * tanhf(c);
}

// ---------------- rel_pos, curr_pos, pred output, loss ----------------
__global__ void pos_loss_kernel(const float* __restrict__ Wpos, const float* __restrict__ bpos,
                                const float* __restrict__ gt, float* __restrict__ out_pred) {
    int b = threadIdx.x;
    const float* hr = g_h + b*HD;
    float ax = 0.f, ay = 0.f;
    #pragma unroll 8
    for (int k = 0; k < HD; k++) { float hv = hr[k]; ax += hv * Wpos[k]; ay += hv * Wpos[HD + k]; }
    float rx = ax + bpos[0], ry = ay + bpos[1];
    out_pred[b*2]   = rx;
    out_pred[b*2+1] = ry;
    g_pos[b*2]   += rx;
    g_pos[b*2+1] += ry;
    float dx = rx - gt[b*2], dy = ry - gt[b*2+1];
    __shared__ float sd[BATCH];
    sd[b] = dx*dx + dy*dy;
    __syncthreads();
    for (int s = BATCH/2; s > 0; s >>= 1) {
        if (b < s) sd[b] += sd[b + s];
        __syncthreads();
    }
    if (b == 0) g_loss += sd[0] / (float)(BATCH*2);
}

// ---------------- pairwise rel-pos embedding -> bf16 hi/lo (+ scaleA reset) ----------------
__global__ void emb_kernel(const float* __restrict__ Wp, const float* __restrict__ bp) {
    int idx = blockIdx.x * blockDim.x + threadIdx.x;
    if (idx == 0) g_scaleA_u = 0u;
    if (idx >= ROWS_PN*ED) return;
    int r = idx >> 6, e = idx & 63;
    int g = r >> 10, i = (r >> 5) & 31, j = r & 31;
    int bi = g*GROUP + i, bj = g*GROUP + j;
    float rx = g_pos[bj*2]   - g_pos[bi*2];
    float ry = g_pos[bj*2+1] - g_pos[bi*2+1];
    float v = rx * Wp[e*2] + ry * Wp[e*2+1] + bp[e];
    __nv_bfloat16 hi = __float2bfloat16(v);
    g_embhi[idx] = hi;
    g_emblo[idx] = __float2bfloat16(v - __bfloat162float(hi));
}

// ---------------- next dec_in ----------------
__global__ void decin_kernel(const float* __restrict__ gt,
                             const float* __restrict__ Wse, const float* __restrict__ bse) {
    int idx = blockIdx.x * blockDim.x + threadIdx.x;
    if (idx >= BATCH*ED) return;
    int b = idx / ED, e = idx % ED;
    g_decin[idx] = gt[b*2] * Wse[e*2] + gt[b*2+1] * Wse[e*2+1] + bse[e];
}

__global__ void finish_kernel(float* __restrict__ out, int out_size) {
    if (out_size > SEQ_LEN*BATCH*2) out[SEQ_LEN*BATCH*2] = g_loss;
}

// ---------------- X1 -> int8 limbs (per-tensor scale from g_scaleA) ----------------
__global__ void quant_x1_kernel() {
    int i = blockIdx.x * blockDim.x + threadIdx.x;  // over float4s
    float s = __uint_as_float(g_scaleA_u);
    float inv = (s > 0.0f) ? 32512.0f / s : 0.0f;
    float4 x = reinterpret_cast<const float4*>(g_X1f)[i];
    int q0 = __float2int_rn(x.x * inv);
    int q1 = __float2int_rn(x.y * inv);
    int q2 = __float2int_rn(x.z * inv);
    int q3 = __float2int_rn(x.w * inv);
    int h0 = (q0 + 128) >> 8, h1 = (q1 + 128) >> 8, h2 = (q2 + 128) >> 8, h3 = (q3 + 128) >> 8;
    char4 ch = make_char4((char)h0, (char)h1, (char)h2, (char)h3);
    char4 cl = make_char4((char)(q0 - (h0 << 8)), (char)(q1 - (h1 << 8)),
                          (char)(q2 - (h2 << 8)), (char)(q3 - (h3 << 8)));
    reinterpret_cast<char4*>(g_qAhi)[i] = ch;
    reinterpret_cast<char4*>(g_qAlo)[i] = cl;
}

// ---------------- SIMT SGEMM: C = A(MxK) * W(NxK)^T ----------------
template<int MODE>  // 0: store; 1: +bias; 2: relu(+bias)
__global__ void sgemm64(const float* __restrict__ A, int lda,
                        const float* __restrict__ W, int ldw,
                        float* __restrict__ C, int ldc, int K,
                        const float* __restrict__ bias) {
    __shared__ float As[64][17];
    __shared__ float Ws[64][17];
    int tid = threadIdx.x;
    int m0 = blockIdx.y * 64, n0 = blockIdx.x * 64;
    int ty = tid >> 4, tx = tid & 15;
    float acc[4][4] = {};

    for (int k0 = 0; k0 < K; k0 += 16) {
        #pragma unroll
        for (int l = tid; l < 64*16; l += 256) {
            int r = l >> 4, c = l & 15;
            As[r][c] = A[(m0 + r) * lda + k0 + c];
            Ws[r][c] = W[(n0 + r) * ldw + k0 + c];
        }
        __syncthreads();
        #pragma unroll
        for (int kk = 0; kk < 16; kk++) {
            float a[4], w[4];
            #pragma unroll
            for (int i = 0; i < 4; i++) { a[i] = As[ty*4 + i][kk]; w[i] = Ws[tx*4 + i][kk]; }
            #pragma unroll
            for (int i = 0; i < 4; i++)
                #pragma unroll
                for (int j = 0; j < 4; j++) acc[i][j] += a[i] * w[j];
        }
        __syncthreads();
    }

    #pragma unroll
    for (int i = 0; i < 4; i++) {
        int m = m0 + ty*4 + i;
        #pragma unroll
        for (int j = 0; j < 4; j++) {
            int n = n0 + tx*4 + j;
            float v = acc[i][j];
            if (MODE == 0) C[m*ldc + n] = v;
            else if (MODE == 1) C[m*ldc + n] = v + bias[n];
            else C[m*ldc + n] = fmaxf(v + bias[n], 0.0f);
        }
    }
}

// ---------------- X1 HMMA (bf16 3-term): X1 = relu(emb@W1e^T + hW1h[j] + b1) -> fp32 + max ----
#define HG_LDA     72
#define HG_ASTAGE  (256 * HG_LDA * 2)
#define HG_BSTAGE  (128 * HG_LDA * 2)
#define HG_STAGE   (HG_ASTAGE + HG_BSTAGE)
#define HG_DYN     (2 * HG_STAGE)

__global__ void __launch_bounds__(256, 1)
hgemm_x1(const float* __restrict__ bias, const float* __restrict__ aux) {
    extern __shared__ char dyn[];
    __shared__ float s_wmax[8];
    const int tid  = threadIdx.x;
    const int lane = tid & 31;
    const int wid  = tid >> 5;
    const int wm   = wid >> 1;      // 0..3
    const int wn   = wid & 1;       // 0..1
    const int n0 = blockIdx.x * 128;
    const int m0 = blockIdx.y * 256;

    uint32_t sbase = smem_u32(dyn);
    float acc[4][8][4] = {};

    const int a_row  = wm * 64 + (lane & 15);
    const int a_colg = (lane >> 4) * 8;
    const int b_sub  = ((lane >> 4) & 1) * 8 + (lane & 7);
    const int b_colg = ((lane >> 3) & 1) * 8;

    auto load_chunk = [&](int term, int s) {
        const __nv_bfloat16* Ap = (term == 1 ? g_emblo : g_embhi) + (size_t)m0 * ED;
        const __nv_bfloat16* Bp = (term == 2 ? g_W1elo : g_W1ehi) + (size_t)n0 * ED;
        uint32_t sA = sbase + s * HG_STAGE;
        uint32_t sB = sA + HG_ASTAGE;
        #pragma unroll
        for (int u = 0; u < 8; u++) {
            int idx = tid + u * 256;
            int row = idx >> 3, seg = idx & 7;
            cp_async16(sA + (uint32_t)(row * HG_LDA + seg * 8) * 2,
                       Ap + (size_t)row * ED + seg * 8);
        }
        #pragma unroll
        for (int u = 0; u < 4; u++) {
            int idx = tid + u * 256;
            int row = idx >> 3, seg = idx & 7;
            cp_async16(sB + (uint32_t)(row * HG_LDA + seg * 8) * 2,
                       Bp + (size_t)row * ED + seg * 8);
        }
    };

    load_chunk(0, 0);
    CP_COMMIT();

    for (int c = 0; c < 3; c++) {
        if (c + 1 < 3) { load_chunk(c + 1, (c + 1) & 1); CP_COMMIT(); CP_WAIT1(); }
        else CP_WAIT0();
        __syncthreads();

        uint32_t sA = sbase + (c & 1) * HG_STAGE;
        uint32_t sB = sA + HG_ASTAGE;
        #pragma unroll
        for (int ks = 0; ks < 4; ks++) {
            uint32_t afr[4][4];
            #pragma unroll
            for (int mf = 0; mf < 4; mf++)
                ldmatrix_x4(afr[mf], sA + (uint32_t)((a_row + mf*16) * HG_LDA + ks*16 + a_colg) * 2);
            uint32_t bfr[4][4];
            #pragma unroll
            for (int nf2 = 0; nf2 < 4; nf2++)
                ldmatrix_x4(bfr[nf2], sB + (uint32_t)((wn*64 + nf2*16 + b_sub) * HG_LDA + ks*16 + b_colg) * 2);
            #pragma unroll
            for (int mf = 0; mf < 4; mf++)
                #pragma unroll
                for (int nf = 0; nf < 8; nf++)
                    mma_bf16(acc[mf][nf], afr[mf], bfr[nf>>1][(nf&1)*2], bfr[nf>>1][(nf&1)*2 + 1]);
        }
        __syncthreads();
    }

    float tmax = 0.0f;
    #pragma unroll
    for (int mf = 0; mf < 4; mf++) {
        int R  = m0 + wm*64 + mf*16 + (lane >> 2);
        int R8 = R + 8;
        const float* aux0 = aux + (size_t)((R  >> 10)*32 + (R  & 31)) * PRE;
        const float* aux8 = aux + (size_t)((R8 >> 10)*32 + (R8 & 31)) * PRE;
        #pragma unroll
        for (int nf = 0; nf < 8; nf++) {
            int n = n0 + wn*64 + nf*8 + (lane & 3)*2;
            float b0 = bias[n], b1v = bias[n + 1];
            float v0 = fmaxf(acc[mf][nf][0] + b0  + aux0[n],     0.0f);
            float v1 = fmaxf(acc[mf][nf][1] + b1v + aux0[n + 1], 0.0f);
            float v2 = fmaxf(acc[mf][nf][2] + b0  + aux8[n],     0.0f);
            float v3 = fmaxf(acc[mf][nf][3] + b1v + aux8[n + 1], 0.0f);
            tmax = fmaxf(tmax, fmaxf(fmaxf(v0, v1), fmaxf(v2, v3)));
            *reinterpret_cast<float2*>(&g_X1f[(size_t)R  * PRE + n]) = make_float2(v0, v1);
            *reinterpret_cast<float2*>(&g_X1f[(size_t)R8 * PRE + n]) = make_float2(v2, v3);
        }
    }
    #pragma unroll
    for (int d = 16; d > 0; d >>= 1) tmax = fmaxf(tmax, __shfl_xor_sync(0xffffffffu, tmax, d));
    if (lane == 0) s_wmax[wid] = tmax;
    __syncthreads();
    if (tid == 0) {
        float m = s_wmax[0];
        #pragma unroll
        for (int w = 1; w < 8; w++) m = fmaxf(m, s_wmax[w]);
        atomicMax(&g_scaleA_u, __float_as_uint(m));
    }
}

// ---------------- int8 GEMM2: pool = relu(max_j(X1 @ W2^T) + b2) ----------------
// 16-bit fixed-point split, 3 passes (hi*hi -> acc_hh; hi*lo + lo*hi -> acc_mid).
// CTA 128x128, 8 warps (2x4), warp 64x32. K-chunk 128 bytes, XOR-swizzled smem.
#define S8_STAGE 32768        // A 16KB + B 16KB
#define S8_DYN   (2 * S8_STAGE)

__global__ void __launch_bounds__(256, 1)
gemm2_s8(const float* __restrict__ b2, float* __restrict__ pool) {
    extern __shared__ char dyn[];
    const int tid  = threadIdx.x;
    const int lane = tid & 31;
    const int wid  = tid >> 5;
    const int wm   = wid >> 2;      // 0..1 (64 rows each)
    const int wn   = wid & 3;       // 0..3 (32 cols each)
    const int n0 = blockIdx.x * 128;
    const int m0 = blockIdx.y * 128;
    uint32_t sbase = smem_u32(dyn);

    int hh[4][4][4] = {};
    int mid[4][4][4] = {};

    auto load_chunk = [&](int c, int s) {
        int pass = c >> 2, kc = (c & 3) * 128;
        const int8_t* Ap = (pass == 2 ? g_qAlo : g_qAhi) + (size_t)m0 * PRE + kc;
        const int8_t* Bp = (pass == 1 ? g_qBlo : g_qBhi) + (size_t)n0 * PRE + kc;
        uint32_t sA = sbase + s * S8_STAGE;
        uint32_t sB = sA + 16384;
        #pragma unroll
        for (int u = 0; u < 4; u++) {
            int idx = tid + u * 256;            // 0..1023
            int row = idx >> 3, seg = idx & 7;
            uint32_t off = (uint32_t)row * 128 + (uint32_t)((seg ^ (row & 7)) * 16);
            cp_async16(sA + off, Ap + (size_t)row * PRE + seg * 16);
            cp_async16(sB + off, Bp + (size_t)row * PRE + seg * 16);
        }
    };

    load_chunk(0, 0);
    CP_COMMIT();

    for (int c = 0; c < 12; c++) {
        if (c + 1 < 12) { load_chunk(c + 1, (c + 1) & 1); CP_COMMIT(); CP_WAIT1(); }
        else CP_WAIT0();
        __syncthreads();

        uint32_t sA = sbase + (c & 1) * S8_STAGE;
        uint32_t sB = sA + 16384;
        int pass = c >> 2;
        #pragma unroll
        for (int ks = 0; ks < 4; ks++) {
            uint32_t afr[4][4];
            #pragma unroll
            for (int mf = 0; mf < 4; mf++) {
                int r = wm*64 + mf*16 + (lane & 15);
                int colu = ks*2 + (lane >> 4);
                ldmatrix_x4(afr[mf], sA + (uint32_t)r*128 + (uint32_t)((colu ^ (r & 7)) * 16));
            }
            uint32_t bfr[2][4];
            #pragma unroll
            for (int no = 0; no < 2; no++) {
                int r = wn*32 + no*16 + (lane & 15);
                int colu = ks*2 + (lane >> 4);
                ldmatrix_x4(bfr[no], sB + (uint32_t)r*128 + (uint32_t)((colu ^ (r & 7)) * 16));
            }
            if (pass == 0) {
                #pragma unroll
                for (int mf = 0; mf < 4; mf++)
                    #pragma unroll
                    for (int jj = 0; jj < 4; jj++)
                        mma_s8(hh[mf][jj], afr[mf], bfr[jj>>1][jj&1], bfr[jj>>1][(jj&1)+2]);
            } else {
                #pragma unroll
                for (int mf = 0; mf < 4; mf++)
                    #pragma unroll
                    for (int jj = 0; jj < 4; jj++)
                        mma_s8(mid[mf][jj], afr[mf], bfr[jj>>1][jj&1], bfr[jj>>1][(jj&1)+2]);
            }
        }
        __syncthreads();
    }

    // Epilogue: warp rows = two 32-row neighbor groups; max in regs + shfl.
    float sAu = __uint_as_float(g_scaleA_u) / 32512.0f;
    #pragma unroll
    for (int half = 0; half < 2; half++) {
        int pr = blockIdx.y * 4 + wm * 2 + half;    // pool row = m/32
        int mf0 = half * 2, mf1 = mf0 + 1;
        #pragma unroll
        for (int jj = 0; jj < 4; jj++) {
            float v0 = -3.0e38f, v1 = -3.0e38f;
            #pragma unroll
            for (int mfi = 0; mfi < 2; mfi++) {
                int mf = (mfi == 0) ? mf0 : mf1;
                v0 = fmaxf(v0, fmaxf(65536.0f*(float)hh[mf][jj][0] + 256.0f*(float)mid[mf][jj][0],
                                     65536.0f*(float)hh[mf][jj][2] + 256.0f*(float)mid[mf][jj][2]));
                v1 = fmaxf(v1, fmaxf(65536.0f*(float)hh[mf][jj][1] + 256.0f*(float)mid[mf][jj][1],
                                     65536.0f*(float)hh[mf][jj][3] + 256.0f*(float)mid[mf][jj][3]));
            }
            #pragma unroll
            for (int d = 4; d < 32; d <<= 1) {
                v0 = fmaxf(v0, __shfl_xor_sync(0xffffffffu, v0, d));
                v1 = fmaxf(v1, __shfl_xor_sync(0xffffffffu, v1, d));
            }
            if ((lane >> 2) == 0) {
                int n = n0 + wn*32 + (jj >> 1)*16 + (jj & 1)*8 + (lane & 3)*2;
                pool[pr * BOTTLE + n]     = fmaxf(v0 * sAu * g_sB[n]     + b2[n],     0.0f);
                pool[pr * BOTTLE + n + 1] = fmaxf(v1 * sAu * g_sB[n + 1] + b2[n + 1], 0.0f);
            }
        }
    }
}

// ---------------- launch ----------------
extern "C" void kernel_launch(void* const* d_in, const int* in_sizes, int n_in,
                              void* d_out, int out_size) {
    const float* last_pos      = (const float*)d_in[0];
    const float* last_pos_rel  = (const float*)d_in[1];
    const float* hh            = (const float*)d_in[2];
    const float* ch            = (const float*)d_in[3];
    const float* pred_traj_rel = (const float*)d_in[4];
    const float* W_ih = (const float*)d_in[6];
    const float* W_hh = (const float*)d_in[7];
    const float* b_ih = (const float*)d_in[8];
    const float* b_hh = (const float*)d_in[9];
    const float* Wse  = (const float*)d_in[10];
    const float* bse  = (const float*)d_in[11];
    const float* Wpos = (const float*)d_in[12];
    const float* bpos = (const float*)d_in[13];
    const float* Wp   = (const float*)d_in[14];
    const float* bp   = (const float*)d_in[15];
    const float* W1   = (const float*)d_in[16];
    const float* b1   = (const float*)d_in[17];
    const float* W2   = (const float*)d_in[18];
    const float* b2   = (const float*)d_in[19];
    const float* Wm1  = (const float*)d_in[20];
    const float* bm1  = (const float*)d_in[21];
    const float* Wm2  = (const float*)d_in[22];
    const float* bm2  = (const float*)d_in[23];

    float* out = (float*)d_out;

    float* p_h     = nullptr; cudaGetSymbolAddress((void**)&p_h,     g_h);
    float* p_acat  = nullptr; cudaGetSymbolAddress((void**)&p_acat,  g_acat);
    float* p_Wcat  = nullptr; cudaGetSymbolAddress((void**)&p_Wcat,  g_Wcat);
    float* p_bsum  = nullptr; cudaGetSymbolAddress((void**)&p_bsum,  g_bsum);
    float* p_gates = nullptr; cudaGetSymbolAddress((void**)&p_gates, g_gates);
    float* p_hW1h  = nullptr; cudaGetSymbolAddress((void**)&p_hW1h,  g_hW1h);
    float* p_pool  = nullptr; cudaGetSymbolAddress((void**)&p_pool,  g_pool);
    float* p_dcat  = nullptr; cudaGetSymbolAddress((void**)&p_dcat,  g_dcat);
    float* p_D1    = nullptr; cudaGetSymbolAddress((void**)&p_D1,    g_D1);

    cudaFuncSetAttribute(hgemm_x1, cudaFuncAttributeMaxDynamicSharedMemorySize, HG_DYN);
    cudaFuncSetAttribute(gemm2_s8, cudaFuncAttributeMaxDynamicSharedMemorySize, S8_DYN);

    init_kernel<<<(GATES*KCAT + 255)/256, 256>>>(hh, ch, last_pos, last_pos_rel,
                                                 W_ih, W_hh, b_ih, b_hh, Wse, bse, W1);
    w2q_kernel<<<BOTTLE/8, 256>>>(W2);

    for (int t = 0; t < SEQ_LEN; t++) {
        const float* gt = pred_traj_rel + t * BATCH * 2;
        float* out_pred = out + t * BATCH * 2;

        // LSTM cell
        pack_lstm_kernel<<<(BATCH*KCAT + 255)/256, 256>>>();
        sgemm64<1><<<dim3(GATES/64, BATCH/64), 256>>>(p_acat, KCAT, p_Wcat, KCAT,
                                                      p_gates, GATES, KCAT, p_bsum);
        lstm_elem_kernel<<<(BATCH*HD + 255)/256, 256>>>();

        // rel_pos / curr_pos / pred output / loss
        pos_loss_kernel<<<1, BATCH>>>(Wpos, bpos, gt, out_pred);

        // pool net
        emb_kernel<<<(ROWS_PN*ED + 255)/256, 256>>>(Wp, bp);
        sgemm64<0><<<dim3(PRE/64, BATCH/64), 256>>>(p_h, HD, W1 + ED, KCAT,
                                                    p_hW1h, PRE, HD, nullptr);
        // X1 = relu(emb @ W1e^T + hW1h[j] + b1) -> fp32 + running max
        hgemm_x1<<<dim3(PRE/128, ROWS_PN/256), 256, HG_DYN>>>(b1, p_hW1h);
        // quantize X1 to int8 limbs
        quant_x1_kernel<<<(ROWS_PN*PRE/4)/256, 256>>>();
        // pool = relu(max_j(X1 @ W2^T) + b2) via int8 IMMA
        gemm2_s8<<<dim3(BOTTLE/128, ROWS_PN/128), 256, S8_DYN>>>(b2, p_pool);

        // decoder MLP
        pack_dh_kernel<<<(BATCH*DHK + 255)/256, 256>>>();
        sgemm64<2><<<dim3(MLPD/64, BATCH/64), 256>>>(p_dcat, DHK, Wm1, DHK,
                                                     p_D1, MLPD, DHK, bm1);
        sgemm64<2><<<dim3(HD/64, BATCH/64), 256>>>(p_D1, MLPD, Wm2, MLPD,
                                                   p_h, HD, MLPD, bm2);

        decin_kernel<<<(BATCH*ED + 255)/256, 256>>>(gt, Wse, bse);
    }

    finish_kernel<<<1, 1>>>(out, out_size);
}

// round 8
// speedup vs baseline: 2.1840x; 2.1840x over previous
#include <cuda_runtime.h>
#include <cuda_bf16.h>
#include <cuda_fp16.h>
#include <math.h>
#include <stdint.h>

// Problem dims
#define SEQ_LEN 12
#define BATCH   512
#define NG      16
#define GROUP   32
#define HD      128      // H
#define ED      64       // E
#define PRE     512
#define BOTTLE  1024
#define MLPD    1024
#define GATES   (4*HD)   // 512
#define KCAT    (ED+HD)  // 192
#define ROWS_PN (NG*GROUP*GROUP)  // 16384
#define DHK     (HD+BOTTLE)       // 1152

// ---------------- scratch (device globals; no allocation) ----------------
__device__ float g_h[BATCH*HD];
__device__ float g_c[BATCH*HD];
__device__ float g_pos[BATCH*2];
__device__ float g_decin[BATCH*ED];
__device__ float g_acat[BATCH*KCAT];
__device__ float g_Wcat[GATES*KCAT];
__device__ float g_bsum[GATES];
__device__ float g_gates[BATCH*GATES];
__device__ __align__(16) __nv_bfloat16 g_embhi[ROWS_PN*ED];
__device__ __align__(16) __nv_bfloat16 g_emblo[ROWS_PN*ED];
__device__ __align__(16) __nv_bfloat16 g_W1ehi[PRE*ED];
__device__ __align__(16) __nv_bfloat16 g_W1elo[PRE*ED];
__device__ float g_hW1h[BATCH*PRE];
__device__ __align__(16) __half g_X1h[ROWS_PN*PRE];     // X1 fp16 hi limb
__device__ __align__(16) __half g_X1l[ROWS_PN*PRE];     // X1 fp16 lo limb
__device__ __align__(16) __half g_W2h[BOTTLE*PRE];      // W2 fp16
__device__ __align__(16) __half g_dch[BATCH*DHK];       // dcat fp16 hi
__device__ __align__(16) __half g_dcl[BATCH*DHK];       // dcat fp16 lo
__device__ __align__(16) __half g_Wm1h[MLPD*DHK];       // Wm1 fp16
__device__ float g_pool[BATCH*BOTTLE];
__device__ float g_D1[BATCH*MLPD];
__device__ float g_loss;

__device__ __forceinline__ float sigmoidf(float x) { return 1.0f / (1.0f + expf(-x)); }

// ---------------- PTX helpers (base-arch only: sm_80+ features) ----------------
__device__ __forceinline__ uint32_t smem_u32(const void* p) {
    uint32_t a;
    asm("{ .reg .u64 t; cvta.to.shared.u64 t, %1; cvt.u32.u64 %0, t; }" : "=r"(a) : "l"(p));
    return a;
}
__device__ __forceinline__ void cp_async16(uint32_t s, const void* g) {
    asm volatile("cp.async.cg.shared.global [%0], [%1], 16;" :: "r"(s), "l"(g));
}
#define CP_COMMIT() asm volatile("cp.async.commit_group;" ::: "memory")
#define CP_WAIT1()  asm volatile("cp.async.wait_group 1;" ::: "memory")
#define CP_WAIT0()  asm volatile("cp.async.wait_group 0;" ::: "memory")

__device__ __forceinline__ void ldmatrix_x4(uint32_t* r, uint32_t addr) {
    asm volatile("ldmatrix.sync.aligned.m8n8.x4.shared.b16 {%0,%1,%2,%3}, [%4];"
                 : "=r"(r[0]), "=r"(r[1]), "=r"(r[2]), "=r"(r[3]) : "r"(addr));
}
__device__ __forceinline__ void mma_bf16(float* c, const uint32_t* a, uint32_t b0, uint32_t b1) {
    asm volatile("mma.sync.aligned.m16n8k16.row.col.f32.bf16.bf16.f32 "
                 "{%0,%1,%2,%3}, {%4,%5,%6,%7}, {%8,%9}, {%0,%1,%2,%3};"
                 : "+f"(c[0]), "+f"(c[1]), "+f"(c[2]), "+f"(c[3])
                 : "r"(a[0]), "r"(a[1]), "r"(a[2]), "r"(a[3]), "r"(b0), "r"(b1));
}
__device__ __forceinline__ void mma_f16(float* c, const uint32_t* a, uint32_t b0, uint32_t b1) {
    asm volatile("mma.sync.aligned.m16n8k16.row.col.f32.f16.f16.f32 "
                 "{%0,%1,%2,%3}, {%4,%5,%6,%7}, {%8,%9}, {%0,%1,%2,%3};"
                 : "+f"(c[0]), "+f"(c[1]), "+f"(c[2]), "+f"(c[3])
                 : "r"(a[0]), "r"(a[1]), "r"(a[2]), "r"(a[3]), "r"(b0), "r"(b1));
}

// ---------------- init ----------------
__global__ void init_kernel(const float* __restrict__ hh, const float* __restrict__ ch,
                            const float* __restrict__ last_pos, const float* __restrict__ last_pos_rel,
                            const float* __restrict__ Wih, const float* __restrict__ Whh,
                            const float* __restrict__ bih, const float* __restrict__ bhh,
                            const float* __restrict__ Wse, const float* __restrict__ bse,
                            const float* __restrict__ W1, const float* __restrict__ W2,
                            const float* __restrict__ Wm1) {
    int idx = blockIdx.x * blockDim.x + threadIdx.x;
    if (idx < BATCH*HD) { g_h[idx] = hh[idx]; g_c[idx] = ch[idx]; }
    if (idx < BATCH*2)  g_pos[idx] = last_pos[idx];
    if (idx < BATCH*ED) {
        int b = idx / ED, e = idx % ED;
        g_decin[idx] = last_pos_rel[b*2] * Wse[e*2] + last_pos_rel[b*2+1] * Wse[e*2+1] + bse[e];
    }
    if (idx < GATES) g_bsum[idx] = bih[idx] + bhh[idx];
    if (idx < GATES*KCAT) {
        int n = idx / KCAT, k = idx % KCAT;
        g_Wcat[idx] = (k < ED) ? Wih[n*ED + k] : Whh[n*HD + (k - ED)];
    }
    if (idx < PRE*ED) {
        int n = idx >> 6, k = idx & 63;
        float w = W1[n*KCAT + k];
        __nv_bfloat16 hi = __float2bfloat16(w);
        g_W1ehi[idx] = hi;
        g_W1elo[idx] = __float2bfloat16(w - __bfloat162float(hi));
    }
    if (idx < BOTTLE*PRE) g_W2h[idx] = __float2half(W2[idx]);
    if (idx < MLPD*DHK)   g_Wm1h[idx] = __float2half(Wm1[idx]);
    if (idx == 0) g_loss = 0.0f;
}

// ---------------- packs ----------------
__global__ void pack_lstm_kernel() {
    int idx = blockIdx.x * blockDim.x + threadIdx.x;
    if (idx >= BATCH*KCAT) return;
    int b = idx / KCAT, k = idx % KCAT;
    g_acat[idx] = (k < ED) ? g_decin[b*ED + k] : g_h[b*HD + (k - ED)];
}

__global__ void pack_dh_kernel() {
    int idx = blockIdx.x * blockDim.x + threadIdx.x;
    if (idx >= BATCH*DHK) return;
    int b = idx / DHK, k = idx % DHK;
    float v = (k < HD) ? g_h[b*HD + k] : g_pool[b*BOTTLE + (k - HD)];
    __half hi = __float2half(v);
    g_dch[idx] = hi;
    g_dcl[idx] = __float2half(v - __half2float(hi));
}

// ---------------- LSTM elementwise ----------------
__global__ void lstm_elem_kernel() {
    int idx = blockIdx.x * blockDim.x + threadIdx.x;
    if (idx >= BATCH*HD) return;
    int b = idx / HD, j = idx % HD;
    const float* gr = g_gates + b*GATES;
    float ig = gr[j], fg = gr[HD + j], gg = gr[2*HD + j], og = gr[3*HD + j];
    float c = sigmoidf(fg) * g_c[idx] + sigmoidf(ig) * tanhf(gg);
    g_c[idx] = c;
    g_h[idx] = sigmoidf(og) * tanhf(c);
}

// ---------------- rel_pos, curr_pos, pred output, loss ----------------
__global__ void pos_loss_kernel(const float* __restrict__ Wpos, const float* __restrict__ bpos,
                                const float* __restrict__ gt, float* __restrict__ out_pred) {
    int b = threadIdx.x;
    const float* hr = g_h + b*HD;
    float ax = 0.f, ay = 0.f;
    #pragma unroll 8
    for (int k = 0; k < HD; k++) { float hv = hr[k]; ax += hv * Wpos[k]; ay += hv * Wpos[HD + k]; }
    float rx = ax + bpos[0], ry = ay + bpos[1];
    out_pred[b*2]   = rx;
    out_pred[b*2+1] = ry;
    g_pos[b*2]   += rx;
    g_pos[b*2+1] += ry;
    float dx = rx - gt[b*2], dy = ry - gt[b*2+1];
    __shared__ float sd[BATCH];
    sd[b] = dx*dx + dy*dy;
    __syncthreads();
    for (int s = BATCH/2; s > 0; s >>= 1) {
        if (b < s) sd[b] += sd[b + s];
        __syncthreads();
    }
    if (b == 0) g_loss += sd[0] / (float)(BATCH*2);
}

// ---------------- pairwise rel-pos embedding -> bf16 hi/lo ----------------
__global__ void emb_kernel(const float* __restrict__ Wp, const float* __restrict__ bp) {
    int idx = blockIdx.x * blockDim.x + threadIdx.x;
    if (idx >= ROWS_PN*ED) return;
    int r = idx >> 6, e = idx & 63;
    int g = r >> 10, i = (r >> 5) & 31, j = r & 31;
    int bi = g*GROUP + i, bj = g*GROUP + j;
    float rx = g_pos[bj*2]   - g_pos[bi*2];
    float ry = g_pos[bj*2+1] - g_pos[bi*2+1];
    float v = rx * Wp[e*2] + ry * Wp[e*2+1] + bp[e];
    __nv_bfloat16 hi = __float2bfloat16(v);
    g_embhi[idx] = hi;
    g_emblo[idx] = __float2bfloat16(v - __bfloat162float(hi));
}

// ---------------- next dec_in ----------------
__global__ void decin_kernel(const float* __restrict__ gt,
                             const float* __restrict__ Wse, const float* __restrict__ bse) {
    int idx = blockIdx.x * blockDim.x + threadIdx.x;
    if (idx >= BATCH*ED) return;
    int b = idx / ED, e = idx % ED;
    g_decin[idx] = gt[b*2] * Wse[e*2] + gt[b*2+1] * Wse[e*2+1] + bse[e];
}

__global__ void finish_kernel(float* __restrict__ out, int out_size) {
    if (out_size > SEQ_LEN*BATCH*2) out[SEQ_LEN*BATCH*2] = g_loss;
}

// ---------------- SIMT SGEMM: C = A(MxK) * W(NxK)^T ----------------
template<int MODE>  // 0: store; 1: +bias; 2: relu(+bias)
__global__ void sgemm64(const float* __restrict__ A, int lda,
                        const float* __restrict__ W, int ldw,
                        float* __restrict__ C, int ldc, int K,
                        const float* __restrict__ bias) {
    __shared__ float As[64][17];
    __shared__ float Ws[64][17];
    int tid = threadIdx.x;
    int m0 = blockIdx.y * 64, n0 = blockIdx.x * 64;
    int ty = tid >> 4, tx = tid & 15;
    float acc[4][4] = {};

    for (int k0 = 0; k0 < K; k0 += 16) {
        #pragma unroll
        for (int l = tid; l < 64*16; l += 256) {
            int r = l >> 4, c = l & 15;
            As[r][c] = A[(m0 + r) * lda + k0 + c];
            Ws[r][c] = W[(n0 + r) * ldw + k0 + c];
        }
        __syncthreads();
        #pragma unroll
        for (int kk = 0; kk < 16; kk++) {
            float a[4], w[4];
            #pragma unroll
            for (int i = 0; i < 4; i++) { a[i] = As[ty*4 + i][kk]; w[i] = Ws[tx*4 + i][kk]; }
            #pragma unroll
            for (int i = 0; i < 4; i++)
                #pragma unroll
                for (int j = 0; j < 4; j++) acc[i][j] += a[i] * w[j];
        }
        __syncthreads();
    }

    #pragma unroll
    for (int i = 0; i < 4; i++) {
        int m = m0 + ty*4 + i;
        #pragma unroll
        for (int j = 0; j < 4; j++) {
            int n = n0 + tx*4 + j;
            float v = acc[i][j];
            if (MODE == 0) C[m*ldc + n] = v;
            else if (MODE == 1) C[m*ldc + n] = v + bias[n];
            else C[m*ldc + n] = fmaxf(v + bias[n], 0.0f);
        }
    }
}

// ---------------- X1 HMMA (bf16 3-term, known-good): X1 -> fp16 limbs ----------------
// CTA 256x128, 8 warps (4x2), warp 64x64. K=64, 3 term-chunks.
#define HG_LDA     72
#define HG_ASTAGE  (256 * HG_LDA * 2)
#define HG_BSTAGE  (128 * HG_LDA * 2)
#define HG_STAGE   (HG_ASTAGE + HG_BSTAGE)
#define HG_DYN     (2 * HG_STAGE)

__global__ void __launch_bounds__(256, 1)
hgemm_x1(const float* __restrict__ bias, const float* __restrict__ aux) {
    extern __shared__ char dyn[];
    const int tid  = threadIdx.x;
    const int lane = tid & 31;
    const int wid  = tid >> 5;
    const int wm   = wid >> 1;      // 0..3
    const int wn   = wid & 1;       // 0..1
    const int n0 = blockIdx.x * 128;
    const int m0 = blockIdx.y * 256;

    uint32_t sbase = smem_u32(dyn);
    float acc[4][8][4] = {};

    const int a_row  = wm * 64 + (lane & 15);
    const int a_colg = (lane >> 4) * 8;
    const int b_sub  = ((lane >> 4) & 1) * 8 + (lane & 7);
    const int b_colg = ((lane >> 3) & 1) * 8;

    auto load_chunk = [&](int term, int s) {
        const __nv_bfloat16* Ap = (term == 1 ? g_emblo : g_embhi) + (size_t)m0 * ED;
        const __nv_bfloat16* Bp = (term == 2 ? g_W1elo : g_W1ehi) + (size_t)n0 * ED;
        uint32_t sA = sbase + s * HG_STAGE;
        uint32_t sB = sA + HG_ASTAGE;
        #pragma unroll
        for (int u = 0; u < 8; u++) {
            int idx = tid + u * 256;
            int row = idx >> 3, seg = idx & 7;
            cp_async16(sA + (uint32_t)(row * HG_LDA + seg * 8) * 2,
                       Ap + (size_t)row * ED + seg * 8);
        }
        #pragma unroll
        for (int u = 0; u < 4; u++) {
            int idx = tid + u * 256;
            int row = idx >> 3, seg = idx & 7;
            cp_async16(sB + (uint32_t)(row * HG_LDA + seg * 8) * 2,
                       Bp + (size_t)row * ED + seg * 8);
        }
    };

    load_chunk(0, 0);
    CP_COMMIT();

    for (int c = 0; c < 3; c++) {
        if (c + 1 < 3) { load_chunk(c + 1, (c + 1) & 1); CP_COMMIT(); CP_WAIT1(); }
        else CP_WAIT0();
        __syncthreads();

        uint32_t sA = sbase + (c & 1) * HG_STAGE;
        uint32_t sB = sA + HG_ASTAGE;
        #pragma unroll
        for (int ks = 0; ks < 4; ks++) {
            uint32_t afr[4][4];
            #pragma unroll
            for (int mf = 0; mf < 4; mf++)
                ldmatrix_x4(afr[mf], sA + (uint32_t)((a_row + mf*16) * HG_LDA + ks*16 + a_colg) * 2);
            uint32_t bfr[4][4];
            #pragma unroll
            for (int nf2 = 0; nf2 < 4; nf2++)
                ldmatrix_x4(bfr[nf2], sB + (uint32_t)((wn*64 + nf2*16 + b_sub) * HG_LDA + ks*16 + b_colg) * 2);
            #pragma unroll
            for (int mf = 0; mf < 4; mf++)
                #pragma unroll
                for (int nf = 0; nf < 8; nf++)
                    mma_bf16(acc[mf][nf], afr[mf], bfr[nf>>1][(nf&1)*2], bfr[nf>>1][(nf&1)*2 + 1]);
        }
        __syncthreads();
    }

    #pragma unroll
    for (int mf = 0; mf < 4; mf++) {
        int R  = m0 + wm*64 + mf*16 + (lane >> 2);
        int R8 = R + 8;
        const float* aux0 = aux + (size_t)((R  >> 10)*32 + (R  & 31)) * PRE;
        const float* aux8 = aux + (size_t)((R8 >> 10)*32 + (R8 & 31)) * PRE;
        #pragma unroll
        for (int nf = 0; nf < 8; nf++) {
            int n = n0 + wn*64 + nf*8 + (lane & 3)*2;
            float b0 = bias[n], b1v = bias[n + 1];
            float v0 = fmaxf(acc[mf][nf][0] + b0  + aux0[n],     0.0f);
            float v1 = fmaxf(acc[mf][nf][1] + b1v + aux0[n + 1], 0.0f);
            float v2 = fmaxf(acc[mf][nf][2] + b0  + aux8[n],     0.0f);
            float v3 = fmaxf(acc[mf][nf][3] + b1v + aux8[n + 1], 0.0f);
            __half2 h01, h23, l01, l23;
            h01.x = __float2half(v0); h01.y = __float2half(v1);
            h23.x = __float2half(v2); h23.y = __float2half(v3);
            l01.x = __float2half(v0 - __half2float(h01.x));
            l01.y = __float2half(v1 - __half2float(h01.y));
            l23.x = __float2half(v2 - __half2float(h23.x));
            l23.y = __float2half(v3 - __half2float(h23.y));
            *reinterpret_cast<__half2*>(&g_X1h[(size_t)R  * PRE + n]) = h01;
            *reinterpret_cast<__half2*>(&g_X1h[(size_t)R8 * PRE + n]) = h23;
            *reinterpret_cast<__half2*>(&g_X1l[(size_t)R  * PRE + n]) = l01;
            *reinterpret_cast<__half2*>(&g_X1l[(size_t)R8 * PRE + n]) = l23;
        }
    }
}

// ---------------- fp16 2-limb GEMM2: pool = relu(max_j(X1 @ W2^T) + b2) ----------------
// CTA 256x128, 8 warps (4x2), warp 64x64. K-chunk 64; per chunk load Ahi, Alo, B once;
// both limbs accumulate into the same fp32 acc. 8 chunks, 2-stage cp.async.
#define G2_AH      (256 * HG_LDA * 2)    // 36864 per A limb
#define G2_B       (128 * HG_LDA * 2)    // 18432
#define G2_STG     (2 * G2_AH + G2_B)    // 92160
#define G2_DYN     (2 * G2_STG)          // 184320

__global__ void __launch_bounds__(256, 1)
gemm2_f16(const float* __restrict__ b2, float* __restrict__ pool) {
    extern __shared__ char dyn[];
    const int tid  = threadIdx.x;
    const int lane = tid & 31;
    const int wid  = tid >> 5;
    const int wm   = wid >> 1;      // 0..3
    const int wn   = wid & 1;       // 0..1
    const int n0 = blockIdx.x * 128;
    const int m0 = blockIdx.y * 256;

    uint32_t sbase = smem_u32(dyn);
    float acc[4][8][4] = {};

    const int a_row  = wm * 64 + (lane & 15);
    const int a_colg = (lane >> 4) * 8;
    const int b_sub  = ((lane >> 4) & 1) * 8 + (lane & 7);
    const int b_colg = ((lane >> 3) & 1) * 8;

    auto load_chunk = [&](int c, int s) {
        int kc = c * 64;
        const __half* Ah = g_X1h + (size_t)m0 * PRE + kc;
        const __half* Al = g_X1l + (size_t)m0 * PRE + kc;
        const __half* Bp = g_W2h + (size_t)n0 * PRE + kc;
        uint32_t sAh = sbase + s * G2_STG;
        uint32_t sAl = sAh + G2_AH;
        uint32_t sB  = sAl + G2_AH;
        #pragma unroll
        for (int u = 0; u < 8; u++) {
            int idx = tid + u * 256;          // 0..2047
            int row = idx >> 3, seg = idx & 7;
            uint32_t off = (uint32_t)(row * HG_LDA + seg * 8) * 2;
            cp_async16(sAh + off, Ah + (size_t)row * PRE + seg * 8);
            cp_async16(sAl + off, Al + (size_t)row * PRE + seg * 8);
        }
        #pragma unroll
        for (int u = 0; u < 4; u++) {
            int idx = tid + u * 256;          // 0..1023
            int row = idx >> 3, seg = idx & 7;
            cp_async16(sB + (uint32_t)(row * HG_LDA + seg * 8) * 2,
                       Bp + (size_t)row * PRE + seg * 8);
        }
    };

    load_chunk(0, 0);
    CP_COMMIT();

    for (int c = 0; c < 8; c++) {
        if (c + 1 < 8) { load_chunk(c + 1, (c + 1) & 1); CP_COMMIT(); CP_WAIT1(); }
        else CP_WAIT0();
        __syncthreads();

        uint32_t sAh = sbase + (c & 1) * G2_STG;
        uint32_t sAl = sAh + G2_AH;
        uint32_t sB  = sAl + G2_AH;
        #pragma unroll
        for (int ks = 0; ks < 4; ks++) {
            uint32_t bfr[4][4];
            #pragma unroll
            for (int nf2 = 0; nf2 < 4; nf2++)
                ldmatrix_x4(bfr[nf2], sB + (uint32_t)((wn*64 + nf2*16 + b_sub) * HG_LDA + ks*16 + b_colg) * 2);
            {
                uint32_t afr[4][4];
                #pragma unroll
                for (int mf = 0; mf < 4; mf++)
                    ldmatrix_x4(afr[mf], sAh + (uint32_t)((a_row + mf*16) * HG_LDA + ks*16 + a_colg) * 2);
                #pragma unroll
                for (int mf = 0; mf < 4; mf++)
                    #pragma unroll
                    for (int nf = 0; nf < 8; nf++)
                        mma_f16(acc[mf][nf], afr[mf], bfr[nf>>1][(nf&1)*2], bfr[nf>>1][(nf&1)*2 + 1]);
            }
            {
                uint32_t afr[4][4];
                #pragma unroll
                for (int mf = 0; mf < 4; mf++)
                    ldmatrix_x4(afr[mf], sAl + (uint32_t)((a_row + mf*16) * HG_LDA + ks*16 + a_colg) * 2);
                #pragma unroll
                for (int mf = 0; mf < 4; mf++)
                    #pragma unroll
                    for (int nf = 0; nf < 8; nf++)
                        mma_f16(acc[mf][nf], afr[mf], bfr[nf>>1][(nf&1)*2], bfr[nf>>1][(nf&1)*2 + 1]);
            }
        }
        __syncthreads();
    }

    // Register pool epilogue: warp owns rows m0+wm*64..+63 = two 32-row groups.
    #pragma unroll
    for (int half = 0; half < 2; half++) {
        int pr = blockIdx.y * 8 + wm * 2 + half;    // pool row = m/32
        #pragma unroll
        for (int nf = 0; nf < 8; nf++) {
            float v0 = fmaxf(fmaxf(acc[2*half][nf][0], acc[2*half][nf][2]),
                             fmaxf(acc[2*half+1][nf][0], acc[2*half+1][nf][2]));
            float v1 = fmaxf(fmaxf(acc[2*half][nf][1], acc[2*half][nf][3]),
                             fmaxf(acc[2*half+1][nf][1], acc[2*half+1][nf][3]));
            #pragma unroll
            for (int d = 4; d < 32; d <<= 1) {
                v0 = fmaxf(v0, __shfl_xor_sync(0xffffffffu, v0, d));
                v1 = fmaxf(v1, __shfl_xor_sync(0xffffffffu, v1, d));
            }
            if ((lane >> 2) == 0) {
                int n = n0 + wn*64 + nf*8 + (lane & 3)*2;
                pool[pr * BOTTLE + n]     = fmaxf(v0 + b2[n], 0.0f);
                pool[pr * BOTTLE + n + 1] = fmaxf(v1 + b2[n + 1], 0.0f);
            }
        }
    }
}

// ---------------- fp16 2-limb D1: D1 = relu(dcat @ Wm1^T + bm1) ----------------
// CTA 64x128, 8 warps (2x4), warp 32x32. K=1152, 18 chunks of 64.
#define D1_AH   (64 * HG_LDA * 2)     // 9216 per A limb
#define D1_B    (128 * HG_LDA * 2)    // 18432
#define D1_STG  (2 * D1_AH + D1_B)    // 36864
#define D1_DYN  (2 * D1_STG)          // 73728

__global__ void __launch_bounds__(256, 1)
hgemm_d1(const float* __restrict__ bias) {
    extern __shared__ char dyn[];
    const int tid  = threadIdx.x;
    const int lane = tid & 31;
    const int wid  = tid >> 5;
    const int wm   = wid >> 2;      // 0..1
    const int wn   = wid & 3;       // 0..3
    const int n0 = blockIdx.x * 128;
    const int m0 = blockIdx.y * 64;

    uint32_t sbase = smem_u32(dyn);
    float acc[2][4][4] = {};

    const int a_row  = wm * 32 + (lane & 15);
    const int a_colg = (lane >> 4) * 8;
    const int b_sub  = ((lane >> 4) & 1) * 8 + (lane & 7);
    const int b_colg = ((lane >> 3) & 1) * 8;

    auto load_chunk = [&](int c, int s) {
        int kc = c * 64;
        const __half* Ah = g_dch + (size_t)m0 * DHK + kc;
        const __half* Al = g_dcl + (size_t)m0 * DHK + kc;
        const __half* Bp = g_Wm1h + (size_t)n0 * DHK + kc;
        uint32_t sAh = sbase + s * D1_STG;
        uint32_t sAl = sAh + D1_AH;
        uint32_t sB  = sAl + D1_AH;
        #pragma unroll
        for (int u = 0; u < 2; u++) {
            int idx = tid + u * 256;          // 0..511
            int row = idx >> 3, seg = idx & 7;
            uint32_t off = (uint32_t)(row * HG_LDA + seg * 8) * 2;
            cp_async16(sAh + off, Ah + (size_t)row * DHK + seg * 8);
            cp_async16(sAl + off, Al + (size_t)row * DHK + seg * 8);
        }
        #pragma unroll
        for (int u = 0; u < 4; u++) {
            int idx = tid + u * 256;          // 0..1023
            int row = idx >> 3, seg = idx & 7;
            cp_async16(sB + (uint32_t)(row * HG_LDA + seg * 8) * 2,
                       Bp + (size_t)row * DHK + seg * 8);
        }
    };

    load_chunk(0, 0);
    CP_COMMIT();

    for (int c = 0; c < 18; c++) {
        if (c + 1 < 18) { load_chunk(c + 1, (c + 1) & 1); CP_COMMIT(); CP_WAIT1(); }
        else CP_WAIT0();
        __syncthreads();

        uint32_t sAh = sbase + (c & 1) * D1_STG;
        uint32_t sAl = sAh + D1_AH;
        uint32_t sB  = sAl + D1_AH;
        #pragma unroll
        for (int ks = 0; ks < 4; ks++) {
            uint32_t bfr[2][4];
            #pragma unroll
            for (int nf2 = 0; nf2 < 2; nf2++)
                ldmatrix_x4(bfr[nf2], sB + (uint32_t)((wn*32 + nf2*16 + b_sub) * HG_LDA + ks*16 + b_colg) * 2);
            {
                uint32_t afr[2][4];
                #pragma unroll
                for (int mf = 0; mf < 2; mf++)
                    ldmatrix_x4(afr[mf], sAh + (uint32_t)((a_row + mf*16) * HG_LDA + ks*16 + a_colg) * 2);
                #pragma unroll
                for (int mf = 0; mf < 2; mf++)
                    #pragma unroll
                    for (int nf = 0; nf < 4; nf++)
                        mma_f16(acc[mf][nf], afr[mf], bfr[nf>>1][(nf&1)*2], bfr[nf>>1][(nf&1)*2 + 1]);
            }
            {
                uint32_t afr[2][4];
                #pragma unroll
                for (int mf = 0; mf < 2; mf++)
                    ldmatrix_x4(afr[mf], sAl + (uint32_t)((a_row + mf*16) * HG_LDA + ks*16 + a_colg) * 2);
                #pragma unroll
                for (int mf = 0; mf < 2; mf++)
                    #pragma unroll
                    for (int nf = 0; nf < 4; nf++)
                        mma_f16(acc[mf][nf], afr[mf], bfr[nf>>1][(nf&1)*2], bfr[nf>>1][(nf&1)*2 + 1]);
            }
        }
        __syncthreads();
    }

    #pragma unroll
    for (int mf = 0; mf < 2; mf++) {
        int R  = m0 + wm*32 + mf*16 + (lane >> 2);
        int R8 = R + 8;
        #pragma unroll
        for (int nf = 0; nf < 4; nf++) {
            int n = n0 + wn*32 + nf*8 + (lane & 3)*2;
            float b0 = bias[n], b1v = bias[n + 1];
            g_D1[(size_t)R  * MLPD + n]     = fmaxf(acc[mf][nf][0] + b0,  0.0f);
            g_D1[(size_t)R  * MLPD + n + 1] = fmaxf(acc[mf][nf][1] + b1v, 0.0f);
            g_D1[(size_t)R8 * MLPD + n]     = fmaxf(acc[mf][nf][2] + b0,  0.0f);
            g_D1[(size_t)R8 * MLPD + n + 1] = fmaxf(acc[mf][nf][3] + b1v, 0.0f);
        }
    }
}

// ---------------- launch ----------------
extern "C" void kernel_launch(void* const* d_in, const int* in_sizes, int n_in,
                              void* d_out, int out_size) {
    const float* last_pos      = (const float*)d_in[0];
    const float* last_pos_rel  = (const float*)d_in[1];
    const float* hh            = (const float*)d_in[2];
    const float* ch            = (const float*)d_in[3];
    const float* pred_traj_rel = (const float*)d_in[4];
    const float* W_ih = (const float*)d_in[6];
    const float* W_hh = (const float*)d_in[7];
    const float* b_ih = (const float*)d_in[8];
    const float* b_hh = (const float*)d_in[9];
    const float* Wse  = (const float*)d_in[10];
    const float* bse  = (const float*)d_in[11];
    const float* Wpos = (const float*)d_in[12];
    const float* bpos = (const float*)d_in[13];
    const float* Wp   = (const float*)d_in[14];
    const float* bp   = (const float*)d_in[15];
    const float* W1   = (const float*)d_in[16];
    const float* b1   = (const float*)d_in[17];
    const float* W2   = (const float*)d_in[18];
    const float* b2   = (const float*)d_in[19];
    const float* Wm1  = (const float*)d_in[20];
    const float* bm1  = (const float*)d_in[21];
    const float* Wm2  = (const float*)d_in[22];
    const float* bm2  = (const float*)d_in[23];

    float* out = (float*)d_out;

    float* p_h     = nullptr; cudaGetSymbolAddress((void**)&p_h,     g_h);
    float* p_acat  = nullptr; cudaGetSymbolAddress((void**)&p_acat,  g_acat);
    float* p_Wcat  = nullptr; cudaGetSymbolAddress((void**)&p_Wcat,  g_Wcat);
    float* p_bsum  = nullptr; cudaGetSymbolAddress((void**)&p_bsum,  g_bsum);
    float* p_gates = nullptr; cudaGetSymbolAddress((void**)&p_gates, g_gates);
    float* p_hW1h  = nullptr; cudaGetSymbolAddress((void**)&p_hW1h,  g_hW1h);
    float* p_pool  = nullptr; cudaGetSymbolAddress((void**)&p_pool,  g_pool);
    float* p_D1    = nullptr; cudaGetSymbolAddress((void**)&p_D1,    g_D1);

    cudaFuncSetAttribute(hgemm_x1,  cudaFuncAttributeMaxDynamicSharedMemorySize, HG_DYN);
    cudaFuncSetAttribute(gemm2_f16, cudaFuncAttributeMaxDynamicSharedMemorySize, G2_DYN);
    cudaFuncSetAttribute(hgemm_d1,  cudaFuncAttributeMaxDynamicSharedMemorySize, D1_DYN);

    init_kernel<<<(MLPD*DHK + 255)/256, 256>>>(hh, ch, last_pos, last_pos_rel,
                                               W_ih, W_hh, b_ih, b_hh, Wse, bse, W1, W2, Wm1);

    for (int t = 0; t < SEQ_LEN; t++) {
        const float* gt = pred_traj_rel + t * BATCH * 2;
        float* out_pred = out + t * BATCH * 2;

        // LSTM cell
        pack_lstm_kernel<<<(BATCH*KCAT + 255)/256, 256>>>();
        sgemm64<1><<<dim3(GATES/64, BATCH/64), 256>>>(p_acat, KCAT, p_Wcat, KCAT,
                                                      p_gates, GATES, KCAT, p_bsum);
        lstm_elem_kernel<<<(BATCH*HD + 255)/256, 256>>>();

        // rel_pos / curr_pos / pred output / loss
        pos_loss_kernel<<<1, BATCH>>>(Wpos, bpos, gt, out_pred);

        // pool net
        emb_kernel<<<(ROWS_PN*ED + 255)/256, 256>>>(Wp, bp);
        sgemm64<0><<<dim3(PRE/64, BATCH/64), 256>>>(p_h, HD, W1 + ED, KCAT,
                                                    p_hW1h, PRE, HD, nullptr);
        // X1 = relu(emb @ W1e^T + hW1h[j] + b1) -> fp16 limbs (bf16 3-term HMMA)
        hgemm_x1<<<dim3(PRE/128, ROWS_PN/256), 256, HG_DYN>>>(b1, p_hW1h);
        // pool = relu(max_j(X1 @ W2^T) + b2) (fp16 2-limb HMMA)
        gemm2_f16<<<dim3(BOTTLE/128, ROWS_PN/256), 256, G2_DYN>>>(b2, p_pool);

        // decoder MLP
        pack_dh_kernel<<<(BATCH*DHK + 255)/256, 256>>>();
        hgemm_d1<<<dim3(MLPD/128, BATCH/64), 256, D1_DYN>>>(bm1);
        sgemm64<2><<<dim3(HD/64, BATCH/64), 256>>>(p_D1, MLPD, Wm2, MLPD,
                                                   p_h, HD, MLPD, bm2);

        decin_kernel<<<(BATCH*ED + 255)/256, 256>>>(gt, Wse, bse);
    }

    finish_kernel<<<1, 1>>>(out, out_size);
}

// round 9
// speedup vs baseline: 2.6783x; 1.2263x over previous
#include <cuda_runtime.h>
#include <cuda_bf16.h>
#include <cuda_fp16.h>
#include <math.h>
#include <stdint.h>

// Problem dims
#define SEQ_LEN 12
#define BATCH   512
#define NG      16
#define GROUP   32
#define HD      128      // H
#define ED      64       // E
#define PRE     512
#define BOTTLE  1024
#define MLPD    1024
#define GATES   (4*HD)   // 512
#define KCAT    (ED+HD)  // 192
#define ROWS_PN (NG*GROUP*GROUP)  // 16384
#define DHK     (HD+BOTTLE)       // 1152

// ---------------- scratch (device globals; no allocation) ----------------
__device__ float g_h[BATCH*HD];
__device__ float g_c[BATCH*HD];
__device__ float g_pos[BATCH*2];
__device__ float g_decin[BATCH*ED];
__device__ float g_acat[BATCH*KCAT];
__device__ float g_Wcat[GATES*KCAT];
__device__ float g_bsum[GATES];
__device__ float g_gates[BATCH*GATES];
__device__ __align__(16) __half g_embh[ROWS_PN*ED];     // emb fp16 hi limb
__device__ __align__(16) __half g_embl[ROWS_PN*ED];     // emb fp16 lo limb
__device__ __align__(16) __half g_W1eh[PRE*ED];         // W1 emb-part fp16
__device__ float g_hW1h[BATCH*PRE];
__device__ __align__(16) __half g_X1h[ROWS_PN*PRE];     // X1 fp16
__device__ __align__(16) __half g_W2h[BOTTLE*PRE];      // W2 fp16
__device__ __align__(16) __half g_dch[BATCH*DHK];       // dcat fp16
__device__ __align__(16) __half g_Wm1h[MLPD*DHK];       // Wm1 fp16
__device__ float g_pool[BATCH*BOTTLE];
__device__ float g_D1[BATCH*MLPD];
__device__ float g_loss;

__device__ __forceinline__ float sigmoidf(float x) { return 1.0f / (1.0f + expf(-x)); }

// ---------------- PTX helpers (base-arch only: sm_80+ features) ----------------
__device__ __forceinline__ uint32_t smem_u32(const void* p) {
    uint32_t a;
    asm("{ .reg .u64 t; cvta.to.shared.u64 t, %1; cvt.u32.u64 %0, t; }" : "=r"(a) : "l"(p));
    return a;
}
__device__ __forceinline__ void cp_async16(uint32_t s, const void* g) {
    asm volatile("cp.async.cg.shared.global [%0], [%1], 16;" :: "r"(s), "l"(g));
}
#define CP_COMMIT() asm volatile("cp.async.commit_group;" ::: "memory")
#define CP_WAIT1()  asm volatile("cp.async.wait_group 1;" ::: "memory")
#define CP_WAIT0()  asm volatile("cp.async.wait_group 0;" ::: "memory")

__device__ __forceinline__ void ldmatrix_x4(uint32_t* r, uint32_t addr) {
    asm volatile("ldmatrix.sync.aligned.m8n8.x4.shared.b16 {%0,%1,%2,%3}, [%4];"
                 : "=r"(r[0]), "=r"(r[1]), "=r"(r[2]), "=r"(r[3]) : "r"(addr));
}
__device__ __forceinline__ void mma_f16(float* c, const uint32_t* a, uint32_t b0, uint32_t b1) {
    asm volatile("mma.sync.aligned.m16n8k16.row.col.f32.f16.f16.f32 "
                 "{%0,%1,%2,%3}, {%4,%5,%6,%7}, {%8,%9}, {%0,%1,%2,%3};"
                 : "+f"(c[0]), "+f"(c[1]), "+f"(c[2]), "+f"(c[3])
                 : "r"(a[0]), "r"(a[1]), "r"(a[2]), "r"(a[3]), "r"(b0), "r"(b1));
}

// ---------------- init ----------------
__global__ void init_kernel(const float* __restrict__ hh, const float* __restrict__ ch,
                            const float* __restrict__ last_pos, const float* __restrict__ last_pos_rel,
                            const float* __restrict__ Wih, const float* __restrict__ Whh,
                            const float* __restrict__ bih, const float* __restrict__ bhh,
                            const float* __restrict__ Wse, const float* __restrict__ bse,
                            const float* __restrict__ W1, const float* __restrict__ W2,
                            const float* __restrict__ Wm1) {
    int idx = blockIdx.x * blockDim.x + threadIdx.x;
    if (idx < BATCH*HD) { g_h[idx] = hh[idx]; g_c[idx] = ch[idx]; }
    if (idx < BATCH*2)  g_pos[idx] = last_pos[idx];
    if (idx < BATCH*ED) {
        int b = idx / ED, e = idx % ED;
        g_decin[idx] = last_pos_rel[b*2] * Wse[e*2] + last_pos_rel[b*2+1] * Wse[e*2+1] + bse[e];
    }
    if (idx < GATES) g_bsum[idx] = bih[idx] + bhh[idx];
    if (idx < GATES*KCAT) {
        int n = idx / KCAT, k = idx % KCAT;
        g_Wcat[idx] = (k < ED) ? Wih[n*ED + k] : Whh[n*HD + (k - ED)];
    }
    if (idx < PRE*ED) {
        int n = idx >> 6, k = idx & 63;
        g_W1eh[idx] = __float2half(W1[n*KCAT + k]);
    }
    if (idx < BOTTLE*PRE) g_W2h[idx] = __float2half(W2[idx]);
    if (idx < MLPD*DHK)   g_Wm1h[idx] = __float2half(Wm1[idx]);
    if (idx == 0) g_loss = 0.0f;
}

// ---------------- packs ----------------
__global__ void pack_lstm_kernel() {
    int idx = blockIdx.x * blockDim.x + threadIdx.x;
    if (idx >= BATCH*KCAT) return;
    int b = idx / KCAT, k = idx % KCAT;
    g_acat[idx] = (k < ED) ? g_decin[b*ED + k] : g_h[b*HD + (k - ED)];
}

__global__ void pack_dh_kernel() {
    int idx = blockIdx.x * blockDim.x + threadIdx.x;
    if (idx >= BATCH*DHK) return;
    int b = idx / DHK, k = idx % DHK;
    float v = (k < HD) ? g_h[b*HD + k] : g_pool[b*BOTTLE + (k - HD)];
    g_dch[idx] = __float2half(v);
}

// ---------------- LSTM elementwise ----------------
__global__ void lstm_elem_kernel() {
    int idx = blockIdx.x * blockDim.x + threadIdx.x;
    if (idx >= BATCH*HD) return;
    int b = idx / HD, j = idx % HD;
    const float* gr = g_gates + b*GATES;
    float ig = gr[j], fg = gr[HD + j], gg = gr[2*HD + j], og = gr[3*HD + j];
    float c = sigmoidf(fg) * g_c[idx] + sigmoidf(ig) * tanhf(gg);
    g_c[idx] = c;
    g_h[idx] = sigmoidf(og) * tanhf(c);
}

// ---------------- rel_pos, curr_pos, pred output, loss ----------------
__global__ void pos_loss_kernel(const float* __restrict__ Wpos, const float* __restrict__ bpos,
                                const float* __restrict__ gt, float* __restrict__ out_pred) {
    int b = threadIdx.x;
    const float* hr = g_h + b*HD;
    float ax = 0.f, ay = 0.f;
    #pragma unroll 8
    for (int k = 0; k < HD; k++) { float hv = hr[k]; ax += hv * Wpos[k]; ay += hv * Wpos[HD + k]; }
    float rx = ax + bpos[0], ry = ay + bpos[1];
    out_pred[b*2]   = rx;
    out_pred[b*2+1] = ry;
    g_pos[b*2]   += rx;
    g_pos[b*2+1] += ry;
    float dx = rx - gt[b*2], dy = ry - gt[b*2+1];
    __shared__ float sd[BATCH];
    sd[b] = dx*dx + dy*dy;
    __syncthreads();
    for (int s = BATCH/2; s > 0; s >>= 1) {
        if (b < s) sd[b] += sd[b + s];
        __syncthreads();
    }
    if (b == 0) g_loss += sd[0] / (float)(BATCH*2);
}

// ---------------- pairwise rel-pos embedding -> fp16 hi/lo ----------------
__global__ void emb_kernel(const float* __restrict__ Wp, const float* __restrict__ bp) {
    int idx = blockIdx.x * blockDim.x + threadIdx.x;
    if (idx >= ROWS_PN*ED) return;
    int r = idx >> 6, e = idx & 63;
    int g = r >> 10, i = (r >> 5) & 31, j = r & 31;
    int bi = g*GROUP + i, bj = g*GROUP + j;
    float rx = g_pos[bj*2]   - g_pos[bi*2];
    float ry = g_pos[bj*2+1] - g_pos[bi*2+1];
    float v = rx * Wp[e*2] + ry * Wp[e*2+1] + bp[e];
    __half hi = __float2half(v);
    g_embh[idx] = hi;
    g_embl[idx] = __float2half(v - __half2float(hi));
}

// ---------------- next dec_in ----------------
__global__ void decin_kernel(const float* __restrict__ gt,
                             const float* __restrict__ Wse, const float* __restrict__ bse) {
    int idx = blockIdx.x * blockDim.x + threadIdx.x;
    if (idx >= BATCH*ED) return;
    int b = idx / ED, e = idx % ED;
    g_decin[idx] = gt[b*2] * Wse[e*2] + gt[b*2+1] * Wse[e*2+1] + bse[e];
}

__global__ void finish_kernel(float* __restrict__ out, int out_size) {
    if (out_size > SEQ_LEN*BATCH*2) out[SEQ_LEN*BATCH*2] = g_loss;
}

// ---------------- SIMT SGEMM: C = A(MxK) * W(NxK)^T ----------------
template<int MODE>  // 0: store; 1: +bias; 2: relu(+bias)
__global__ void sgemm64(const float* __restrict__ A, int lda,
                        const float* __restrict__ W, int ldw,
                        float* __restrict__ C, int ldc, int K,
                        const float* __restrict__ bias) {
    __shared__ float As[64][17];
    __shared__ float Ws[64][17];
    int tid = threadIdx.x;
    int m0 = blockIdx.y * 64, n0 = blockIdx.x * 64;
    int ty = tid >> 4, tx = tid & 15;
    float acc[4][4] = {};

    for (int k0 = 0; k0 < K; k0 += 16) {
        #pragma unroll
        for (int l = tid; l < 64*16; l += 256) {
            int r = l >> 4, c = l & 15;
            As[r][c] = A[(m0 + r) * lda + k0 + c];
            Ws[r][c] = W[(n0 + r) * ldw + k0 + c];
        }
        __syncthreads();
        #pragma unroll
        for (int kk = 0; kk < 16; kk++) {
            float a[4], w[4];
            #pragma unroll
            for (int i = 0; i < 4; i++) { a[i] = As[ty*4 + i][kk]; w[i] = Ws[tx*4 + i][kk]; }
            #pragma unroll
            for (int i = 0; i < 4; i++)
                #pragma unroll
                for (int j = 0; j < 4; j++) acc[i][j] += a[i] * w[j];
        }
        __syncthreads();
    }

    #pragma unroll
    for (int i = 0; i < 4; i++) {
        int m = m0 + ty*4 + i;
        #pragma unroll
        for (int j = 0; j < 4; j++) {
            int n = n0 + tx*4 + j;
            float v = acc[i][j];
            if (MODE == 0) C[m*ldc + n] = v;
            else if (MODE == 1) C[m*ldc + n] = v + bias[n];
            else C[m*ldc + n] = fmaxf(v + bias[n], 0.0f);
        }
    }
}

// ---------------- X1 HMMA (fp16: emb 2-limb x W1e): single-stage, K=64 ----------------
// CTA 256x128, 8 warps (4x2), warp 64x64.
#define HG_LDA     72
#define X1_AH      (256 * HG_LDA * 2)   // 36864 per emb limb
#define X1_B       (128 * HG_LDA * 2)   // 18432
#define X1_DYN     (2 * X1_AH + X1_B)   // 92160

__global__ void __launch_bounds__(256, 1)
hgemm_x1(const float* __restrict__ bias, const float* __restrict__ aux) {
    extern __shared__ char dyn[];
    const int tid  = threadIdx.x;
    const int lane = tid & 31;
    const int wid  = tid >> 5;
    const int wm   = wid >> 1;      // 0..3
    const int wn   = wid & 1;       // 0..1
    const int n0 = blockIdx.x * 128;
    const int m0 = blockIdx.y * 256;

    uint32_t sbase = smem_u32(dyn);
    uint32_t sAh = sbase;
    uint32_t sAl = sAh + X1_AH;
    uint32_t sB  = sAl + X1_AH;
    float acc[4][8][4] = {};

    const int a_row  = wm * 64 + (lane & 15);
    const int a_colg = (lane >> 4) * 8;
    const int b_sub  = ((lane >> 4) & 1) * 8 + (lane & 7);
    const int b_colg = ((lane >> 3) & 1) * 8;

    {
        const __half* Ah = g_embh + (size_t)m0 * ED;
        const __half* Al = g_embl + (size_t)m0 * ED;
        const __half* Bp = g_W1eh + (size_t)n0 * ED;
        #pragma unroll
        for (int u = 0; u < 8; u++) {
            int idx = tid + u * 256;          // 0..2047
            int row = idx >> 3, seg = idx & 7;
            uint32_t off = (uint32_t)(row * HG_LDA + seg * 8) * 2;
            cp_async16(sAh + off, Ah + (size_t)row * ED + seg * 8);
            cp_async16(sAl + off, Al + (size_t)row * ED + seg * 8);
        }
        #pragma unroll
        for (int u = 0; u < 4; u++) {
            int idx = tid + u * 256;          // 0..1023
            int row = idx >> 3, seg = idx & 7;
            cp_async16(sB + (uint32_t)(row * HG_LDA + seg * 8) * 2,
                       Bp + (size_t)row * ED + seg * 8);
        }
        CP_COMMIT();
        CP_WAIT0();
        __syncthreads();
    }

    #pragma unroll
    for (int ks = 0; ks < 4; ks++) {
        uint32_t bfr[4][4];
        #pragma unroll
        for (int nf2 = 0; nf2 < 4; nf2++)
            ldmatrix_x4(bfr[nf2], sB + (uint32_t)((wn*64 + nf2*16 + b_sub) * HG_LDA + ks*16 + b_colg) * 2);
        {
            uint32_t afr[4][4];
            #pragma unroll
            for (int mf = 0; mf < 4; mf++)
                ldmatrix_x4(afr[mf], sAh + (uint32_t)((a_row + mf*16) * HG_LDA + ks*16 + a_colg) * 2);
            #pragma unroll
            for (int mf = 0; mf < 4; mf++)
                #pragma unroll
                for (int nf = 0; nf < 8; nf++)
                    mma_f16(acc[mf][nf], afr[mf], bfr[nf>>1][(nf&1)*2], bfr[nf>>1][(nf&1)*2 + 1]);
        }
        {
            uint32_t afr[4][4];
            #pragma unroll
            for (int mf = 0; mf < 4; mf++)
                ldmatrix_x4(afr[mf], sAl + (uint32_t)((a_row + mf*16) * HG_LDA + ks*16 + a_colg) * 2);
            #pragma unroll
            for (int mf = 0; mf < 4; mf++)
                #pragma unroll
                for (int nf = 0; nf < 8; nf++)
                    mma_f16(acc[mf][nf], afr[mf], bfr[nf>>1][(nf&1)*2], bfr[nf>>1][(nf&1)*2 + 1]);
        }
    }

    #pragma unroll
    for (int mf = 0; mf < 4; mf++) {
        int R  = m0 + wm*64 + mf*16 + (lane >> 2);
        int R8 = R + 8;
        const float* aux0 = aux + (size_t)((R  >> 10)*32 + (R  & 31)) * PRE;
        const float* aux8 = aux + (size_t)((R8 >> 10)*32 + (R8 & 31)) * PRE;
        #pragma unroll
        for (int nf = 0; nf < 8; nf++) {
            int n = n0 + wn*64 + nf*8 + (lane & 3)*2;
            float b0 = bias[n], b1v = bias[n + 1];
            float v0 = fmaxf(acc[mf][nf][0] + b0  + aux0[n],     0.0f);
            float v1 = fmaxf(acc[mf][nf][1] + b1v + aux0[n + 1], 0.0f);
            float v2 = fmaxf(acc[mf][nf][2] + b0  + aux8[n],     0.0f);
            float v3 = fmaxf(acc[mf][nf][3] + b1v + aux8[n + 1], 0.0f);
            __half2 h01, h23;
            h01.x = __float2half(v0); h01.y = __float2half(v1);
            h23.x = __float2half(v2); h23.y = __float2half(v3);
            *reinterpret_cast<__half2*>(&g_X1h[(size_t)R  * PRE + n]) = h01;
            *reinterpret_cast<__half2*>(&g_X1h[(size_t)R8 * PRE + n]) = h23;
        }
    }
}

// ---------------- fp16 GEMM2: pool = relu(max_j(X1 @ W2^T) + b2) ----------------
// CTA 256x128, 8 warps (4x2), warp 64x64. Single fp16 A. 8 chunks of 64, 2-stage.
#define G2_A       (256 * HG_LDA * 2)    // 36864
#define G2_B       (128 * HG_LDA * 2)    // 18432
#define G2_STG     (G2_A + G2_B)         // 55296
#define G2_DYN     (2 * G2_STG)          // 110592

__global__ void __launch_bounds__(256, 1)
gemm2_f16(const float* __restrict__ b2, float* __restrict__ pool) {
    extern __shared__ char dyn[];
    const int tid  = threadIdx.x;
    const int lane = tid & 31;
    const int wid  = tid >> 5;
    const int wm   = wid >> 1;      // 0..3
    const int wn   = wid & 1;       // 0..1
    const int n0 = blockIdx.x * 128;
    const int m0 = blockIdx.y * 256;

    uint32_t sbase = smem_u32(dyn);
    float acc[4][8][4] = {};

    const int a_row  = wm * 64 + (lane & 15);
    const int a_colg = (lane >> 4) * 8;
    const int b_sub  = ((lane >> 4) & 1) * 8 + (lane & 7);
    const int b_colg = ((lane >> 3) & 1) * 8;

    auto load_chunk = [&](int c, int s) {
        int kc = c * 64;
        const __half* Ap = g_X1h + (size_t)m0 * PRE + kc;
        const __half* Bp = g_W2h + (size_t)n0 * PRE + kc;
        uint32_t sA = sbase + s * G2_STG;
        uint32_t sB = sA + G2_A;
        #pragma unroll
        for (int u = 0; u < 8; u++) {
            int idx = tid + u * 256;          // 0..2047
            int row = idx >> 3, seg = idx & 7;
            cp_async16(sA + (uint32_t)(row * HG_LDA + seg * 8) * 2,
                       Ap + (size_t)row * PRE + seg * 8);
        }
        #pragma unroll
        for (int u = 0; u < 4; u++) {
            int idx = tid + u * 256;          // 0..1023
            int row = idx >> 3, seg = idx & 7;
            cp_async16(sB + (uint32_t)(row * HG_LDA + seg * 8) * 2,
                       Bp + (size_t)row * PRE + seg * 8);
        }
    };

    load_chunk(0, 0);
    CP_COMMIT();

    for (int c = 0; c < 8; c++) {
        if (c + 1 < 8) { load_chunk(c + 1, (c + 1) & 1); CP_COMMIT(); CP_WAIT1(); }
        else CP_WAIT0();
        __syncthreads();

        uint32_t sA = sbase + (c & 1) * G2_STG;
        uint32_t sB = sA + G2_A;
        #pragma unroll
        for (int ks = 0; ks < 4; ks++) {
            uint32_t bfr[4][4];
            #pragma unroll
            for (int nf2 = 0; nf2 < 4; nf2++)
                ldmatrix_x4(bfr[nf2], sB + (uint32_t)((wn*64 + nf2*16 + b_sub) * HG_LDA + ks*16 + b_colg) * 2);
            uint32_t afr[4][4];
            #pragma unroll
            for (int mf = 0; mf < 4; mf++)
                ldmatrix_x4(afr[mf], sA + (uint32_t)((a_row + mf*16) * HG_LDA + ks*16 + a_colg) * 2);
            #pragma unroll
            for (int mf = 0; mf < 4; mf++)
                #pragma unroll
                for (int nf = 0; nf < 8; nf++)
                    mma_f16(acc[mf][nf], afr[mf], bfr[nf>>1][(nf&1)*2], bfr[nf>>1][(nf&1)*2 + 1]);
        }
        __syncthreads();
    }

    // Register pool epilogue: warp owns rows m0+wm*64..+63 = two 32-row groups.
    #pragma unroll
    for (int half = 0; half < 2; half++) {
        int pr = blockIdx.y * 8 + wm * 2 + half;    // pool row = m/32
        #pragma unroll
        for (int nf = 0; nf < 8; nf++) {
            float v0 = fmaxf(fmaxf(acc[2*half][nf][0], acc[2*half][nf][2]),
                             fmaxf(acc[2*half+1][nf][0], acc[2*half+1][nf][2]));
            float v1 = fmaxf(fmaxf(acc[2*half][nf][1], acc[2*half][nf][3]),
                             fmaxf(acc[2*half+1][nf][1], acc[2*half+1][nf][3]));
            #pragma unroll
            for (int d = 4; d < 32; d <<= 1) {
                v0 = fmaxf(v0, __shfl_xor_sync(0xffffffffu, v0, d));
                v1 = fmaxf(v1, __shfl_xor_sync(0xffffffffu, v1, d));
            }
            if ((lane >> 2) == 0) {
                int n = n0 + wn*64 + nf*8 + (lane & 3)*2;
                pool[pr * BOTTLE + n]     = fmaxf(v0 + b2[n], 0.0f);
                pool[pr * BOTTLE + n + 1] = fmaxf(v1 + b2[n + 1], 0.0f);
            }
        }
    }
}

// ---------------- fp16 D1: D1 = relu(dcat @ Wm1^T + bm1) ----------------
// CTA 64x128, 8 warps (2x4), warp 32x32. K=1152, 18 chunks of 64, single A limb.
#define D1_A    (64 * HG_LDA * 2)     // 9216
#define D1_B    (128 * HG_LDA * 2)    // 18432
#define D1_STG  (D1_A + D1_B)         // 27648
#define D1_DYN  (2 * D1_STG)          // 55296

__global__ void __launch_bounds__(256, 1)
hgemm_d1(const float* __restrict__ bias) {
    extern __shared__ char dyn[];
    const int tid  = threadIdx.x;
    const int lane = tid & 31;
    const int wid  = tid >> 5;
    const int wm   = wid >> 2;      // 0..1
    const int wn   = wid & 3;       // 0..3
    const int n0 = blockIdx.x * 128;
    const int m0 = blockIdx.y * 64;

    uint32_t sbase = smem_u32(dyn);
    float acc[2][4][4] = {};

    const int a_row  = wm * 32 + (lane & 15);
    const int a_colg = (lane >> 4) * 8;
    const int b_sub  = ((lane >> 4) & 1) * 8 + (lane & 7);
    const int b_colg = ((lane >> 3) & 1) * 8;

    auto load_chunk = [&](int c, int s) {
        int kc = c * 64;
        const __half* Ap = g_dch + (size_t)m0 * DHK + kc;
        const __half* Bp = g_Wm1h + (size_t)n0 * DHK + kc;
        uint32_t sA = sbase + s * D1_STG;
        uint32_t sB = sA + D1_A;
        #pragma unroll
        for (int u = 0; u < 2; u++) {
            int idx = tid + u * 256;          // 0..511
            int row = idx >> 3, seg = idx & 7;
            cp_async16(sA + (uint32_t)(row * HG_LDA + seg * 8) * 2,
                       Ap + (size_t)row * DHK + seg * 8);
        }
        #pragma unroll
        for (int u = 0; u < 4; u++) {
            int idx = tid + u * 256;          // 0..1023
            int row = idx >> 3, seg = idx & 7;
            cp_async16(sB + (uint32_t)(row * HG_LDA + seg * 8) * 2,
                       Bp + (size_t)row * DHK + seg * 8);
        }
    };

    load_chunk(0, 0);
    CP_COMMIT();

    for (int c = 0; c < 18; c++) {
        if (c + 1 < 18) { load_chunk(c + 1, (c + 1) & 1); CP_COMMIT(); CP_WAIT1(); }
        else CP_WAIT0();
        __syncthreads();

        uint32_t sA = sbase + (c & 1) * D1_STG;
        uint32_t sB = sA + D1_A;
        #pragma unroll
        for (int ks = 0; ks < 4; ks++) {
            uint32_t bfr[2][4];
            #pragma unroll
            for (int nf2 = 0; nf2 < 2; nf2++)
                ldmatrix_x4(bfr[nf2], sB + (uint32_t)((wn*32 + nf2*16 + b_sub) * HG_LDA + ks*16 + b_colg) * 2);
            uint32_t afr[2][4];
            #pragma unroll
            for (int mf = 0; mf < 2; mf++)
                ldmatrix_x4(afr[mf], sA + (uint32_t)((a_row + mf*16) * HG_LDA + ks*16 + a_colg) * 2);
            #pragma unroll
            for (int mf = 0; mf < 2; mf++)
                #pragma unroll
                for (int nf = 0; nf < 4; nf++)
                    mma_f16(acc[mf][nf], afr[mf], bfr[nf>>1][(nf&1)*2], bfr[nf>>1][(nf&1)*2 + 1]);
        }
        __syncthreads();
    }

    #pragma unroll
    for (int mf = 0; mf < 2; mf++) {
        int R  = m0 + wm*32 + mf*16 + (lane >> 2);
        int R8 = R + 8;
        #pragma unroll
        for (int nf = 0; nf < 4; nf++) {
            int n = n0 + wn*32 + nf*8 + (lane & 3)*2;
            float b0 = bias[n], b1v = bias[n + 1];
            g_D1[(size_t)R  * MLPD + n]     = fmaxf(acc[mf][nf][0] + b0,  0.0f);
            g_D1[(size_t)R  * MLPD + n + 1] = fmaxf(acc[mf][nf][1] + b1v, 0.0f);
            g_D1[(size_t)R8 * MLPD + n]     = fmaxf(acc[mf][nf][2] + b0,  0.0f);
            g_D1[(size_t)R8 * MLPD + n + 1] = fmaxf(acc[mf][nf][3] + b1v, 0.0f);
        }
    }
}

// ---------------- launch ----------------
extern "C" void kernel_launch(void* const* d_in, const int* in_sizes, int n_in,
                              void* d_out, int out_size) {
    const float* last_pos      = (const float*)d_in[0];
    const float* last_pos_rel  = (const float*)d_in[1];
    const float* hh            = (const float*)d_in[2];
    const float* ch            = (const float*)d_in[3];
    const float* pred_traj_rel = (const float*)d_in[4];
    const float* W_ih = (const float*)d_in[6];
    const float* W_hh = (const float*)d_in[7];
    const float* b_ih = (const float*)d_in[8];
    const float* b_hh = (const float*)d_in[9];
    const float* Wse  = (const float*)d_in[10];
    const float* bse  = (const float*)d_in[11];
    const float* Wpos = (const float*)d_in[12];
    const float* bpos = (const float*)d_in[13];
    const float* Wp   = (const float*)d_in[14];
    const float* bp   = (const float*)d_in[15];
    const float* W1   = (const float*)d_in[16];
    const float* b1   = (const float*)d_in[17];
    const float* W2   = (const float*)d_in[18];
    const float* b2   = (const float*)d_in[19];
    const float* Wm1  = (const float*)d_in[20];
    const float* bm1  = (const float*)d_in[21];
    const float* Wm2  = (const float*)d_in[22];
    const float* bm2  = (const float*)d_in[23];

    float* out = (float*)d_out;

    float* p_h     = nullptr; cudaGetSymbolAddress((void**)&p_h,     g_h);
    float* p_acat  = nullptr; cudaGetSymbolAddress((void**)&p_acat,  g_acat);
    float* p_Wcat  = nullptr; cudaGetSymbolAddress((void**)&p_Wcat,  g_Wcat);
    float* p_bsum  = nullptr; cudaGetSymbolAddress((void**)&p_bsum,  g_bsum);
    float* p_gates = nullptr; cudaGetSymbolAddress((void**)&p_gates, g_gates);
    float* p_hW1h  = nullptr; cudaGetSymbolAddress((void**)&p_hW1h,  g_hW1h);
    float* p_pool  = nullptr; cudaGetSymbolAddress((void**)&p_pool,  g_pool);
    float* p_D1    = nullptr; cudaGetSymbolAddress((void**)&p_D1,    g_D1);

    cudaFuncSetAttribute(hgemm_x1,  cudaFuncAttributeMaxDynamicSharedMemorySize, X1_DYN);
    cudaFuncSetAttribute(gemm2_f16, cudaFuncAttributeMaxDynamicSharedMemorySize, G2_DYN);
    cudaFuncSetAttribute(hgemm_d1,  cudaFuncAttributeMaxDynamicSharedMemorySize, D1_DYN);

    init_kernel<<<(MLPD*DHK + 255)/256, 256>>>(hh, ch, last_pos, last_pos_rel,
                                               W_ih, W_hh, b_ih, b_hh, Wse, bse, W1, W2, Wm1);

    for (int t = 0; t < SEQ_LEN; t++) {
        const float* gt = pred_traj_rel + t * BATCH * 2;
        float* out_pred = out + t * BATCH * 2;

        // LSTM cell
        pack_lstm_kernel<<<(BATCH*KCAT + 255)/256, 256>>>();
        sgemm64<1><<<dim3(GATES/64, BATCH/64), 256>>>(p_acat, KCAT, p_Wcat, KCAT,
                                                      p_gates, GATES, KCAT, p_bsum);
        lstm_elem_kernel<<<(BATCH*HD + 255)/256, 256>>>();

        // rel_pos / curr_pos / pred output / loss
        pos_loss_kernel<<<1, BATCH>>>(Wpos, bpos, gt, out_pred);

        // pool net
        emb_kernel<<<(ROWS_PN*ED + 255)/256, 256>>>(Wp, bp);
        sgemm64<0><<<dim3(PRE/64, BATCH/64), 256>>>(p_h, HD, W1 + ED, KCAT,
                                                    p_hW1h, PRE, HD, nullptr);
        // X1 = relu(emb @ W1e^T + hW1h[j] + b1) -> fp16 (2-limb emb x fp16 W1e)
        hgemm_x1<<<dim3(PRE/128, ROWS_PN/256), 256, X1_DYN>>>(b1, p_hW1h);
        // pool = relu(max_j(X1 @ W2^T) + b2) (single-limb fp16 HMMA)
        gemm2_f16<<<dim3(BOTTLE/128, ROWS_PN/256), 256, G2_DYN>>>(b2, p_pool);

        // decoder MLP
        pack_dh_kernel<<<(BATCH*DHK + 255)/256, 256>>>();
        hgemm_d1<<<dim3(MLPD/128, BATCH/64), 256, D1_DYN>>>(bm1);
        sgemm64<2><<<dim3(HD/64, BATCH/64), 256>>>(p_D1, MLPD, Wm2, MLPD,
                                                   p_h, HD, MLPD, bm2);

        decin_kernel<<<(BATCH*ED + 255)/256, 256>>>(gt, Wse, bse);
    }

    finish_kernel<<<1, 1>>>(out, out_size);
}

// round 11
// speedup vs baseline: 3.3490x; 1.2504x over previous
#include <cuda_runtime.h>
#include <cuda_bf16.h>
#include <cuda_fp16.h>
#include <math.h>
#include <stdint.h>

// Problem dims
#define SEQ_LEN 12
#define BATCH   512
#define NG      16
#define GROUP   32
#define HD      128      // H
#define ED      64       // E
#define PRE     512
#define BOTTLE  1024
#define MLPD    1024
#define GATES   (4*HD)   // 512
#define KCAT    (ED+HD)  // 192
#define ROWS_PN (NG*GROUP*GROUP)  // 16384
#define DHK     (HD+BOTTLE)       // 1152

// ---------------- scratch (device globals; no allocation) ----------------
__device__ float g_h[BATCH*HD];
__device__ float g_c[BATCH*HD];
__device__ float g_pos[BATCH*2];
__device__ float g_decin[BATCH*ED];
__device__ __align__(16) __half g_acath[BATCH*KCAT];    // acat fp16 hi limb
__device__ __align__(16) __half g_acatl[BATCH*KCAT];    // acat fp16 lo limb
__device__ __align__(16) __half g_Wch[GATES*KCAT];      // Wcat fp16 hi
__device__ __align__(16) __half g_Wcl[GATES*KCAT];      // Wcat fp16 lo
__device__ float g_bsum[GATES];
__device__ float g_gates[BATCH*GATES];
__device__ __align__(16) __half g_hh16[BATCH*HD];       // h fp16 hi limb
__device__ __align__(16) __half g_hl16[BATCH*HD];       // h fp16 lo limb
__device__ __align__(16) __half g_W1hh[PRE*HD];         // W1 h-part fp16
__device__ __align__(16) __half g_embh[ROWS_PN*ED];     // emb fp16 hi limb
__device__ __align__(16) __half g_embl[ROWS_PN*ED];     // emb fp16 lo limb
__device__ __align__(16) __half g_W1eh[PRE*ED];         // W1 emb-part fp16
__device__ float g_hW1h[BATCH*PRE];
__device__ __align__(16) __half g_X1h[ROWS_PN*PRE];     // X1 fp16
__device__ __align__(16) __half g_W2h[BOTTLE*PRE];      // W2 fp16
__device__ __align__(16) __half g_dch[BATCH*DHK];       // dcat fp16
__device__ __align__(16) __half g_Wm1h[MLPD*DHK];       // Wm1 fp16
__device__ float g_pool[BATCH*BOTTLE];
__device__ float g_D1[BATCH*MLPD];
__device__ float g_sqacc[BATCH];

__device__ __forceinline__ float sigmoidf(float x) { return 1.0f / (1.0f + expf(-x)); }

// ---------------- PTX helpers (base-arch only: sm_80+ features) ----------------
__device__ __forceinline__ uint32_t smem_u32(const void* p) {
    uint32_t a;
    asm("{ .reg .u64 t; cvta.to.shared.u64 t, %1; cvt.u32.u64 %0, t; }" : "=r"(a) : "l"(p));
    return a;
}
__device__ __forceinline__ void cp_async16(uint32_t s, const void* g) {
    asm volatile("cp.async.cg.shared.global [%0], [%1], 16;" :: "r"(s), "l"(g));
}
#define CP_COMMIT() asm volatile("cp.async.commit_group;" ::: "memory")
#define CP_WAIT1()  asm volatile("cp.async.wait_group 1;" ::: "memory")
#define CP_WAIT0()  asm volatile("cp.async.wait_group 0;" ::: "memory")

__device__ __forceinline__ void ldmatrix_x4(uint32_t* r, uint32_t addr) {
    asm volatile("ldmatrix.sync.aligned.m8n8.x4.shared.b16 {%0,%1,%2,%3}, [%4];"
                 : "=r"(r[0]), "=r"(r[1]), "=r"(r[2]), "=r"(r[3]) : "r"(addr));
}
__device__ __forceinline__ void mma_f16(float* c, const uint32_t* a, uint32_t b0, uint32_t b1) {
    asm volatile("mma.sync.aligned.m16n8k16.row.col.f32.f16.f16.f32 "
                 "{%0,%1,%2,%3}, {%4,%5,%6,%7}, {%8,%9}, {%0,%1,%2,%3};"
                 : "+f"(c[0]), "+f"(c[1]), "+f"(c[2]), "+f"(c[3])
                 : "r"(a[0]), "r"(a[1]), "r"(a[2]), "r"(a[3]), "r"(b0), "r"(b1));
}

// ---------------- init ----------------
__global__ void init_kernel(const float* __restrict__ hh, const float* __restrict__ ch,
                            const float* __restrict__ last_pos, const float* __restrict__ last_pos_rel,
                            const float* __restrict__ Wih, const float* __restrict__ Whh,
                            const float* __restrict__ bih, const float* __restrict__ bhh,
                            const float* __restrict__ Wse, const float* __restrict__ bse,
                            const float* __restrict__ W1, const float* __restrict__ W2,
                            const float* __restrict__ Wm1) {
    int idx = blockIdx.x * blockDim.x + threadIdx.x;
    if (idx < BATCH*HD) { g_h[idx] = hh[idx]; g_c[idx] = ch[idx]; }
    if (idx < BATCH*2)  g_pos[idx] = last_pos[idx];
    if (idx < BATCH)    g_sqacc[idx] = 0.0f;
    if (idx < BATCH*ED) {
        int b = idx / ED, e = idx % ED;
        g_decin[idx] = last_pos_rel[b*2] * Wse[e*2] + last_pos_rel[b*2+1] * Wse[e*2+1] + bse[e];
    }
    if (idx < GATES) g_bsum[idx] = bih[idx] + bhh[idx];
    if (idx < GATES*KCAT) {
        int n = idx / KCAT, k = idx % KCAT;
        float w = (k < ED) ? Wih[n*ED + k] : Whh[n*HD + (k - ED)];
        __half hi = __float2half(w);
        g_Wch[idx] = hi;
        g_Wcl[idx] = __float2half(w - __half2float(hi));
    }
    if (idx < PRE*ED) {
        int n = idx >> 6, k = idx & 63;
        g_W1eh[idx] = __float2half(W1[n*KCAT + k]);
    }
    if (idx < PRE*HD) {
        int n = idx >> 7, k = idx & 127;
        g_W1hh[idx] = __float2half(W1[n*KCAT + ED + k]);
    }
    if (idx < BOTTLE*PRE) g_W2h[idx] = __float2half(W2[idx]);
    if (idx < MLPD*DHK)   g_Wm1h[idx] = __float2half(Wm1[idx]);
}

// ---------------- packs ----------------
__global__ void pack_lstm_kernel() {
    int idx = blockIdx.x * blockDim.x + threadIdx.x;
    if (idx >= BATCH*KCAT) return;
    int b = idx / KCAT, k = idx % KCAT;
    float v = (k < ED) ? g_decin[b*ED + k] : g_h[b*HD + (k - ED)];
    __half hi = __float2half(v);
    g_acath[idx] = hi;
    g_acatl[idx] = __float2half(v - __half2float(hi));
}

__global__ void pack_dh_kernel() {
    int idx = blockIdx.x * blockDim.x + threadIdx.x;
    if (idx >= BATCH*DHK) return;
    int b = idx / DHK, k = idx % DHK;
    float v = (k < HD) ? g_h[b*HD + k] : g_pool[b*BOTTLE + (k - HD)];
    g_dch[idx] = __float2half(v);
}

// ---------------- fused LSTM elementwise + rel_pos + pos + loss accum ----------------
// 512 blocks x 128 threads; block b owns batch row b.
__global__ void lstm_pos_kernel(const float* __restrict__ Wpos, const float* __restrict__ bpos,
                                const float* __restrict__ gt, float* __restrict__ out_pred) {
    int b = blockIdx.x, j = threadIdx.x;
    const float* gr = g_gates + b*GATES;
    float ig = gr[j], fg = gr[HD + j], gg = gr[2*HD + j], og = gr[3*HD + j];
    float c = sigmoidf(fg) * g_c[b*HD + j] + sigmoidf(ig) * tanhf(gg);
    float h = sigmoidf(og) * tanhf(c);
    g_c[b*HD + j] = c;
    g_h[b*HD + j] = h;
    __half hhv = __float2half(h);
    g_hh16[b*HD + j] = hhv;
    g_hl16[b*HD + j] = __float2half(h - __half2float(hhv));

    __shared__ float sx[HD], sy[HD];
    sx[j] = h * Wpos[j];
    sy[j] = h * Wpos[HD + j];
    __syncthreads();
    for (int s = HD/2; s > 0; s >>= 1) {
        if (j < s) { sx[j] += sx[j + s]; sy[j] += sy[j + s]; }
        __syncthreads();
    }
    if (j == 0) {
        float rx = sx[0] + bpos[0], ry = sy[0] + bpos[1];
        out_pred[b*2]   = rx;
        out_pred[b*2+1] = ry;
        g_pos[b*2]   += rx;
        g_pos[b*2+1] += ry;
        float dx = rx - gt[b*2], dy = ry - gt[b*2+1];
        g_sqacc[b] += dx*dx + dy*dy;
    }
}

// ---------------- pairwise rel-pos embedding -> fp16 hi/lo ----------------
__global__ void emb_kernel(const float* __restrict__ Wp, const float* __restrict__ bp) {
    int idx = blockIdx.x * blockDim.x + threadIdx.x;
    if (idx >= ROWS_PN*ED) return;
    int r = idx >> 6, e = idx & 63;
    int g = r >> 10, i = (r >> 5) & 31, j = r & 31;
    int bi = g*GROUP + i, bj = g*GROUP + j;
    float rx = g_pos[bj*2]   - g_pos[bi*2];
    float ry = g_pos[bj*2+1] - g_pos[bi*2+1];
    float v = rx * Wp[e*2] + ry * Wp[e*2+1] + bp[e];
    __half hi = __float2half(v);
    g_embh[idx] = hi;
    g_embl[idx] = __float2half(v - __half2float(hi));
}

// ---------------- next dec_in ----------------
__global__ void decin_kernel(const float* __restrict__ gt,
                             const float* __restrict__ Wse, const float* __restrict__ bse) {
    int idx = blockIdx.x * blockDim.x + threadIdx.x;
    if (idx >= BATCH*ED) return;
    int b = idx / ED, e = idx % ED;
    g_decin[idx] = gt[b*2] * Wse[e*2] + gt[b*2+1] * Wse[e*2+1] + bse[e];
}

__global__ void finish_kernel(float* __restrict__ out, int out_size) {
    __shared__ float sd[BATCH];
    int t = threadIdx.x;
    sd[t] = g_sqacc[t];
    __syncthreads();
    for (int s = BATCH/2; s > 0; s >>= 1) {
        if (t < s) sd[t] += sd[t + s];
        __syncthreads();
    }
    if (t == 0 && out_size > SEQ_LEN*BATCH*2)
        out[SEQ_LEN*BATCH*2] = sd[0] / (float)(BATCH*2);
}

// ---------------- SIMT SGEMM (D2 only): C = relu(A(MxK) * W(NxK)^T + bias) ----------------
__global__ void sgemm64_relu(const float* __restrict__ A, int lda,
                             const float* __restrict__ W, int ldw,
                             float* __restrict__ C, int ldc, int K,
                             const float* __restrict__ bias) {
    __shared__ float As[64][17];
    __shared__ float Ws[64][17];
    int tid = threadIdx.x;
    int m0 = blockIdx.y * 64, n0 = blockIdx.x * 64;
    int ty = tid >> 4, tx = tid & 15;
    float acc[4][4] = {};

    for (int k0 = 0; k0 < K; k0 += 16) {
        #pragma unroll
        for (int l = tid; l < 64*16; l += 256) {
            int r = l >> 4, c = l & 15;
            As[r][c] = A[(m0 + r) * lda + k0 + c];
            Ws[r][c] = W[(n0 + r) * ldw + k0 + c];
        }
        __syncthreads();
        #pragma unroll
        for (int kk = 0; kk < 16; kk++) {
            float a[4], w[4];
            #pragma unroll
            for (int i = 0; i < 4; i++) { a[i] = As[ty*4 + i][kk]; w[i] = Ws[tx*4 + i][kk]; }
            #pragma unroll
            for (int i = 0; i < 4; i++)
                #pragma unroll
                for (int j = 0; j < 4; j++) acc[i][j] += a[i] * w[j];
        }
        __syncthreads();
    }

    #pragma unroll
    for (int i = 0; i < 4; i++) {
        int m = m0 + ty*4 + i;
        #pragma unroll
        for (int j = 0; j < 4; j++) {
            int n = n0 + tx*4 + j;
            C[m*ldc + n] = fmaxf(acc[i][j] + bias[n], 0.0f);
        }
    }
}

#define HG_LDA 72

// ---------------- HMMA gates: gates = acat @ Wcat^T + bsum (3-term fp16) ----------------
// CTA 64(M) x 128(N), warps 2x4, warp 32x32. K=192, 3 chunks, single-buffer.
#define GT_A    (64 * HG_LDA * 2)      // 9216 per A limb
#define GT_B    (128 * HG_LDA * 2)     // 18432 per B limb
#define GT_DYN  (2*GT_A + 2*GT_B)      // 55296

__global__ void __launch_bounds__(256, 1)
hgemm_gates() {
    extern __shared__ char dyn[];
    const int tid  = threadIdx.x;
    const int lane = tid & 31;
    const int wid  = tid >> 5;
    const int wm   = wid >> 2;      // 0..1
    const int wn   = wid & 3;       // 0..3
    const int n0 = blockIdx.x * 128;
    const int m0 = blockIdx.y * 64;

    uint32_t sAh = smem_u32(dyn);
    uint32_t sAl = sAh + GT_A;
    uint32_t sBh = sAl + GT_A;
    uint32_t sBl = sBh + GT_B;
    float acc[2][4][4] = {};

    const int a_row  = wm * 32 + (lane & 15);
    const int a_colg = (lane >> 4) * 8;
    const int b_sub  = ((lane >> 4) & 1) * 8 + (lane & 7);
    const int b_colg = ((lane >> 3) & 1) * 8;

    for (int c = 0; c < 3; c++) {
        int kc = c * 64;
        const __half* Ah = g_acath + (size_t)m0 * KCAT + kc;
        const __half* Al = g_acatl + (size_t)m0 * KCAT + kc;
        const __half* Bh = g_Wch + (size_t)n0 * KCAT + kc;
        const __half* Bl = g_Wcl + (size_t)n0 * KCAT + kc;
        #pragma unroll
        for (int u = 0; u < 2; u++) {
            int idx = tid + u * 256;          // 0..511
            int row = idx >> 3, seg = idx & 7;
            uint32_t off = (uint32_t)(row * HG_LDA + seg * 8) * 2;
            cp_async16(sAh + off, Ah + (size_t)row * KCAT + seg * 8);
            cp_async16(sAl + off, Al + (size_t)row * KCAT + seg * 8);
        }
        #pragma unroll
        for (int u = 0; u < 4; u++) {
            int idx = tid + u * 256;          // 0..1023
            int row = idx >> 3, seg = idx & 7;
            uint32_t off = (uint32_t)(row * HG_LDA + seg * 8) * 2;
            cp_async16(sBh + off, Bh + (size_t)row * KCAT + seg * 8);
            cp_async16(sBl + off, Bl + (size_t)row * KCAT + seg * 8);
        }
        CP_COMMIT();
        CP_WAIT0();
        __syncthreads();

        #pragma unroll
        for (int ks = 0; ks < 4; ks++) {
            uint32_t bh[2][4], bl[2][4];
            #pragma unroll
            for (int nf2 = 0; nf2 < 2; nf2++) {
                uint32_t ro = (uint32_t)((wn*32 + nf2*16 + b_sub) * HG_LDA + ks*16 + b_colg) * 2;
                ldmatrix_x4(bh[nf2], sBh + ro);
                ldmatrix_x4(bl[nf2], sBl + ro);
            }
            uint32_t ah[2][4], al[2][4];
            #pragma unroll
            for (int mf = 0; mf < 2; mf++) {
                uint32_t ro = (uint32_t)((a_row + mf*16) * HG_LDA + ks*16 + a_colg) * 2;
                ldmatrix_x4(ah[mf], sAh + ro);
                ldmatrix_x4(al[mf], sAl + ro);
            }
            #pragma unroll
            for (int mf = 0; mf < 2; mf++)
                #pragma unroll
                for (int nf = 0; nf < 4; nf++) {
                    uint32_t bh0 = bh[nf>>1][(nf&1)*2], bh1 = bh[nf>>1][(nf&1)*2 + 1];
                    uint32_t bl0 = bl[nf>>1][(nf&1)*2], bl1 = bl[nf>>1][(nf&1)*2 + 1];
                    mma_f16(acc[mf][nf], ah[mf], bh0, bh1);
                    mma_f16(acc[mf][nf], ah[mf], bl0, bl1);
                    mma_f16(acc[mf][nf], al[mf], bh0, bh1);
                }
        }
        __syncthreads();
    }

    #pragma unroll
    for (int mf = 0; mf < 2; mf++) {
        int R  = m0 + wm*32 + mf*16 + (lane >> 2);
        int R8 = R + 8;
        #pragma unroll
        for (int nf = 0; nf < 4; nf++) {
            int n = n0 + wn*32 + nf*8 + (lane & 3)*2;
            float b0 = g_bsum[n], b1v = g_bsum[n + 1];
            g_gates[(size_t)R  * GATES + n]     = acc[mf][nf][0] + b0;
            g_gates[(size_t)R  * GATES + n + 1] = acc[mf][nf][1] + b1v;
            g_gates[(size_t)R8 * GATES + n]     = acc[mf][nf][2] + b0;
            g_gates[(size_t)R8 * GATES + n + 1] = acc[mf][nf][3] + b1v;
        }
    }
}

// ---------------- HMMA hW1h: hW1h = h @ W1h^T (h 2-limb x W1h fp16) ----------------
// CTA 64(M) x 128(N), warps 2x4, warp 32x32. K=128, 2 chunks, single-buffer.
#define HW_A    (64 * HG_LDA * 2)
#define HW_B    (128 * HG_LDA * 2)
#define HW_DYN  (2*HW_A + HW_B)        // 36864

__global__ void __launch_bounds__(256, 1)
hgemm_hw1h() {
    extern __shared__ char dyn[];
    const int tid  = threadIdx.x;
    const int lane = tid & 31;
    const int wid  = tid >> 5;
    const int wm   = wid >> 2;      // 0..1
    const int wn   = wid & 3;       // 0..3
    const int n0 = blockIdx.x * 128;
    const int m0 = blockIdx.y * 64;

    uint32_t sAh = smem_u32(dyn);
    uint32_t sAl = sAh + HW_A;
    uint32_t sB  = sAl + HW_A;
    float acc[2][4][4] = {};

    const int a_row  = wm * 32 + (lane & 15);
    const int a_colg = (lane >> 4) * 8;
    const int b_sub  = ((lane >> 4) & 1) * 8 + (lane & 7);
    const int b_colg = ((lane >> 3) & 1) * 8;

    for (int c = 0; c < 2; c++) {
        int kc = c * 64;
        const __half* Ah = g_hh16 + (size_t)m0 * HD + kc;
        const __half* Al = g_hl16 + (size_t)m0 * HD + kc;
        const __half* Bp = g_W1hh + (size_t)n0 * HD + kc;
        #pragma unroll
        for (int u = 0; u < 2; u++) {
            int idx = tid + u * 256;
            int row = idx >> 3, seg = idx & 7;
            uint32_t off = (uint32_t)(row * HG_LDA + seg * 8) * 2;
            cp_async16(sAh + off, Ah + (size_t)row * HD + seg * 8);
            cp_async16(sAl + off, Al + (size_t)row * HD + seg * 8);
        }
        #pragma unroll
        for (int u = 0; u < 4; u++) {
            int idx = tid + u * 256;
            int row = idx >> 3, seg = idx & 7;
            cp_async16(sB + (uint32_t)(row * HG_LDA + seg * 8) * 2,
                       Bp + (size_t)row * HD + seg * 8);
        }
        CP_COMMIT();
        CP_WAIT0();
        __syncthreads();

        #pragma unroll
        for (int ks = 0; ks < 4; ks++) {
            uint32_t bfr[2][4];
            #pragma unroll
            for (int nf2 = 0; nf2 < 2; nf2++)
                ldmatrix_x4(bfr[nf2], sB + (uint32_t)((wn*32 + nf2*16 + b_sub) * HG_LDA + ks*16 + b_colg) * 2);
            uint32_t ah[2][4], al[2][4];
            #pragma unroll
            for (int mf = 0; mf < 2; mf++) {
                uint32_t ro = (uint32_t)((a_row + mf*16) * HG_LDA + ks*16 + a_colg) * 2;
                ldmatrix_x4(ah[mf], sAh + ro);
                ldmatrix_x4(al[mf], sAl + ro);
            }
            #pragma unroll
            for (int mf = 0; mf < 2; mf++)
                #pragma unroll
                for (int nf = 0; nf < 4; nf++) {
                    uint32_t b0 = bfr[nf>>1][(nf&1)*2], b1 = bfr[nf>>1][(nf&1)*2 + 1];
                    mma_f16(acc[mf][nf], ah[mf], b0, b1);
                    mma_f16(acc[mf][nf], al[mf], b0, b1);
                }
        }
        __syncthreads();
    }

    #pragma unroll
    for (int mf = 0; mf < 2; mf++) {
        int R  = m0 + wm*32 + mf*16 + (lane >> 2);
        int R8 = R + 8;
        #pragma unroll
        for (int nf = 0; nf < 4; nf++) {
            int n = n0 + wn*32 + nf*8 + (lane & 3)*2;
            g_hW1h[(size_t)R  * PRE + n]     = acc[mf][nf][0];
            g_hW1h[(size_t)R  * PRE + n + 1] = acc[mf][nf][1];
            g_hW1h[(size_t)R8 * PRE + n]     = acc[mf][nf][2];
            g_hW1h[(size_t)R8 * PRE + n + 1] = acc[mf][nf][3];
        }
    }
}

// ---------------- X1 HMMA (fp16: emb 2-limb x W1e): single-stage, K=64 ----------------
// CTA 256x128, 8 warps (4x2), warp 64x64.
#define X1_AH      (256 * HG_LDA * 2)   // 36864 per emb limb
#define X1_B       (128 * HG_LDA * 2)   // 18432
#define X1_DYN     (2 * X1_AH + X1_B)   // 92160

__global__ void __launch_bounds__(256, 1)
hgemm_x1(const float* __restrict__ bias, const float* __restrict__ aux) {
    extern __shared__ char dyn[];
    const int tid  = threadIdx.x;
    const int lane = tid & 31;
    const int wid  = tid >> 5;
    const int wm   = wid >> 1;      // 0..3
    const int wn   = wid & 1;       // 0..1
    const int n0 = blockIdx.x * 128;
    const int m0 = blockIdx.y * 256;

    uint32_t sbase = smem_u32(dyn);
    uint32_t sAh = sbase;
    uint32_t sAl = sAh + X1_AH;
    uint32_t sB  = sAl + X1_AH;
    float acc[4][8][4] = {};

    const int a_row  = wm * 64 + (lane & 15);
    const int a_colg = (lane >> 4) * 8;
    const int b_sub  = ((lane >> 4) & 1) * 8 + (lane & 7);
    const int b_colg = ((lane >> 3) & 1) * 8;

    {
        const __half* Ah = g_embh + (size_t)m0 * ED;
        const __half* Al = g_embl + (size_t)m0 * ED;
        const __half* Bp = g_W1eh + (size_t)n0 * ED;
        #pragma unroll
        for (int u = 0; u < 8; u++) {
            int idx = tid + u * 256;          // 0..2047
            int row = idx >> 3, seg = idx & 7;
            uint32_t off = (uint32_t)(row * HG_LDA + seg * 8) * 2;
            cp_async16(sAh + off, Ah + (size_t)row * ED + seg * 8);
            cp_async16(sAl + off, Al + (size_t)row * ED + seg * 8);
        }
        #pragma unroll
        for (int u = 0; u < 4; u++) {
            int idx = tid + u * 256;          // 0..1023
            int row = idx >> 3, seg = idx & 7;
            cp_async16(sB + (uint32_t)(row * HG_LDA + seg * 8) * 2,
                       Bp + (size_t)row * ED + seg * 8);
        }
        CP_COMMIT();
        CP_WAIT0();
        __syncthreads();
    }

    #pragma unroll
    for (int ks = 0; ks < 4; ks++) {
        uint32_t bfr[4][4];
        #pragma unroll
        for (int nf2 = 0; nf2 < 4; nf2++)
            ldmatrix_x4(bfr[nf2], sB + (uint32_t)((wn*64 + nf2*16 + b_sub) * HG_LDA + ks*16 + b_colg) * 2);
        {
            uint32_t afr[4][4];
            #pragma unroll
            for (int mf = 0; mf < 4; mf++)
                ldmatrix_x4(afr[mf], sAh + (uint32_t)((a_row + mf*16) * HG_LDA + ks*16 + a_colg) * 2);
            #pragma unroll
            for (int mf = 0; mf < 4; mf++)
                #pragma unroll
                for (int nf = 0; nf < 8; nf++)
                    mma_f16(acc[mf][nf], afr[mf], bfr[nf>>1][(nf&1)*2], bfr[nf>>1][(nf&1)*2 + 1]);
        }
        {
            uint32_t afr[4][4];
            #pragma unroll
            for (int mf = 0; mf < 4; mf++)
                ldmatrix_x4(afr[mf], sAl + (uint32_t)((a_row + mf*16) * HG_LDA + ks*16 + a_colg) * 2);
            #pragma unroll
            for (int mf = 0; mf < 4; mf++)
                #pragma unroll
                for (int nf = 0; nf < 8; nf++)
                    mma_f16(acc[mf][nf], afr[mf], bfr[nf>>1][(nf&1)*2], bfr[nf>>1][(nf&1)*2 + 1]);
        }
    }

    #pragma unroll
    for (int mf = 0; mf < 4; mf++) {
        int R  = m0 + wm*64 + mf*16 + (lane >> 2);
        int R8 = R + 8;
        const float* aux0 = aux + (size_t)((R  >> 10)*32 + (R  & 31)) * PRE;
        const float* aux8 = aux + (size_t)((R8 >> 10)*32 + (R8 & 31)) * PRE;
        #pragma unroll
        for (int nf = 0; nf < 8; nf++) {
            int n = n0 + wn*64 + nf*8 + (lane & 3)*2;
            float b0 = bias[n], b1v = bias[n + 1];
            float v0 = fmaxf(acc[mf][nf][0] + b0  + aux0[n],     0.0f);
            float v1 = fmaxf(acc[mf][nf][1] + b1v + aux0[n + 1], 0.0f);
            float v2 = fmaxf(acc[mf][nf][2] + b0  + aux8[n],     0.0f);
            float v3 = fmaxf(acc[mf][nf][3] + b1v + aux8[n + 1], 0.0f);
            __half2 h01, h23;
            h01.x = __float2half(v0); h01.y = __float2half(v1);
            h23.x = __float2half(v2); h23.y = __float2half(v3);
            *reinterpret_cast<__half2*>(&g_X1h[(size_t)R  * PRE + n]) = h01;
            *reinterpret_cast<__half2*>(&g_X1h[(size_t)R8 * PRE + n]) = h23;
        }
    }
}

// ---------------- fp16 GEMM2: pool = relu(max_j(X1 @ W2^T) + b2) ----------------
#define G2_A       (256 * HG_LDA * 2)    // 36864
#define G2_B       (128 * HG_LDA * 2)    // 18432
#define G2_STG     (G2_A + G2_B)         // 55296
#define G2_DYN     (2 * G2_STG)          // 110592

__global__ void __launch_bounds__(256, 1)
gemm2_f16(const float* __restrict__ b2, float* __restrict__ pool) {
    extern __shared__ char dyn[];
    const int tid  = threadIdx.x;
    const int lane = tid & 31;
    const int wid  = tid >> 5;
    const int wm   = wid >> 1;      // 0..3
    const int wn   = wid & 1;       // 0..1
    const int n0 = blockIdx.x * 128;
    const int m0 = blockIdx.y * 256;

    uint32_t sbase = smem_u32(dyn);
    float acc[4][8][4] = {};

    const int a_row  = wm * 64 + (lane & 15);
    const int a_colg = (lane >> 4) * 8;
    const int b_sub  = ((lane >> 4) & 1) * 8 + (lane & 7);
    const int b_colg = ((lane >> 3) & 1) * 8;

    auto load_chunk = [&](int c, int s) {
        int kc = c * 64;
        const __half* Ap = g_X1h + (size_t)m0 * PRE + kc;
        const __half* Bp = g_W2h + (size_t)n0 * PRE + kc;
        uint32_t sA = sbase + s * G2_STG;
        uint32_t sB = sA + G2_A;
        #pragma unroll
        for (int u = 0; u < 8; u++) {
            int idx = tid + u * 256;
            int row = idx >> 3, seg = idx & 7;
            cp_async16(sA + (uint32_t)(row * HG_LDA + seg * 8) * 2,
                       Ap + (size_t)row * PRE + seg * 8);
        }
        #pragma unroll
        for (int u = 0; u < 4; u++) {
            int idx = tid + u * 256;
            int row = idx >> 3, seg = idx & 7;
            cp_async16(sB + (uint32_t)(row * HG_LDA + seg * 8) * 2,
                       Bp + (size_t)row * PRE + seg * 8);
        }
    };

    load_chunk(0, 0);
    CP_COMMIT();

    for (int c = 0; c < 8; c++) {
        if (c + 1 < 8) { load_chunk(c + 1, (c + 1) & 1); CP_COMMIT(); CP_WAIT1(); }
        else CP_WAIT0();
        __syncthreads();

        uint32_t sA = sbase + (c & 1) * G2_STG;
        uint32_t sB = sA + G2_A;
        #pragma unroll
        for (int ks = 0; ks < 4; ks++) {
            uint32_t bfr[4][4];
            #pragma unroll
            for (int nf2 = 0; nf2 < 4; nf2++)
                ldmatrix_x4(bfr[nf2], sB + (uint32_t)((wn*64 + nf2*16 + b_sub) * HG_LDA + ks*16 + b_colg) * 2);
            uint32_t afr[4][4];
            #pragma unroll
            for (int mf = 0; mf < 4; mf++)
                ldmatrix_x4(afr[mf], sA + (uint32_t)((a_row + mf*16) * HG_LDA + ks*16 + a_colg) * 2);
            #pragma unroll
            for (int mf = 0; mf < 4; mf++)
                #pragma unroll
                for (int nf = 0; nf < 8; nf++)
                    mma_f16(acc[mf][nf], afr[mf], bfr[nf>>1][(nf&1)*2], bfr[nf>>1][(nf&1)*2 + 1]);
        }
        __syncthreads();
    }

    #pragma unroll
    for (int half = 0; half < 2; half++) {
        int pr = blockIdx.y * 8 + wm * 2 + half;    // pool row = m/32
        #pragma unroll
        for (int nf = 0; nf < 8; nf++) {
            float v0 = fmaxf(fmaxf(acc[2*half][nf][0], acc[2*half][nf][2]),
                             fmaxf(acc[2*half+1][nf][0], acc[2*half+1][nf][2]));
            float v1 = fmaxf(fmaxf(acc[2*half][nf][1], acc[2*half][nf][3]),
                             fmaxf(acc[2*half+1][nf][1], acc[2*half+1][nf][3]));
            #pragma unroll
            for (int d = 4; d < 32; d <<= 1) {
                v0 = fmaxf(v0, __shfl_xor_sync(0xffffffffu, v0, d));
                v1 = fmaxf(v1, __shfl_xor_sync(0xffffffffu, v1, d));
            }
            if ((lane >> 2) == 0) {
                int n = n0 + wn*64 + nf*8 + (lane & 3)*2;
                pool[pr * BOTTLE + n]     = fmaxf(v0 + b2[n], 0.0f);
                pool[pr * BOTTLE + n + 1] = fmaxf(v1 + b2[n + 1], 0.0f);
            }
        }
    }
}

// ---------------- fp16 D1: D1 = relu(dcat @ Wm1^T + bm1) ----------------
#define D1_A    (64 * HG_LDA * 2)     // 9216
#define D1_B    (128 * HG_LDA * 2)    // 18432
#define D1_STG  (D1_A + D1_B)         // 27648
#define D1_DYN  (2 * D1_STG)          // 55296

__global__ void __launch_bounds__(256, 1)
hgemm_d1(const float* __restrict__ bias) {
    extern __shared__ char dyn[];
    const int tid  = threadIdx.x;
    const int lane = tid & 31;
    const int wid  = tid >> 5;
    const int wm   = wid >> 2;      // 0..1
    const int wn   = wid & 3;       // 0..3
    const int n0 = blockIdx.x * 128;
    const int m0 = blockIdx.y * 64;

    uint32_t sbase = smem_u32(dyn);
    float acc[2][4][4] = {};

    const int a_row  = wm * 32 + (lane & 15);
    const int a_colg = (lane >> 4) * 8;
    const int b_sub  = ((lane >> 4) & 1) * 8 + (lane & 7);
    const int b_colg = ((lane >> 3) & 1) * 8;

    auto load_chunk = [&](int c, int s) {
        int kc = c * 64;
        const __half* Ap = g_dch + (size_t)m0 * DHK + kc;
        const __half* Bp = g_Wm1h + (size_t)n0 * DHK + kc;
        uint32_t sA = sbase + s * D1_STG;
        uint32_t sB = sA + D1_A;
        #pragma unroll
        for (int u = 0; u < 2; u++) {
            int idx = tid + u * 256;
            int row = idx >> 3, seg = idx & 7;
            cp_async16(sA + (uint32_t)(row * HG_LDA + seg * 8) * 2,
                       Ap + (size_t)row * DHK + seg * 8);
        }
        #pragma unroll
        for (int u = 0; u < 4; u++) {
            int idx = tid + u * 256;
            int row = idx >> 3, seg = idx & 7;
            cp_async16(sB + (uint32_t)(row * HG_LDA + seg * 8) * 2,
                       Bp + (size_t)row * DHK + seg * 8);
        }
    };

    load_chunk(0, 0);
    CP_COMMIT();

    for (int c = 0; c < 18; c++) {
        if (c + 1 < 18) { load_chunk(c + 1, (c + 1) & 1); CP_COMMIT(); CP_WAIT1(); }
        else CP_WAIT0();
        __syncthreads();

        uint32_t sA = sbase + (c & 1) * D1_STG;
        uint32_t sB = sA + D1_A;
        #pragma unroll
        for (int ks = 0; ks < 4; ks++) {
            uint32_t bfr[2][4];
            #pragma unroll
            for (int nf2 = 0; nf2 < 2; nf2++)
                ldmatrix_x4(bfr[nf2], sB + (uint32_t)((wn*32 + nf2*16 + b_sub) * HG_LDA + ks*16 + b_colg) * 2);
            uint32_t afr[2][4];
            #pragma unroll
            for (int mf = 0; mf < 2; mf++)
                ldmatrix_x4(afr[mf], sA + (uint32_t)((a_row + mf*16) * HG_LDA + ks*16 + a_colg) * 2);
            #pragma unroll
            for (int mf = 0; mf < 2; mf++)
                #pragma unroll
                for (int nf = 0; nf < 4; nf++)
                    mma_f16(acc[mf][nf], afr[mf], bfr[nf>>1][(nf&1)*2], bfr[nf>>1][(nf&1)*2 + 1]);
        }
        __syncthreads();
    }

    #pragma unroll
    for (int mf = 0; mf < 2; mf++) {
        int R  = m0 + wm*32 + mf*16 + (lane >> 2);
        int R8 = R + 8;
        #pragma unroll
        for (int nf = 0; nf < 4; nf++) {
            int n = n0 + wn*32 + nf*8 + (lane & 3)*2;
            float b0 = bias[n], b1v = bias[n + 1];
            g_D1[(size_t)R  * MLPD + n]     = fmaxf(acc[mf][nf][0] + b0,  0.0f);
            g_D1[(size_t)R  * MLPD + n + 1] = fmaxf(acc[mf][nf][1] + b1v, 0.0f);
            g_D1[(size_t)R8 * MLPD + n]     = fmaxf(acc[mf][nf][2] + b0,  0.0f);
            g_D1[(size_t)R8 * MLPD + n + 1] = fmaxf(acc[mf][nf][3] + b1v, 0.0f);
        }
    }
}

// ---------------- launch ----------------
extern "C" void kernel_launch(void* const* d_in, const int* in_sizes, int n_in,
                              void* d_out, int out_size) {
    const float* last_pos      = (const float*)d_in[0];
    const float* last_pos_rel  = (const float*)d_in[1];
    const float* hh            = (const float*)d_in[2];
    const float* ch            = (const float*)d_in[3];
    const float* pred_traj_rel = (const float*)d_in[4];
    const float* W_ih = (const float*)d_in[6];
    const float* W_hh = (const float*)d_in[7];
    const float* b_ih = (const float*)d_in[8];
    const float* b_hh = (const float*)d_in[9];
    const float* Wse  = (const float*)d_in[10];
    const float* bse  = (const float*)d_in[11];
    const float* Wpos = (const float*)d_in[12];
    const float* bpos = (const float*)d_in[13];
    const float* Wp   = (const float*)d_in[14];
    const float* bp   = (const float*)d_in[15];
    const float* W1   = (const float*)d_in[16];
    const float* b1   = (const float*)d_in[17];
    const float* W2   = (const float*)d_in[18];
    const float* b2   = (const float*)d_in[19];
    const float* Wm1  = (const float*)d_in[20];
    const float* bm1  = (const float*)d_in[21];
    const float* Wm2  = (const float*)d_in[22];
    const float* bm2  = (const float*)d_in[23];

    float* out = (float*)d_out;

    float* p_hW1h  = nullptr; cudaGetSymbolAddress((void**)&p_hW1h,  g_hW1h);
    float* p_pool  = nullptr; cudaGetSymbolAddress((void**)&p_pool,  g_pool);
    float* p_D1    = nullptr; cudaGetSymbolAddress((void**)&p_D1,    g_D1);
    float* p_h     = nullptr; cudaGetSymbolAddress((void**)&p_h,     g_h);

    cudaFuncSetAttribute(hgemm_gates, cudaFuncAttributeMaxDynamicSharedMemorySize, GT_DYN);
    cudaFuncSetAttribute(hgemm_hw1h,  cudaFuncAttributeMaxDynamicSharedMemorySize, HW_DYN);
    cudaFuncSetAttribute(hgemm_x1,    cudaFuncAttributeMaxDynamicSharedMemorySize, X1_DYN);
    cudaFuncSetAttribute(gemm2_f16,   cudaFuncAttributeMaxDynamicSharedMemorySize, G2_DYN);
    cudaFuncSetAttribute(hgemm_d1,    cudaFuncAttributeMaxDynamicSharedMemorySize, D1_DYN);

    init_kernel<<<(MLPD*DHK + 255)/256, 256>>>(hh, ch, last_pos, last_pos_rel,
                                               W_ih, W_hh, b_ih, b_hh, Wse, bse, W1, W2, Wm1);

    for (int t = 0; t < SEQ_LEN; t++) {
        const float* gt = pred_traj_rel + t * BATCH * 2;
        float* out_pred = out + t * BATCH * 2;

        // LSTM cell: pack -> HMMA gates -> fused elementwise/pos/loss
        pack_lstm_kernel<<<(BATCH*KCAT + 255)/256, 256>>>();
        hgemm_gates<<<dim3(GATES/128, BATCH/64), 256, GT_DYN>>>();
        lstm_pos_kernel<<<BATCH, HD>>>(Wpos, bpos, gt, out_pred);

        // pool net
        emb_kernel<<<(ROWS_PN*ED + 255)/256, 256>>>(Wp, bp);
        hgemm_hw1h<<<dim3(PRE/128, BATCH/64), 256, HW_DYN>>>();
        hgemm_x1<<<dim3(PRE/128, ROWS_PN/256), 256, X1_DYN>>>(b1, p_hW1h);
        gemm2_f16<<<dim3(BOTTLE/128, ROWS_PN/256), 256, G2_DYN>>>(b2, p_pool);

        // decoder MLP
        pack_dh_kernel<<<(BATCH*DHK + 255)/256, 256>>>();
        hgemm_d1<<<dim3(MLPD/128, BATCH/64), 256, D1_DYN>>>(bm1);
        sgemm64_relu<<<dim3(HD/64, BATCH/64), 256>>>(p_D1, MLPD, Wm2, MLPD,
                                                     p_h, HD, MLPD, bm2);

        decin_kernel<<<(BATCH*ED + 255)/256, 256>>>(gt, Wse, bse);
    }

    finish_kernel<<<1, BATCH>>>(out, out_size);
}

// round 13
// speedup vs baseline: 3.3578x; 1.0026x over previous
#include <cuda_runtime.h>
#include <cuda_bf16.h>
#include <cuda_fp16.h>
#include <math.h>
#include <stdint.h>

// Problem dims
#define SEQ_LEN 12
#define BATCH   512
#define NG      16
#define GROUP   32
#define HD      128      // H
#define ED      64       // E
#define PRE     512
#define BOTTLE  1024
#define MLPD    1024
#define GATES   (4*HD)   // 512
#define KCAT    (ED+HD)  // 192
#define ROWS_PN (NG*GROUP*GROUP)  // 16384
#define DHK     (HD+BOTTLE)       // 1152

// ---------------- scratch (device globals; no allocation) ----------------
__device__ float g_h[BATCH*HD];
__device__ float g_c[BATCH*HD];
__device__ float g_pos[BATCH*2];
__device__ __align__(16) __half g_deh[SEQ_LEN*BATCH*ED];  // dec_in fp16 hi, all steps
__device__ __align__(16) __half g_del[SEQ_LEN*BATCH*ED];  // dec_in fp16 lo, all steps
__device__ __align__(16) __half g_Wch[GATES*KCAT];      // Wcat fp16 hi
__device__ __align__(16) __half g_Wcl[GATES*KCAT];      // Wcat fp16 lo
__device__ float g_bsum[GATES];
__device__ float g_gates[BATCH*GATES];
__device__ __align__(16) __half g_hh16[BATCH*HD];       // h fp16 hi limb (tracks current h)
__device__ __align__(16) __half g_hl16[BATCH*HD];       // h fp16 lo limb
__device__ __align__(16) __half g_W1hh[PRE*HD];         // W1 h-part fp16
__device__ __align__(16) __half g_embh[ROWS_PN*ED];     // emb fp16 hi limb
__device__ __align__(16) __half g_embl[ROWS_PN*ED];     // emb fp16 lo limb
__device__ __align__(16) __half g_W1eh[PRE*ED];         // W1 emb-part fp16
__device__ float g_hW1h[BATCH*PRE];
__device__ __align__(16) __half g_X1h[ROWS_PN*PRE];     // X1 fp16
__device__ __align__(16) __half g_W2h[BOTTLE*PRE];      // W2 fp16
__device__ __align__(16) __half g_dch[BATCH*DHK];       // dcat fp16 = [h | pool]
__device__ __align__(16) __half g_Wm1h[MLPD*DHK];       // Wm1 fp16
__device__ float g_D1[BATCH*MLPD];
__device__ float g_sqacc[BATCH];

__device__ __forceinline__ float sigmoidf(float x) { return 1.0f / (1.0f + expf(-x)); }

// ---------------- PTX helpers (base-arch only: sm_80+ features) ----------------
__device__ __forceinline__ uint32_t smem_u32(const void* p) {
    uint32_t a;
    asm("{ .reg .u64 t; cvta.to.shared.u64 t, %1; cvt.u32.u64 %0, t; }" : "=r"(a) : "l"(p));
    return a;
}
__device__ __forceinline__ void cp_async16(uint32_t s, const void* g) {
    asm volatile("cp.async.cg.shared.global [%0], [%1], 16;" :: "r"(s), "l"(g));
}
#define CP_COMMIT() asm volatile("cp.async.commit_group;" ::: "memory")
#define CP_WAIT1()  asm volatile("cp.async.wait_group 1;" ::: "memory")
#define CP_WAIT0()  asm volatile("cp.async.wait_group 0;" ::: "memory")

__device__ __forceinline__ void ldmatrix_x4(uint32_t* r, uint32_t addr) {
    asm volatile("ldmatrix.sync.aligned.m8n8.x4.shared.b16 {%0,%1,%2,%3}, [%4];"
                 : "=r"(r[0]), "=r"(r[1]), "=r"(r[2]), "=r"(r[3]) : "r"(addr));
}
__device__ __forceinline__ void mma_f16(float* c, const uint32_t* a, uint32_t b0, uint32_t b1) {
    asm volatile("mma.sync.aligned.m16n8k16.row.col.f32.f16.f16.f32 "
                 "{%0,%1,%2,%3}, {%4,%5,%6,%7}, {%8,%9}, {%0,%1,%2,%3};"
                 : "+f"(c[0]), "+f"(c[1]), "+f"(c[2]), "+f"(c[3])
                 : "r"(a[0]), "r"(a[1]), "r"(a[2]), "r"(a[3]), "r"(b0), "r"(b1));
}

// ---------------- init ----------------
__global__ void init_kernel(const float* __restrict__ hh, const float* __restrict__ ch,
                            const float* __restrict__ last_pos,
                            const float* __restrict__ Wih, const float* __restrict__ Whh,
                            const float* __restrict__ bih, const float* __restrict__ bhh,
                            const float* __restrict__ W1, const float* __restrict__ W2,
                            const float* __restrict__ Wm1) {
    int idx = blockIdx.x * blockDim.x + threadIdx.x;
    if (idx < BATCH*HD) {
        float h = hh[idx];
        g_h[idx] = h; g_c[idx] = ch[idx];
        __half hv = __float2half(h);
        g_hh16[idx] = hv;
        g_hl16[idx] = __float2half(h - __half2float(hv));
    }
    if (idx < BATCH*2)  g_pos[idx] = last_pos[idx];
    if (idx < BATCH)    g_sqacc[idx] = 0.0f;
    if (idx < GATES) g_bsum[idx] = bih[idx] + bhh[idx];
    if (idx < GATES*KCAT) {
        int n = idx / KCAT, k = idx % KCAT;
        float w = (k < ED) ? Wih[n*ED + k] : Whh[n*HD + (k - ED)];
        __half hi = __float2half(w);
        g_Wch[idx] = hi;
        g_Wcl[idx] = __float2half(w - __half2float(hi));
    }
    if (idx < PRE*ED) {
        int n = idx >> 6, k = idx & 63;
        g_W1eh[idx] = __float2half(W1[n*KCAT + k]);
    }
    if (idx < PRE*HD) {
        int n = idx >> 7, k = idx & 127;
        g_W1hh[idx] = __float2half(W1[n*KCAT + ED + k]);
    }
    if (idx < BOTTLE*PRE) g_W2h[idx] = __float2half(W2[idx]);
    if (idx < MLPD*DHK)   g_Wm1h[idx] = __float2half(Wm1[idx]);
}

// Precompute dec_in spatial embeddings for ALL steps (teacher forcing is static).
__global__ void decall_kernel(const float* __restrict__ last_pos_rel,
                              const float* __restrict__ pred_traj_rel,
                              const float* __restrict__ Wse, const float* __restrict__ bse) {
    int idx = blockIdx.x * blockDim.x + threadIdx.x;
    if (idx >= SEQ_LEN*BATCH*ED) return;
    int t = idx / (BATCH*ED);
    int r = idx % (BATCH*ED);
    int b = r / ED, e = r % ED;
    const float* rel = (t == 0) ? (last_pos_rel + b*2)
                                : (pred_traj_rel + ((size_t)(t-1)*BATCH + b)*2);
    float v = rel[0] * Wse[e*2] + rel[1] * Wse[e*2+1] + bse[e];
    __half hi = __float2half(v);
    g_deh[idx] = hi;
    g_del[idx] = __float2half(v - __half2float(hi));
}

// ---------------- fused LSTM elementwise + rel_pos + pos + loss accum ----------------
// 512 blocks x 128 threads; block b owns batch row b. Emits pre-MLP h limbs + dcat h-part.
__global__ void lstm_pos_kernel(const float* __restrict__ Wpos, const float* __restrict__ bpos,
                                const float* __restrict__ gt, float* __restrict__ out_pred) {
    int b = blockIdx.x, j = threadIdx.x;
    const float* gr = g_gates + b*GATES;
    float ig = gr[j], fg = gr[HD + j], gg = gr[2*HD + j], og = gr[3*HD + j];
    float c = sigmoidf(fg) * g_c[b*HD + j] + sigmoidf(ig) * tanhf(gg);
    float h = sigmoidf(og) * tanhf(c);
    g_c[b*HD + j] = c;
    __half hhv = __float2half(h);
    g_hh16[b*HD + j] = hhv;
    g_hl16[b*HD + j] = __float2half(h - __half2float(hhv));
    g_dch[(size_t)b*DHK + j] = hhv;

    __shared__ float sx[HD], sy[HD];
    sx[j] = h * Wpos[j];
    sy[j] = h * Wpos[HD + j];
    __syncthreads();
    for (int s = HD/2; s > 0; s >>= 1) {
        if (j < s) { sx[j] += sx[j + s]; sy[j] += sy[j + s]; }
        __syncthreads();
    }
    if (j == 0) {
        float rx = sx[0] + bpos[0], ry = sy[0] + bpos[1];
        out_pred[b*2]   = rx;
        out_pred[b*2+1] = ry;
        g_pos[b*2]   += rx;
        g_pos[b*2+1] += ry;
        float dx = rx - gt[b*2], dy = ry - gt[b*2+1];
        g_sqacc[b] += dx*dx + dy*dy;
    }
}

// ---------------- pairwise rel-pos embedding -> fp16 hi/lo ----------------
__global__ void emb_kernel(const float* __restrict__ Wp, const float* __restrict__ bp) {
    int idx = blockIdx.x * blockDim.x + threadIdx.x;
    if (idx >= ROWS_PN*ED) return;
    int r = idx >> 6, e = idx & 63;
    int g = r >> 10, i = (r >> 5) & 31, j = r & 31;
    int bi = g*GROUP + i, bj = g*GROUP + j;
    float rx = g_pos[bj*2]   - g_pos[bi*2];
    float ry = g_pos[bj*2+1] - g_pos[bi*2+1];
    float v = rx * Wp[e*2] + ry * Wp[e*2+1] + bp[e];
    __half hi = __float2half(v);
    g_embh[idx] = hi;
    g_embl[idx] = __float2half(v - __half2float(hi));
}

__global__ void finish_kernel(float* __restrict__ out, int out_size) {
    __shared__ float sd[BATCH];
    int t = threadIdx.x;
    sd[t] = g_sqacc[t];
    __syncthreads();
    for (int s = BATCH/2; s > 0; s >>= 1) {
        if (t < s) sd[t] += sd[t + s];
        __syncthreads();
    }
    if (t == 0 && out_size > SEQ_LEN*BATCH*2)
        out[SEQ_LEN*BATCH*2] = sd[0] / (float)(BATCH*2);
}

// ---------------- D2: h = relu(D1 @ Wm2^T + bm2); ALSO emits post-MLP h fp16 limbs ----------------
__global__ void d2_kernel(const float* __restrict__ A,       // g_D1, lda=MLPD
                          const float* __restrict__ W,       // Wm2, ldw=MLPD
                          const float* __restrict__ bias) {
    __shared__ float As[64][17];
    __shared__ float Ws[64][17];
    int tid = threadIdx.x;
    int m0 = blockIdx.y * 64, n0 = blockIdx.x * 64;
    int ty = tid >> 4, tx = tid & 15;
    float acc[4][4] = {};

    for (int k0 = 0; k0 < MLPD; k0 += 16) {
        #pragma unroll
        for (int l = tid; l < 64*16; l += 256) {
            int r = l >> 4, c = l & 15;
            As[r][c] = A[(m0 + r) * MLPD + k0 + c];
            Ws[r][c] = W[(n0 + r) * MLPD + k0 + c];
        }
        __syncthreads();
        #pragma unroll
        for (int kk = 0; kk < 16; kk++) {
            float a[4], w[4];
            #pragma unroll
            for (int i = 0; i < 4; i++) { a[i] = As[ty*4 + i][kk]; w[i] = Ws[tx*4 + i][kk]; }
            #pragma unroll
            for (int i = 0; i < 4; i++)
                #pragma unroll
                for (int j = 0; j < 4; j++) acc[i][j] += a[i] * w[j];
        }
        __syncthreads();
    }

    #pragma unroll
    for (int i = 0; i < 4; i++) {
        int m = m0 + ty*4 + i;
        #pragma unroll
        for (int j = 0; j < 4; j++) {
            int n = n0 + tx*4 + j;
            float v = fmaxf(acc[i][j] + bias[n], 0.0f);
            g_h[m*HD + n] = v;
            __half hv = __float2half(v);
            g_hh16[m*HD + n] = hv;                               // post-MLP limbs for next gates
            g_hl16[m*HD + n] = __float2half(v - __half2float(hv));
        }
    }
}

#define HG_LDA 72

// ---------------- HMMA gates: gates = [dec_in|h] @ Wcat^T + bsum (3-term fp16) ----------------
// A sources per k-chunk: chunk 0 = g_deh/g_del (stride ED), chunks 1,2 = g_hh16/g_hl16 (stride HD).
#define GT_A    (64 * HG_LDA * 2)      // 9216 per A limb
#define GT_B    (128 * HG_LDA * 2)     // 18432 per B limb
#define GT_DYN  (2*GT_A + 2*GT_B)      // 55296

__global__ void __launch_bounds__(256, 1)
hgemm_gates(int t) {
    extern __shared__ char dyn[];
    const int tid  = threadIdx.x;
    const int lane = tid & 31;
    const int wid  = tid >> 5;
    const int wm   = wid >> 2;      // 0..1
    const int wn   = wid & 3;       // 0..3
    const int n0 = blockIdx.x * 128;
    const int m0 = blockIdx.y * 64;

    uint32_t sAh = smem_u32(dyn);
    uint32_t sAl = sAh + GT_A;
    uint32_t sBh = sAl + GT_A;
    uint32_t sBl = sBh + GT_B;
    float acc[2][4][4] = {};

    const int a_row  = wm * 32 + (lane & 15);
    const int a_colg = (lane >> 4) * 8;
    const int b_sub  = ((lane >> 4) & 1) * 8 + (lane & 7);
    const int b_colg = ((lane >> 3) & 1) * 8;

    for (int c = 0; c < 3; c++) {
        int kc = c * 64;
        const __half *Ah, *Al;
        int lda;
        if (c == 0) {
            Ah = g_deh + (size_t)t*BATCH*ED + (size_t)m0 * ED;
            Al = g_del + (size_t)t*BATCH*ED + (size_t)m0 * ED;
            lda = ED;
        } else {
            Ah = g_hh16 + (size_t)m0 * HD + (c - 1) * 64;
            Al = g_hl16 + (size_t)m0 * HD + (c - 1) * 64;
            lda = HD;
        }
        const __half* Bh = g_Wch + (size_t)n0 * KCAT + kc;
        const __half* Bl = g_Wcl + (size_t)n0 * KCAT + kc;
        #pragma unroll
        for (int u = 0; u < 2; u++) {
            int idx = tid + u * 256;          // 0..511
            int row = idx >> 3, seg = idx & 7;
            uint32_t off = (uint32_t)(row * HG_LDA + seg * 8) * 2;
            cp_async16(sAh + off, Ah + (size_t)row * lda + seg * 8);
            cp_async16(sAl + off, Al + (size_t)row * lda + seg * 8);
        }
        #pragma unroll
        for (int u = 0; u < 4; u++) {
            int idx = tid + u * 256;          // 0..1023
            int row = idx >> 3, seg = idx & 7;
            uint32_t off = (uint32_t)(row * HG_LDA + seg * 8) * 2;
            cp_async16(sBh + off, Bh + (size_t)row * KCAT + seg * 8);
            cp_async16(sBl + off, Bl + (size_t)row * KCAT + seg * 8);
        }
        CP_COMMIT();
        CP_WAIT0();
        __syncthreads();

        #pragma unroll
        for (int ks = 0; ks < 4; ks++) {
            uint32_t bh[2][4], bl[2][4];
            #pragma unroll
            for (int nf2 = 0; nf2 < 2; nf2++) {
                uint32_t ro = (uint32_t)((wn*32 + nf2*16 + b_sub) * HG_LDA + ks*16 + b_colg) * 2;
                ldmatrix_x4(bh[nf2], sBh + ro);
                ldmatrix_x4(bl[nf2], sBl + ro);
            }
            uint32_t ah[2][4], al[2][4];
            #pragma unroll
            for (int mf = 0; mf < 2; mf++) {
                uint32_t ro = (uint32_t)((a_row + mf*16) * HG_LDA + ks*16 + a_colg) * 2;
                ldmatrix_x4(ah[mf], sAh + ro);
                ldmatrix_x4(al[mf], sAl + ro);
            }
            #pragma unroll
            for (int mf = 0; mf < 2; mf++)
                #pragma unroll
                for (int nf = 0; nf < 4; nf++) {
                    uint32_t bh0 = bh[nf>>1][(nf&1)*2], bh1 = bh[nf>>1][(nf&1)*2 + 1];
                    uint32_t bl0 = bl[nf>>1][(nf&1)*2], bl1 = bl[nf>>1][(nf&1)*2 + 1];
                    mma_f16(acc[mf][nf], ah[mf], bh0, bh1);
                    mma_f16(acc[mf][nf], ah[mf], bl0, bl1);
                    mma_f16(acc[mf][nf], al[mf], bh0, bh1);
                }
        }
        __syncthreads();
    }

    #pragma unroll
    for (int mf = 0; mf < 2; mf++) {
        int R  = m0 + wm*32 + mf*16 + (lane >> 2);
        int R8 = R + 8;
        #pragma unroll
        for (int nf = 0; nf < 4; nf++) {
            int n = n0 + wn*32 + nf*8 + (lane & 3)*2;
            float b0 = g_bsum[n], b1v = g_bsum[n + 1];
            g_gates[(size_t)R  * GATES + n]     = acc[mf][nf][0] + b0;
            g_gates[(size_t)R  * GATES + n + 1] = acc[mf][nf][1] + b1v;
            g_gates[(size_t)R8 * GATES + n]     = acc[mf][nf][2] + b0;
            g_gates[(size_t)R8 * GATES + n + 1] = acc[mf][nf][3] + b1v;
        }
    }
}

// ---------------- HMMA hW1h: hW1h = h @ W1h^T (h 2-limb x W1h fp16) ----------------
#define HW_A    (64 * HG_LDA * 2)
#define HW_B    (128 * HG_LDA * 2)
#define HW_DYN  (2*HW_A + HW_B)        // 36864

__global__ void __launch_bounds__(256, 1)
hgemm_hw1h() {
    extern __shared__ char dyn[];
    const int tid  = threadIdx.x;
    const int lane = tid & 31;
    const int wid  = tid >> 5;
    const int wm   = wid >> 2;      // 0..1
    const int wn   = wid & 3;       // 0..3
    const int n0 = blockIdx.x * 128;
    const int m0 = blockIdx.y * 64;

    uint32_t sAh = smem_u32(dyn);
    uint32_t sAl = sAh + HW_A;
    uint32_t sB  = sAl + HW_A;
    float acc[2][4][4] = {};

    const int a_row  = wm * 32 + (lane & 15);
    const int a_colg = (lane >> 4) * 8;
    const int b_sub  = ((lane >> 4) & 1) * 8 + (lane & 7);
    const int b_colg = ((lane >> 3) & 1) * 8;

    for (int c = 0; c < 2; c++) {
        int kc = c * 64;
        const __half* Ah = g_hh16 + (size_t)m0 * HD + kc;
        const __half* Al = g_hl16 + (size_t)m0 * HD + kc;
        const __half* Bp = g_W1hh + (size_t)n0 * HD + kc;
        #pragma unroll
        for (int u = 0; u < 2; u++) {
            int idx = tid + u * 256;
            int row = idx >> 3, seg = idx & 7;
            uint32_t off = (uint32_t)(row * HG_LDA + seg * 8) * 2;
            cp_async16(sAh + off, Ah + (size_t)row * HD + seg * 8);
            cp_async16(sAl + off, Al + (size_t)row * HD + seg * 8);
        }
        #pragma unroll
        for (int u = 0; u < 4; u++) {
            int idx = tid + u * 256;
            int row = idx >> 3, seg = idx & 7;
            cp_async16(sB + (uint32_t)(row * HG_LDA + seg * 8) * 2,
                       Bp + (size_t)row * HD + seg * 8);
        }
        CP_COMMIT();
        CP_WAIT0();
        __syncthreads();

        #pragma unroll
        for (int ks = 0; ks < 4; ks++) {
            uint32_t bfr[2][4];
            #pragma unroll
            for (int nf2 = 0; nf2 < 2; nf2++)
                ldmatrix_x4(bfr[nf2], sB + (uint32_t)((wn*32 + nf2*16 + b_sub) * HG_LDA + ks*16 + b_colg) * 2);
            uint32_t ah[2][4], al[2][4];
            #pragma unroll
            for (int mf = 0; mf < 2; mf++) {
                uint32_t ro = (uint32_t)((a_row + mf*16) * HG_LDA + ks*16 + a_colg) * 2;
                ldmatrix_x4(ah[mf], sAh + ro);
                ldmatrix_x4(al[mf], sAl + ro);
            }
            #pragma unroll
            for (int mf = 0; mf < 2; mf++)
                #pragma unroll
                for (int nf = 0; nf < 4; nf++) {
                    uint32_t b0 = bfr[nf>>1][(nf&1)*2], b1 = bfr[nf>>1][(nf&1)*2 + 1];
                    mma_f16(acc[mf][nf], ah[mf], b0, b1);
                    mma_f16(acc[mf][nf], al[mf], b0, b1);
                }
        }
        __syncthreads();
    }

    #pragma unroll
    for (int mf = 0; mf < 2; mf++) {
        int R  = m0 + wm*32 + mf*16 + (lane >> 2);
        int R8 = R + 8;
        #pragma unroll
        for (int nf = 0; nf < 4; nf++) {
            int n = n0 + wn*32 + nf*8 + (lane & 3)*2;
            g_hW1h[(size_t)R  * PRE + n]     = acc[mf][nf][0];
            g_hW1h[(size_t)R  * PRE + n + 1] = acc[mf][nf][1];
            g_hW1h[(size_t)R8 * PRE + n]     = acc[mf][nf][2];
            g_hW1h[(size_t)R8 * PRE + n + 1] = acc[mf][nf][3];
        }
    }
}

// ---------------- X1 HMMA (fp16: emb 2-limb x W1e): single-stage, K=64 ----------------
// CTA 256x128, 8 warps (4x2), warp 64x64.
#define X1_AH      (256 * HG_LDA * 2)   // 36864 per emb limb
#define X1_B       (128 * HG_LDA * 2)   // 18432
#define X1_DYN     (2 * X1_AH + X1_B)   // 92160

__global__ void __launch_bounds__(256, 1)
hgemm_x1(const float* __restrict__ bias, const float* __restrict__ aux) {
    extern __shared__ char dyn[];
    const int tid  = threadIdx.x;
    const int lane = tid & 31;
    const int wid  = tid >> 5;
    const int wm   = wid >> 1;      // 0..3
    const int wn   = wid & 1;       // 0..1
    const int n0 = blockIdx.x * 128;
    const int m0 = blockIdx.y * 256;

    uint32_t sbase = smem_u32(dyn);
    uint32_t sAh = sbase;
    uint32_t sAl = sAh + X1_AH;
    uint32_t sB  = sAl + X1_AH;
    float acc[4][8][4] = {};

    const int a_row  = wm * 64 + (lane & 15);
    const int a_colg = (lane >> 4) * 8;
    const int b_sub  = ((lane >> 4) & 1) * 8 + (lane & 7);
    const int b_colg = ((lane >> 3) & 1) * 8;

    {
        const __half* Ah = g_embh + (size_t)m0 * ED;
        const __half* Al = g_embl + (size_t)m0 * ED;
        const __half* Bp = g_W1eh + (size_t)n0 * ED;
        #pragma unroll
        for (int u = 0; u < 8; u++) {
            int idx = tid + u * 256;          // 0..2047
            int row = idx >> 3, seg = idx & 7;
            uint32_t off = (uint32_t)(row * HG_LDA + seg * 8) * 2;
            cp_async16(sAh + off, Ah + (size_t)row * ED + seg * 8);
            cp_async16(sAl + off, Al + (size_t)row * ED + seg * 8);
        }
        #pragma unroll
        for (int u = 0; u < 4; u++) {
            int idx = tid + u * 256;          // 0..1023
            int row = idx >> 3, seg = idx & 7;
            cp_async16(sB + (uint32_t)(row * HG_LDA + seg * 8) * 2,
                       Bp + (size_t)row * ED + seg * 8);
        }
        CP_COMMIT();
        CP_WAIT0();
        __syncthreads();
    }

    #pragma unroll
    for (int ks = 0; ks < 4; ks++) {
        uint32_t bfr[4][4];
        #pragma unroll
        for (int nf2 = 0; nf2 < 4; nf2++)
            ldmatrix_x4(bfr[nf2], sB + (uint32_t)((wn*64 + nf2*16 + b_sub) * HG_LDA + ks*16 + b_colg) * 2);
        {
            uint32_t afr[4][4];
            #pragma unroll
            for (int mf = 0; mf < 4; mf++)
                ldmatrix_x4(afr[mf], sAh + (uint32_t)((a_row + mf*16) * HG_LDA + ks*16 + a_colg) * 2);
            #pragma unroll
            for (int mf = 0; mf < 4; mf++)
                #pragma unroll
                for (int nf = 0; nf < 8; nf++)
                    mma_f16(acc[mf][nf], afr[mf], bfr[nf>>1][(nf&1)*2], bfr[nf>>1][(nf&1)*2 + 1]);
        }
        {
            uint32_t afr[4][4];
            #pragma unroll
            for (int mf = 0; mf < 4; mf++)
                ldmatrix_x4(afr[mf], sAl + (uint32_t)((a_row + mf*16) * HG_LDA + ks*16 + a_colg) * 2);
            #pragma unroll
            for (int mf = 0; mf < 4; mf++)
                #pragma unroll
                for (int nf = 0; nf < 8; nf++)
                    mma_f16(acc[mf][nf], afr[mf], bfr[nf>>1][(nf&1)*2], bfr[nf>>1][(nf&1)*2 + 1]);
        }
    }

    #pragma unroll
    for (int mf = 0; mf < 4; mf++) {
        int R  = m0 + wm*64 + mf*16 + (lane >> 2);
        int R8 = R + 8;
        const float* aux0 = aux + (size_t)((R  >> 10)*32 + (R  & 31)) * PRE;
        const float* aux8 = aux + (size_t)((R8 >> 10)*32 + (R8 & 31)) * PRE;
        #pragma unroll
        for (int nf = 0; nf < 8; nf++) {
            int n = n0 + wn*64 + nf*8 + (lane & 3)*2;
            float b0 = bias[n], b1v = bias[n + 1];
            float v0 = fmaxf(acc[mf][nf][0] + b0  + aux0[n],     0.0f);
            float v1 = fmaxf(acc[mf][nf][1] + b1v + aux0[n + 1], 0.0f);
            float v2 = fmaxf(acc[mf][nf][2] + b0  + aux8[n],     0.0f);
            float v3 = fmaxf(acc[mf][nf][3] + b1v + aux8[n + 1], 0.0f);
            __half2 h01, h23;
            h01.x = __float2half(v0); h01.y = __float2half(v1);
            h23.x = __float2half(v2); h23.y = __float2half(v3);
            *reinterpret_cast<__half2*>(&g_X1h[(size_t)R  * PRE + n]) = h01;
            *reinterpret_cast<__half2*>(&g_X1h[(size_t)R8 * PRE + n]) = h23;
        }
    }
}

// ---------------- fp16 GEMM2 (128x128 CTA, 8 warps 2x4, warp 64x32) ----------------
// pool-part of dcat = relu(max_j(X1 @ W2^T) + b2) written as fp16 to g_dch[:, HD:].
#define G2_A       (128 * HG_LDA * 2)    // 18432
#define G2_B       (128 * HG_LDA * 2)    // 18432
#define G2_STG     (G2_A + G2_B)         // 36864
#define G2_DYN     (2 * G2_STG)          // 73728

__global__ void __launch_bounds__(256, 1)
gemm2_f16(const float* __restrict__ b2) {
    extern __shared__ char dyn[];
    const int tid  = threadIdx.x;
    const int lane = tid & 31;
    const int wid  = tid >> 5;
    const int wm   = wid >> 2;      // 0..1 (64 rows each)
    const int wn   = wid & 3;       // 0..3 (32 cols each)
    const int n0 = blockIdx.x * 128;
    const int m0 = blockIdx.y * 128;

    uint32_t sbase = smem_u32(dyn);
    float acc[4][4][4] = {};

    const int a_row  = wm * 64 + (lane & 15);
    const int a_colg = (lane >> 4) * 8;
    const int b_sub  = ((lane >> 4) & 1) * 8 + (lane & 7);
    const int b_colg = ((lane >> 3) & 1) * 8;

    auto load_chunk = [&](int c, int s) {
        int kc = c * 64;
        const __half* Ap = g_X1h + (size_t)m0 * PRE + kc;
        const __half* Bp = g_W2h + (size_t)n0 * PRE + kc;
        uint32_t sA = sbase + s * G2_STG;
        uint32_t sB = sA + G2_A;
        #pragma unroll
        for (int u = 0; u < 4; u++) {
            int idx = tid + u * 256;          // 0..1023
            int row = idx >> 3, seg = idx & 7;
            uint32_t off = (uint32_t)(row * HG_LDA + seg * 8) * 2;
            cp_async16(sA + off, Ap + (size_t)row * PRE + seg * 8);
            cp_async16(sB + off, Bp + (size_t)row * PRE + seg * 8);
        }
    };

    load_chunk(0, 0);
    CP_COMMIT();

    for (int c = 0; c < 8; c++) {
        if (c + 1 < 8) { load_chunk(c + 1, (c + 1) & 1); CP_COMMIT(); CP_WAIT1(); }
        else CP_WAIT0();
        __syncthreads();

        uint32_t sA = sbase + (c & 1) * G2_STG;
        uint32_t sB = sA + G2_A;
        #pragma unroll
        for (int ks = 0; ks < 4; ks++) {
            uint32_t bfr[2][4];
            #pragma unroll
            for (int nf2 = 0; nf2 < 2; nf2++)
                ldmatrix_x4(bfr[nf2], sB + (uint32_t)((wn*32 + nf2*16 + b_sub) * HG_LDA + ks*16 + b_colg) * 2);
            uint32_t afr[4][4];
            #pragma unroll
            for (int mf = 0; mf < 4; mf++)
                ldmatrix_x4(afr[mf], sA + (uint32_t)((a_row + mf*16) * HG_LDA + ks*16 + a_colg) * 2);
            #pragma unroll
            for (int mf = 0; mf < 4; mf++)
                #pragma unroll
                for (int nf = 0; nf < 4; nf++)
                    mma_f16(acc[mf][nf], afr[mf], bfr[nf>>1][(nf&1)*2], bfr[nf>>1][(nf&1)*2 + 1]);
        }
        __syncthreads();
    }

    // Register pool epilogue: warp owns rows m0+wm*64..+63 = two 32-row groups.
    #pragma unroll
    for (int half = 0; half < 2; half++) {
        int pr = blockIdx.y * 4 + wm * 2 + half;    // pool row = m/32
        int mf0 = half * 2, mf1 = mf0 + 1;
        #pragma unroll
        for (int nf = 0; nf < 4; nf++) {
            float v0 = fmaxf(fmaxf(acc[mf0][nf][0], acc[mf0][nf][2]),
                             fmaxf(acc[mf1][nf][0], acc[mf1][nf][2]));
            float v1 = fmaxf(fmaxf(acc[mf0][nf][1], acc[mf0][nf][3]),
                             fmaxf(acc[mf1][nf][1], acc[mf1][nf][3]));
            #pragma unroll
            for (int d = 4; d < 32; d <<= 1) {
                v0 = fmaxf(v0, __shfl_xor_sync(0xffffffffu, v0, d));
                v1 = fmaxf(v1, __shfl_xor_sync(0xffffffffu, v1, d));
            }
            if ((lane >> 2) == 0) {
                int n = n0 + wn*32 + nf*8 + (lane & 3)*2;
                __half2 hv;
                hv.x = __float2half(fmaxf(v0 + b2[n],     0.0f));
                hv.y = __float2half(fmaxf(v1 + b2[n + 1], 0.0f));
                *reinterpret_cast<__half2*>(&g_dch[(size_t)pr * DHK + HD + n]) = hv;
            }
        }
    }
}

// ---------------- fp16 D1: D1 = relu(dcat @ Wm1^T + bm1) ----------------
#define D1_A    (64 * HG_LDA * 2)     // 9216
#define D1_B    (128 * HG_LDA * 2)    // 18432
#define D1_STG  (D1_A + D1_B)         // 27648
#define D1_DYN  (2 * D1_STG)          // 55296

__global__ void __launch_bounds__(256, 1)
hgemm_d1(const float* __restrict__ bias) {
    extern __shared__ char dyn[];
    const int tid  = threadIdx.x;
    const int lane = tid & 31;
    const int wid  = tid >> 5;
    const int wm   = wid >> 2;      // 0..1
    const int wn   = wid & 3;       // 0..3
    const int n0 = blockIdx.x * 128;
    const int m0 = blockIdx.y * 64;

    uint32_t sbase = smem_u32(dyn);
    float acc[2][4][4] = {};

    const int a_row  = wm * 32 + (lane & 15);
    const int a_colg = (lane >> 4) * 8;
    const int b_sub  = ((lane >> 4) & 1) * 8 + (lane & 7);
    const int b_colg = ((lane >> 3) & 1) * 8;

    auto load_chunk = [&](int c, int s) {
        int kc = c * 64;
        const __half* Ap = g_dch + (size_t)m0 * DHK + kc;
        const __half* Bp = g_Wm1h + (size_t)n0 * DHK + kc;
        uint32_t sA = sbase + s * D1_STG;
        uint32_t sB = sA + D1_A;
        #pragma unroll
        for (int u = 0; u < 2; u++) {
            int idx = tid + u * 256;
            int row = idx >> 3, seg = idx & 7;
            cp_async16(sA + (uint32_t)(row * HG_LDA + seg * 8) * 2,
                       Ap + (size_t)row * DHK + seg * 8);
        }
        #pragma unroll
        for (int u = 0; u < 4; u++) {
            int idx = tid + u * 256;
            int row = idx >> 3, seg = idx & 7;
            cp_async16(sB + (uint32_t)(row * HG_LDA + seg * 8) * 2,
                       Bp + (size_t)row * DHK + seg * 8);
        }
    };

    load_chunk(0, 0);
    CP_COMMIT();

    for (int c = 0; c < 18; c++) {
        if (c + 1 < 18) { load_chunk(c + 1, (c + 1) & 1); CP_COMMIT(); CP_WAIT1(); }
        else CP_WAIT0();
        __syncthreads();

        uint32_t sA = sbase + (c & 1) * D1_STG;
        uint32_t sB = sA + D1_A;
        #pragma unroll
        for (int ks = 0; ks < 4; ks++) {
            uint32_t bfr[2][4];
            #pragma unroll
            for (int nf2 = 0; nf2 < 2; nf2++)
                ldmatrix_x4(bfr[nf2], sB + (uint32_t)((wn*32 + nf2*16 + b_sub) * HG_LDA + ks*16 + b_colg) * 2);
            uint32_t afr[2][4];
            #pragma unroll
            for (int mf = 0; mf < 2; mf++)
                ldmatrix_x4(afr[mf], sA + (uint32_t)((a_row + mf*16) * HG_LDA + ks*16 + a_colg) * 2);
            #pragma unroll
            for (int mf = 0; mf < 2; mf++)
                #pragma unroll
                for (int nf = 0; nf < 4; nf++)
                    mma_f16(acc[mf][nf], afr[mf], bfr[nf>>1][(nf&1)*2], bfr[nf>>1][(nf&1)*2 + 1]);
        }
        __syncthreads();
    }

    #pragma unroll
    for (int mf = 0; mf < 2; mf++) {
        int R  = m0 + wm*32 + mf*16 + (lane >> 2);
        int R8 = R + 8;
        #pragma unroll
        for (int nf = 0; nf < 4; nf++) {
            int n = n0 + wn*32 + nf*8 + (lane & 3)*2;
            float b0 = bias[n], b1v = bias[n + 1];
            g_D1[(size_t)R  * MLPD + n]     = fmaxf(acc[mf][nf][0] + b0,  0.0f);
            g_D1[(size_t)R  * MLPD + n + 1] = fmaxf(acc[mf][nf][1] + b1v, 0.0f);
            g_D1[(size_t)R8 * MLPD + n]     = fmaxf(acc[mf][nf][2] + b0,  0.0f);
            g_D1[(size_t)R8 * MLPD + n + 1] = fmaxf(acc[mf][nf][3] + b1v, 0.0f);
        }
    }
}

// ---------------- launch ----------------
extern "C" void kernel_launch(void* const* d_in, const int* in_sizes, int n_in,
                              void* d_out, int out_size) {
    const float* last_pos      = (const float*)d_in[0];
    const float* last_pos_rel  = (const float*)d_in[1];
    const float* hh            = (const float*)d_in[2];
    const float* ch            = (const float*)d_in[3];
    const float* pred_traj_rel = (const float*)d_in[4];
    const float* W_ih = (const float*)d_in[6];
    const float* W_hh = (const float*)d_in[7];
    const float* b_ih = (const float*)d_in[8];
    const float* b_hh = (const float*)d_in[9];
    const float* Wse  = (const float*)d_in[10];
    const float* bse  = (const float*)d_in[11];
    const float* Wpos = (const float*)d_in[12];
    const float* bpos = (const float*)d_in[13];
    const float* Wp   = (const float*)d_in[14];
    const float* bp   = (const float*)d_in[15];
    const float* W1   = (const float*)d_in[16];
    const float* b1   = (const float*)d_in[17];
    const float* W2   = (const float*)d_in[18];
    const float* b2   = (const float*)d_in[19];
    const float* Wm1  = (const float*)d_in[20];
    const float* bm1  = (const float*)d_in[21];
    const float* Wm2  = (const float*)d_in[22];
    const float* bm2  = (const float*)d_in[23];

    float* out = (float*)d_out;

    float* p_hW1h  = nullptr; cudaGetSymbolAddress((void**)&p_hW1h,  g_hW1h);
    float* p_D1    = nullptr; cudaGetSymbolAddress((void**)&p_D1,    g_D1);

    cudaFuncSetAttribute(hgemm_gates, cudaFuncAttributeMaxDynamicSharedMemorySize, GT_DYN);
    cudaFuncSetAttribute(hgemm_hw1h,  cudaFuncAttributeMaxDynamicSharedMemorySize, HW_DYN);
    cudaFuncSetAttribute(hgemm_x1,    cudaFuncAttributeMaxDynamicSharedMemorySize, X1_DYN);
    cudaFuncSetAttribute(gemm2_f16,   cudaFuncAttributeMaxDynamicSharedMemorySize, G2_DYN);
    cudaFuncSetAttribute(hgemm_d1,    cudaFuncAttributeMaxDynamicSharedMemorySize, D1_DYN);

    init_kernel<<<(MLPD*DHK + 255)/256, 256>>>(hh, ch, last_pos,
                                               W_ih, W_hh, b_ih, b_hh, W1, W2, Wm1);
    decall_kernel<<<(SEQ_LEN*BATCH*ED + 255)/256, 256>>>(last_pos_rel, pred_traj_rel, Wse, bse);

    for (int t = 0; t < SEQ_LEN; t++) {
        const float* gt = pred_traj_rel + t * BATCH * 2;
        float* out_pred = out + t * BATCH * 2;

        // LSTM cell: HMMA gates (reads post-MLP h limbs) -> fused elementwise/pos/loss
        hgemm_gates<<<dim3(GATES/128, BATCH/64), 256, GT_DYN>>>(t);
        lstm_pos_kernel<<<BATCH, HD>>>(Wpos, bpos, gt, out_pred);

        // pool net (uses pre-MLP h limbs written by lstm_pos)
        emb_kernel<<<(ROWS_PN*ED + 255)/256, 256>>>(Wp, bp);
        hgemm_hw1h<<<dim3(PRE/128, BATCH/64), 256, HW_DYN>>>();
        hgemm_x1<<<dim3(PRE/128, ROWS_PN/256), 256, X1_DYN>>>(b1, p_hW1h);
        gemm2_f16<<<dim3(BOTTLE/128, ROWS_PN/128), 256, G2_DYN>>>(b2);

        // decoder MLP; D2 emits post-MLP h (fp32 + fp16 limbs) for next step's gates
        hgemm_d1<<<dim3(MLPD/128, BATCH/64), 256, D1_DYN>>>(bm1);
        d2_kernel<<<dim3(HD/64, BATCH/64), 256>>>(p_D1, Wm2, bm2);
    }

    finish_kernel<<<1, BATCH>>>(out, out_size);
}

// round 14
// speedup vs baseline: 3.4439x; 1.0256x over previous
#include <cuda_runtime.h>
#include <cuda_bf16.h>
#include <cuda_fp16.h>
#include <math.h>
#include <stdint.h>

// Problem dims
#define SEQ_LEN 12
#define BATCH   512
#define NG      16
#define GROUP   32
#define HD      128      // H
#define ED      64       // E
#define PRE     512
#define BOTTLE  1024
#define MLPD    1024
#define GATES   (4*HD)   // 512
#define KCAT    (ED+HD)  // 192
#define ROWS_PN (NG*GROUP*GROUP)  // 16384
#define DHK     (HD+BOTTLE)       // 1152

// ---------------- scratch (device globals; no allocation) ----------------
__device__ float g_h[BATCH*HD];
__device__ float g_c[BATCH*HD];
__device__ float g_pos[BATCH*2];
__device__ __align__(16) __half g_deh[SEQ_LEN*BATCH*ED];  // dec_in fp16 hi, all steps
__device__ __align__(16) __half g_del[SEQ_LEN*BATCH*ED];  // dec_in fp16 lo, all steps
__device__ __align__(16) __half g_Wch[GATES*KCAT];      // Wcat fp16 hi
__device__ __align__(16) __half g_Wcl[GATES*KCAT];      // Wcat fp16 lo
__device__ float g_bsum[GATES];
__device__ float g_gates[BATCH*GATES];
__device__ __align__(16) __half g_hh16[BATCH*HD];       // h fp16 hi limb (tracks current h)
__device__ __align__(16) __half g_hl16[BATCH*HD];       // h fp16 lo limb
__device__ __align__(16) __half g_W1hh[PRE*HD];         // W1 h-part fp16
__device__ __align__(16) __half g_embh[ROWS_PN*ED];     // emb fp16 hi limb
__device__ __align__(16) __half g_embl[ROWS_PN*ED];     // emb fp16 lo limb
__device__ __align__(16) __half g_W1eh[PRE*ED];         // W1 emb-part fp16
__device__ float g_hW1h[BATCH*PRE];
__device__ __align__(16) __half g_X1h[ROWS_PN*PRE];     // X1 fp16
__device__ __align__(16) __half g_W2h[BOTTLE*PRE];      // W2 fp16
__device__ __align__(16) __half g_dch[BATCH*DHK];       // dcat fp16 = [h | pool]
__device__ __align__(16) __half g_Wm1h[MLPD*DHK];       // Wm1 fp16
__device__ float g_D1[BATCH*MLPD];
__device__ float g_sqacc[BATCH];

__device__ __forceinline__ float sigmoidf(float x) { return 1.0f / (1.0f + expf(-x)); }

// ---------------- PTX helpers (base-arch only: sm_80+ features) ----------------
__device__ __forceinline__ uint32_t smem_u32(const void* p) {
    uint32_t a;
    asm("{ .reg .u64 t; cvta.to.shared.u64 t, %1; cvt.u32.u64 %0, t; }" : "=r"(a) : "l"(p));
    return a;
}
__device__ __forceinline__ void cp_async16(uint32_t s, const void* g) {
    asm volatile("cp.async.cg.shared.global [%0], [%1], 16;" :: "r"(s), "l"(g));
}
#define CP_COMMIT() asm volatile("cp.async.commit_group;" ::: "memory")
#define CP_WAIT1()  asm volatile("cp.async.wait_group 1;" ::: "memory")
#define CP_WAIT0()  asm volatile("cp.async.wait_group 0;" ::: "memory")

__device__ __forceinline__ void ldmatrix_x4(uint32_t* r, uint32_t addr) {
    asm volatile("ldmatrix.sync.aligned.m8n8.x4.shared.b16 {%0,%1,%2,%3}, [%4];"
                 : "=r"(r[0]), "=r"(r[1]), "=r"(r[2]), "=r"(r[3]) : "r"(addr));
}
__device__ __forceinline__ void mma_f16(float* c, const uint32_t* a, uint32_t b0, uint32_t b1) {
    asm volatile("mma.sync.aligned.m16n8k16.row.col.f32.f16.f16.f32 "
                 "{%0,%1,%2,%3}, {%4,%5,%6,%7}, {%8,%9}, {%0,%1,%2,%3};"
                 : "+f"(c[0]), "+f"(c[1]), "+f"(c[2]), "+f"(c[3])
                 : "r"(a[0]), "r"(a[1]), "r"(a[2]), "r"(a[3]), "r"(b0), "r"(b1));
}

// ---------------- init ----------------
__global__ void init_kernel(const float* __restrict__ hh, const float* __restrict__ ch,
                            const float* __restrict__ last_pos,
                            const float* __restrict__ Wih, const float* __restrict__ Whh,
                            const float* __restrict__ bih, const float* __restrict__ bhh,
                            const float* __restrict__ W1, const float* __restrict__ W2,
                            const float* __restrict__ Wm1) {
    int idx = blockIdx.x * blockDim.x + threadIdx.x;
    if (idx < BATCH*HD) {
        float h = hh[idx];
        g_h[idx] = h; g_c[idx] = ch[idx];
        __half hv = __float2half(h);
        g_hh16[idx] = hv;
        g_hl16[idx] = __float2half(h - __half2float(hv));
    }
    if (idx < BATCH*2)  g_pos[idx] = last_pos[idx];
    if (idx < BATCH)    g_sqacc[idx] = 0.0f;
    if (idx < GATES) g_bsum[idx] = bih[idx] + bhh[idx];
    if (idx < GATES*KCAT) {
        int n = idx / KCAT, k = idx % KCAT;
        float w = (k < ED) ? Wih[n*ED + k] : Whh[n*HD + (k - ED)];
        __half hi = __float2half(w);
        g_Wch[idx] = hi;
        g_Wcl[idx] = __float2half(w - __half2float(hi));
    }
    if (idx < PRE*ED) {
        int n = idx >> 6, k = idx & 63;
        g_W1eh[idx] = __float2half(W1[n*KCAT + k]);
    }
    if (idx < PRE*HD) {
        int n = idx >> 7, k = idx & 127;
        g_W1hh[idx] = __float2half(W1[n*KCAT + ED + k]);
    }
    if (idx < BOTTLE*PRE) g_W2h[idx] = __float2half(W2[idx]);
    if (idx < MLPD*DHK)   g_Wm1h[idx] = __float2half(Wm1[idx]);
}

// Precompute dec_in spatial embeddings for ALL steps (teacher forcing is static).
__global__ void decall_kernel(const float* __restrict__ last_pos_rel,
                              const float* __restrict__ pred_traj_rel,
                              const float* __restrict__ Wse, const float* __restrict__ bse) {
    int idx = blockIdx.x * blockDim.x + threadIdx.x;
    if (idx >= SEQ_LEN*BATCH*ED) return;
    int t = idx / (BATCH*ED);
    int r = idx % (BATCH*ED);
    int b = r / ED, e = r % ED;
    const float* rel = (t == 0) ? (last_pos_rel + b*2)
                                : (pred_traj_rel + ((size_t)(t-1)*BATCH + b)*2);
    float v = rel[0] * Wse[e*2] + rel[1] * Wse[e*2+1] + bse[e];
    __half hi = __float2half(v);
    g_deh[idx] = hi;
    g_del[idx] = __float2half(v - __half2float(hi));
}

// ---------------- fused LSTM elementwise + rel_pos + pos + loss accum ----------------
__global__ void lstm_pos_kernel(const float* __restrict__ Wpos, const float* __restrict__ bpos,
                                const float* __restrict__ gt, float* __restrict__ out_pred) {
    int b = blockIdx.x, j = threadIdx.x;
    const float* gr = g_gates + b*GATES;
    float ig = gr[j], fg = gr[HD + j], gg = gr[2*HD + j], og = gr[3*HD + j];
    float c = sigmoidf(fg) * g_c[b*HD + j] + sigmoidf(ig) * tanhf(gg);
    float h = sigmoidf(og) * tanhf(c);
    g_c[b*HD + j] = c;
    __half hhv = __float2half(h);
    g_hh16[b*HD + j] = hhv;
    g_hl16[b*HD + j] = __float2half(h - __half2float(hhv));
    g_dch[(size_t)b*DHK + j] = hhv;

    __shared__ float sx[HD], sy[HD];
    sx[j] = h * Wpos[j];
    sy[j] = h * Wpos[HD + j];
    __syncthreads();
    for (int s = HD/2; s > 0; s >>= 1) {
        if (j < s) { sx[j] += sx[j + s]; sy[j] += sy[j + s]; }
        __syncthreads();
    }
    if (j == 0) {
        float rx = sx[0] + bpos[0], ry = sy[0] + bpos[1];
        out_pred[b*2]   = rx;
        out_pred[b*2+1] = ry;
        g_pos[b*2]   += rx;
        g_pos[b*2+1] += ry;
        float dx = rx - gt[b*2], dy = ry - gt[b*2+1];
        g_sqacc[b] += dx*dx + dy*dy;
    }
}

// ---------------- pairwise rel-pos embedding -> fp16 hi/lo ----------------
__global__ void emb_kernel(const float* __restrict__ Wp, const float* __restrict__ bp) {
    int idx = blockIdx.x * blockDim.x + threadIdx.x;
    if (idx >= ROWS_PN*ED) return;
    int r = idx >> 6, e = idx & 63;
    int g = r >> 10, i = (r >> 5) & 31, j = r & 31;
    int bi = g*GROUP + i, bj = g*GROUP + j;
    float rx = g_pos[bj*2]   - g_pos[bi*2];
    float ry = g_pos[bj*2+1] - g_pos[bi*2+1];
    float v = rx * Wp[e*2] + ry * Wp[e*2+1] + bp[e];
    __half hi = __float2half(v);
    g_embh[idx] = hi;
    g_embl[idx] = __float2half(v - __half2float(hi));
}

__global__ void finish_kernel(float* __restrict__ out, int out_size) {
    __shared__ float sd[BATCH];
    int t = threadIdx.x;
    sd[t] = g_sqacc[t];
    __syncthreads();
    for (int s = BATCH/2; s > 0; s >>= 1) {
        if (t < s) sd[t] += sd[t + s];
        __syncthreads();
    }
    if (t == 0 && out_size > SEQ_LEN*BATCH*2)
        out[SEQ_LEN*BATCH*2] = sd[0] / (float)(BATCH*2);
}

// ---------------- D2: h = relu(D1 @ Wm2^T + bm2); ALSO emits post-MLP h fp16 limbs ----------------
__global__ void d2_kernel(const float* __restrict__ A, const float* __restrict__ W,
                          const float* __restrict__ bias) {
    __shared__ float As[64][17];
    __shared__ float Ws[64][17];
    int tid = threadIdx.x;
    int m0 = blockIdx.y * 64, n0 = blockIdx.x * 64;
    int ty = tid >> 4, tx = tid & 15;
    float acc[4][4] = {};

    for (int k0 = 0; k0 < MLPD; k0 += 16) {
        #pragma unroll
        for (int l = tid; l < 64*16; l += 256) {
            int r = l >> 4, c = l & 15;
            As[r][c] = A[(m0 + r) * MLPD + k0 + c];
            Ws[r][c] = W[(n0 + r) * MLPD + k0 + c];
        }
        __syncthreads();
        #pragma unroll
        for (int kk = 0; kk < 16; kk++) {
            float a[4], w[4];
            #pragma unroll
            for (int i = 0; i < 4; i++) { a[i] = As[ty*4 + i][kk]; w[i] = Ws[tx*4 + i][kk]; }
            #pragma unroll
            for (int i = 0; i < 4; i++)
                #pragma unroll
                for (int j = 0; j < 4; j++) acc[i][j] += a[i] * w[j];
        }
        __syncthreads();
    }

    #pragma unroll
    for (int i = 0; i < 4; i++) {
        int m = m0 + ty*4 + i;
        #pragma unroll
        for (int j = 0; j < 4; j++) {
            int n = n0 + tx*4 + j;
            float v = fmaxf(acc[i][j] + bias[n], 0.0f);
            g_h[m*HD + n] = v;
            __half hv = __float2half(v);
            g_hh16[m*HD + n] = hv;
            g_hl16[m*HD + n] = __float2half(v - __half2float(hv));
        }
    }
}

#define HG_LDA 72

// ---------------- HMMA gates: gates = [dec_in|h] @ Wcat^T + bsum (3-term fp16) ----------------
#define GT_A    (64 * HG_LDA * 2)
#define GT_B    (128 * HG_LDA * 2)
#define GT_DYN  (2*GT_A + 2*GT_B)      // 55296

__global__ void __launch_bounds__(256, 1)
hgemm_gates(int t) {
    extern __shared__ char dyn[];
    const int tid  = threadIdx.x;
    const int lane = tid & 31;
    const int wid  = tid >> 5;
    const int wm   = wid >> 2;
    const int wn   = wid & 3;
    const int n0 = blockIdx.x * 128;
    const int m0 = blockIdx.y * 64;

    uint32_t sAh = smem_u32(dyn);
    uint32_t sAl = sAh + GT_A;
    uint32_t sBh = sAl + GT_A;
    uint32_t sBl = sBh + GT_B;
    float acc[2][4][4] = {};

    const int a_row  = wm * 32 + (lane & 15);
    const int a_colg = (lane >> 4) * 8;
    const int b_sub  = ((lane >> 4) & 1) * 8 + (lane & 7);
    const int b_colg = ((lane >> 3) & 1) * 8;

    for (int c = 0; c < 3; c++) {
        int kc = c * 64;
        const __half *Ah, *Al;
        int lda;
        if (c == 0) {
            Ah = g_deh + (size_t)t*BATCH*ED + (size_t)m0 * ED;
            Al = g_del + (size_t)t*BATCH*ED + (size_t)m0 * ED;
            lda = ED;
        } else {
            Ah = g_hh16 + (size_t)m0 * HD + (c - 1) * 64;
            Al = g_hl16 + (size_t)m0 * HD + (c - 1) * 64;
            lda = HD;
        }
        const __half* Bh = g_Wch + (size_t)n0 * KCAT + kc;
        const __half* Bl = g_Wcl + (size_t)n0 * KCAT + kc;
        #pragma unroll
        for (int u = 0; u < 2; u++) {
            int idx = tid + u * 256;
            int row = idx >> 3, seg = idx & 7;
            uint32_t off = (uint32_t)(row * HG_LDA + seg * 8) * 2;
            cp_async16(sAh + off, Ah + (size_t)row * lda + seg * 8);
            cp_async16(sAl + off, Al + (size_t)row * lda + seg * 8);
        }
        #pragma unroll
        for (int u = 0; u < 4; u++) {
            int idx = tid + u * 256;
            int row = idx >> 3, seg = idx & 7;
            uint32_t off = (uint32_t)(row * HG_LDA + seg * 8) * 2;
            cp_async16(sBh + off, Bh + (size_t)row * KCAT + seg * 8);
            cp_async16(sBl + off, Bl + (size_t)row * KCAT + seg * 8);
        }
        CP_COMMIT();
        CP_WAIT0();
        __syncthreads();

        #pragma unroll
        for (int ks = 0; ks < 4; ks++) {
            uint32_t bh[2][4], bl[2][4];
            #pragma unroll
            for (int nf2 = 0; nf2 < 2; nf2++) {
                uint32_t ro = (uint32_t)((wn*32 + nf2*16 + b_sub) * HG_LDA + ks*16 + b_colg) * 2;
                ldmatrix_x4(bh[nf2], sBh + ro);
                ldmatrix_x4(bl[nf2], sBl + ro);
            }
            uint32_t ah[2][4], al[2][4];
            #pragma unroll
            for (int mf = 0; mf < 2; mf++) {
                uint32_t ro = (uint32_t)((a_row + mf*16) * HG_LDA + ks*16 + a_colg) * 2;
                ldmatrix_x4(ah[mf], sAh + ro);
                ldmatrix_x4(al[mf], sAl + ro);
            }
            #pragma unroll
            for (int mf = 0; mf < 2; mf++)
                #pragma unroll
                for (int nf = 0; nf < 4; nf++) {
                    uint32_t bh0 = bh[nf>>1][(nf&1)*2], bh1 = bh[nf>>1][(nf&1)*2 + 1];
                    uint32_t bl0 = bl[nf>>1][(nf&1)*2], bl1 = bl[nf>>1][(nf&1)*2 + 1];
                    mma_f16(acc[mf][nf], ah[mf], bh0, bh1);
                    mma_f16(acc[mf][nf], ah[mf], bl0, bl1);
                    mma_f16(acc[mf][nf], al[mf], bh0, bh1);
                }
        }
        __syncthreads();
    }

    #pragma unroll
    for (int mf = 0; mf < 2; mf++) {
        int R  = m0 + wm*32 + mf*16 + (lane >> 2);
        int R8 = R + 8;
        #pragma unroll
        for (int nf = 0; nf < 4; nf++) {
            int n = n0 + wn*32 + nf*8 + (lane & 3)*2;
            float b0 = g_bsum[n], b1v = g_bsum[n + 1];
            g_gates[(size_t)R  * GATES + n]     = acc[mf][nf][0] + b0;
            g_gates[(size_t)R  * GATES + n + 1] = acc[mf][nf][1] + b1v;
            g_gates[(size_t)R8 * GATES + n]     = acc[mf][nf][2] + b0;
            g_gates[(size_t)R8 * GATES + n + 1] = acc[mf][nf][3] + b1v;
        }
    }
}

// ---------------- HMMA hW1h: hW1h = h @ W1h^T (h 2-limb x W1h fp16) ----------------
#define HW_A    (64 * HG_LDA * 2)
#define HW_B    (128 * HG_LDA * 2)
#define HW_DYN  (2*HW_A + HW_B)

__global__ void __launch_bounds__(256, 1)
hgemm_hw1h() {
    extern __shared__ char dyn[];
    const int tid  = threadIdx.x;
    const int lane = tid & 31;
    const int wid  = tid >> 5;
    const int wm   = wid >> 2;
    const int wn   = wid & 3;
    const int n0 = blockIdx.x * 128;
    const int m0 = blockIdx.y * 64;

    uint32_t sAh = smem_u32(dyn);
    uint32_t sAl = sAh + HW_A;
    uint32_t sB  = sAl + HW_A;
    float acc[2][4][4] = {};

    const int a_row  = wm * 32 + (lane & 15);
    const int a_colg = (lane >> 4) * 8;
    const int b_sub  = ((lane >> 4) & 1) * 8 + (lane & 7);
    const int b_colg = ((lane >> 3) & 1) * 8;

    for (int c = 0; c < 2; c++) {
        int kc = c * 64;
        const __half* Ah = g_hh16 + (size_t)m0 * HD + kc;
        const __half* Al = g_hl16 + (size_t)m0 * HD + kc;
        const __half* Bp = g_W1hh + (size_t)n0 * HD + kc;
        #pragma unroll
        for (int u = 0; u < 2; u++) {
            int idx = tid + u * 256;
            int row = idx >> 3, seg = idx & 7;
            uint32_t off = (uint32_t)(row * HG_LDA + seg * 8) * 2;
            cp_async16(sAh + off, Ah + (size_t)row * HD + seg * 8);
            cp_async16(sAl + off, Al + (size_t)row * HD + seg * 8);
        }
        #pragma unroll
        for (int u = 0; u < 4; u++) {
            int idx = tid + u * 256;
            int row = idx >> 3, seg = idx & 7;
            cp_async16(sB + (uint32_t)(row * HG_LDA + seg * 8) * 2,
                       Bp + (size_t)row * HD + seg * 8);
        }
        CP_COMMIT();
        CP_WAIT0();
        __syncthreads();

        #pragma unroll
        for (int ks = 0; ks < 4; ks++) {
            uint32_t bfr[2][4];
            #pragma unroll
            for (int nf2 = 0; nf2 < 2; nf2++)
                ldmatrix_x4(bfr[nf2], sB + (uint32_t)((wn*32 + nf2*16 + b_sub) * HG_LDA + ks*16 + b_colg) * 2);
            uint32_t ah[2][4], al[2][4];
            #pragma unroll
            for (int mf = 0; mf < 2; mf++) {
                uint32_t ro = (uint32_t)((a_row + mf*16) * HG_LDA + ks*16 + a_colg) * 2;
                ldmatrix_x4(ah[mf], sAh + ro);
                ldmatrix_x4(al[mf], sAl + ro);
            }
            #pragma unroll
            for (int mf = 0; mf < 2; mf++)
                #pragma unroll
                for (int nf = 0; nf < 4; nf++) {
                    uint32_t b0 = bfr[nf>>1][(nf&1)*2], b1 = bfr[nf>>1][(nf&1)*2 + 1];
                    mma_f16(acc[mf][nf], ah[mf], b0, b1);
                    mma_f16(acc[mf][nf], al[mf], b0, b1);
                }
        }
        __syncthreads();
    }

    #pragma unroll
    for (int mf = 0; mf < 2; mf++) {
        int R  = m0 + wm*32 + mf*16 + (lane >> 2);
        int R8 = R + 8;
        #pragma unroll
        for (int nf = 0; nf < 4; nf++) {
            int n = n0 + wn*32 + nf*8 + (lane & 3)*2;
            g_hW1h[(size_t)R  * PRE + n]     = acc[mf][nf][0];
            g_hW1h[(size_t)R  * PRE + n + 1] = acc[mf][nf][1];
            g_hW1h[(size_t)R8 * PRE + n]     = acc[mf][nf][2];
            g_hW1h[(size_t)R8 * PRE + n + 1] = acc[mf][nf][3];
        }
    }
}

// ---------------- X1 HMMA (fp16: emb 2-limb x W1e): single-stage, K=64 ----------------
#define X1_AH      (256 * HG_LDA * 2)
#define X1_B       (128 * HG_LDA * 2)
#define X1_DYN     (2 * X1_AH + X1_B)   // 92160

__global__ void __launch_bounds__(256, 1)
hgemm_x1(const float* __restrict__ bias, const float* __restrict__ aux) {
    extern __shared__ char dyn[];
    const int tid  = threadIdx.x;
    const int lane = tid & 31;
    const int wid  = tid >> 5;
    const int wm   = wid >> 1;
    const int wn   = wid & 1;
    const int n0 = blockIdx.x * 128;
    const int m0 = blockIdx.y * 256;

    uint32_t sbase = smem_u32(dyn);
    uint32_t sAh = sbase;
    uint32_t sAl = sAh + X1_AH;
    uint32_t sB  = sAl + X1_AH;
    float acc[4][8][4] = {};

    const int a_row  = wm * 64 + (lane & 15);
    const int a_colg = (lane >> 4) * 8;
    const int b_sub  = ((lane >> 4) & 1) * 8 + (lane & 7);
    const int b_colg = ((lane >> 3) & 1) * 8;

    {
        const __half* Ah = g_embh + (size_t)m0 * ED;
        const __half* Al = g_embl + (size_t)m0 * ED;
        const __half* Bp = g_W1eh + (size_t)n0 * ED;
        #pragma unroll
        for (int u = 0; u < 8; u++) {
            int idx = tid + u * 256;
            int row = idx >> 3, seg = idx & 7;
            uint32_t off = (uint32_t)(row * HG_LDA + seg * 8) * 2;
            cp_async16(sAh + off, Ah + (size_t)row * ED + seg * 8);
            cp_async16(sAl + off, Al + (size_t)row * ED + seg * 8);
        }
        #pragma unroll
        for (int u = 0; u < 4; u++) {
            int idx = tid + u * 256;
            int row = idx >> 3, seg = idx & 7;
            cp_async16(sB + (uint32_t)(row * HG_LDA + seg * 8) * 2,
                       Bp + (size_t)row * ED + seg * 8);
        }
        CP_COMMIT();
        CP_WAIT0();
        __syncthreads();
    }

    #pragma unroll
    for (int ks = 0; ks < 4; ks++) {
        uint32_t bfr[4][4];
        #pragma unroll
        for (int nf2 = 0; nf2 < 4; nf2++)
            ldmatrix_x4(bfr[nf2], sB + (uint32_t)((wn*64 + nf2*16 + b_sub) * HG_LDA + ks*16 + b_colg) * 2);
        {
            uint32_t afr[4][4];
            #pragma unroll
            for (int mf = 0; mf < 4; mf++)
                ldmatrix_x4(afr[mf], sAh + (uint32_t)((a_row + mf*16) * HG_LDA + ks*16 + a_colg) * 2);
            #pragma unroll
            for (int mf = 0; mf < 4; mf++)
                #pragma unroll
                for (int nf = 0; nf < 8; nf++)
                    mma_f16(acc[mf][nf], afr[mf], bfr[nf>>1][(nf&1)*2], bfr[nf>>1][(nf&1)*2 + 1]);
        }
        {
            uint32_t afr[4][4];
            #pragma unroll
            for (int mf = 0; mf < 4; mf++)
                ldmatrix_x4(afr[mf], sAl + (uint32_t)((a_row + mf*16) * HG_LDA + ks*16 + a_colg) * 2);
            #pragma unroll
            for (int mf = 0; mf < 4; mf++)
                #pragma unroll
                for (int nf = 0; nf < 8; nf++)
                    mma_f16(acc[mf][nf], afr[mf], bfr[nf>>1][(nf&1)*2], bfr[nf>>1][(nf&1)*2 + 1]);
        }
    }

    #pragma unroll
    for (int mf = 0; mf < 4; mf++) {
        int R  = m0 + wm*64 + mf*16 + (lane >> 2);
        int R8 = R + 8;
        const float* aux0 = aux + (size_t)((R  >> 10)*32 + (R  & 31)) * PRE;
        const float* aux8 = aux + (size_t)((R8 >> 10)*32 + (R8 & 31)) * PRE;
        #pragma unroll
        for (int nf = 0; nf < 8; nf++) {
            int n = n0 + wn*64 + nf*8 + (lane & 3)*2;
            float b0 = bias[n], b1v = bias[n + 1];
            float v0 = fmaxf(acc[mf][nf][0] + b0  + aux0[n],     0.0f);
            float v1 = fmaxf(acc[mf][nf][1] + b1v + aux0[n + 1], 0.0f);
            float v2 = fmaxf(acc[mf][nf][2] + b0  + aux8[n],     0.0f);
            float v3 = fmaxf(acc[mf][nf][3] + b1v + aux8[n + 1], 0.0f);
            __half2 h01, h23;
            h01.x = __float2half(v0); h01.y = __float2half(v1);
            h23.x = __float2half(v2); h23.y = __float2half(v3);
            *reinterpret_cast<__half2*>(&g_X1h[(size_t)R  * PRE + n]) = h01;
            *reinterpret_cast<__half2*>(&g_X1h[(size_t)R8 * PRE + n]) = h23;
        }
    }
}

// ---------------- fp16 GEMM2 (256x128 CTA, 8 warps 4x2, warp 64x64) ----------------
// pool-part of dcat = relu(max_j(X1 @ W2^T) + b2) written as fp16 to g_dch[:, HD:].
#define G2_A       (256 * HG_LDA * 2)    // 36864
#define G2_B       (128 * HG_LDA * 2)    // 18432
#define G2_STG     (G2_A + G2_B)         // 55296
#define G2_DYN     (2 * G2_STG)          // 110592

__global__ void __launch_bounds__(256, 1)
gemm2_f16(const float* __restrict__ b2) {
    extern __shared__ char dyn[];
    const int tid  = threadIdx.x;
    const int lane = tid & 31;
    const int wid  = tid >> 5;
    const int wm   = wid >> 1;      // 0..3
    const int wn   = wid & 1;       // 0..1
    const int n0 = blockIdx.x * 128;
    const int m0 = blockIdx.y * 256;

    uint32_t sbase = smem_u32(dyn);
    float acc[4][8][4] = {};

    const int a_row  = wm * 64 + (lane & 15);
    const int a_colg = (lane >> 4) * 8;
    const int b_sub  = ((lane >> 4) & 1) * 8 + (lane & 7);
    const int b_colg = ((lane >> 3) & 1) * 8;

    auto load_chunk = [&](int c, int s) {
        int kc = c * 64;
        const __half* Ap = g_X1h + (size_t)m0 * PRE + kc;
        const __half* Bp = g_W2h + (size_t)n0 * PRE + kc;
        uint32_t sA = sbase + s * G2_STG;
        uint32_t sB = sA + G2_A;
        #pragma unroll
        for (int u = 0; u < 8; u++) {
            int idx = tid + u * 256;
            int row = idx >> 3, seg = idx & 7;
            cp_async16(sA + (uint32_t)(row * HG_LDA + seg * 8) * 2,
                       Ap + (size_t)row * PRE + seg * 8);
        }
        #pragma unroll
        for (int u = 0; u < 4; u++) {
            int idx = tid + u * 256;
            int row = idx >> 3, seg = idx & 7;
            cp_async16(sB + (uint32_t)(row * HG_LDA + seg * 8) * 2,
                       Bp + (size_t)row * PRE + seg * 8);
        }
    };

    load_chunk(0, 0);
    CP_COMMIT();

    for (int c = 0; c < 8; c++) {
        if (c + 1 < 8) { load_chunk(c + 1, (c + 1) & 1); CP_COMMIT(); CP_WAIT1(); }
        else CP_WAIT0();
        __syncthreads();

        uint32_t sA = sbase + (c & 1) * G2_STG;
        uint32_t sB = sA + G2_A;
        #pragma unroll
        for (int ks = 0; ks < 4; ks++) {
            uint32_t bfr[4][4];
            #pragma unroll
            for (int nf2 = 0; nf2 < 4; nf2++)
                ldmatrix_x4(bfr[nf2], sB + (uint32_t)((wn*64 + nf2*16 + b_sub) * HG_LDA + ks*16 + b_colg) * 2);
            uint32_t afr[4][4];
            #pragma unroll
            for (int mf = 0; mf < 4; mf++)
                ldmatrix_x4(afr[mf], sA + (uint32_t)((a_row + mf*16) * HG_LDA + ks*16 + a_colg) * 2);
            #pragma unroll
            for (int mf = 0; mf < 4; mf++)
                #pragma unroll
                for (int nf = 0; nf < 8; nf++)
                    mma_f16(acc[mf][nf], afr[mf], bfr[nf>>1][(nf&1)*2], bfr[nf>>1][(nf&1)*2 + 1]);
        }
        __syncthreads();
    }

    // Register pool epilogue: warp owns rows m0+wm*64..+63 = two 32-row groups.
    #pragma unroll
    for (int half = 0; half < 2; half++) {
        int pr = blockIdx.y * 8 + wm * 2 + half;    // pool row = m/32
        #pragma unroll
        for (int nf = 0; nf < 8; nf++) {
            float v0 = fmaxf(fmaxf(acc[2*half][nf][0], acc[2*half][nf][2]),
                             fmaxf(acc[2*half+1][nf][0], acc[2*half+1][nf][2]));
            float v1 = fmaxf(fmaxf(acc[2*half][nf][1], acc[2*half][nf][3]),
                             fmaxf(acc[2*half+1][nf][1], acc[2*half+1][nf][3]));
            #pragma unroll
            for (int d = 4; d < 32; d <<= 1) {
                v0 = fmaxf(v0, __shfl_xor_sync(0xffffffffu, v0, d));
                v1 = fmaxf(v1, __shfl_xor_sync(0xffffffffu, v1, d));
            }
            if ((lane >> 2) == 0) {
                int n = n0 + wn*64 + nf*8 + (lane & 3)*2;
                __half2 hv;
                hv.x = __float2half(fmaxf(v0 + b2[n],     0.0f));
                hv.y = __float2half(fmaxf(v1 + b2[n + 1], 0.0f));
                *reinterpret_cast<__half2*>(&g_dch[(size_t)pr * DHK + HD + n]) = hv;
            }
        }
    }
}

// ---------------- fp16 D1: D1 = relu(dcat @ Wm1^T + bm1) ----------------
#define D1_A    (64 * HG_LDA * 2)
#define D1_B    (128 * HG_LDA * 2)
#define D1_STG  (D1_A + D1_B)
#define D1_DYN  (2 * D1_STG)

__global__ void __launch_bounds__(256, 1)
hgemm_d1(const float* __restrict__ bias) {
    extern __shared__ char dyn[];
    const int tid  = threadIdx.x;
    const int lane = tid & 31;
    const int wid  = tid >> 5;
    const int wm   = wid >> 2;
    const int wn   = wid & 3;
    const int n0 = blockIdx.x * 128;
    const int m0 = blockIdx.y * 64;

    uint32_t sbase = smem_u32(dyn);
    float acc[2][4][4] = {};

    const int a_row  = wm * 32 + (lane & 15);
    const int a_colg = (lane >> 4) * 8;
    const int b_sub  = ((lane >> 4) & 1) * 8 + (lane & 7);
    const int b_colg = ((lane >> 3) & 1) * 8;

    auto load_chunk = [&](int c, int s) {
        int kc = c * 64;
        const __half* Ap = g_dch + (size_t)m0 * DHK + kc;
        const __half* Bp = g_Wm1h + (size_t)n0 * DHK + kc;
        uint32_t sA = sbase + s * D1_STG;
        uint32_t sB = sA + D1_A;
        #pragma unroll
        for (int u = 0; u < 2; u++) {
            int idx = tid + u * 256;
            int row = idx >> 3, seg = idx & 7;
            cp_async16(sA + (uint32_t)(row * HG_LDA + seg * 8) * 2,
                       Ap + (size_t)row * DHK + seg * 8);
        }
        #pragma unroll
        for (int u = 0; u < 4; u++) {
            int idx = tid + u * 256;
            int row = idx >> 3, seg = idx & 7;
            cp_async16(sB + (uint32_t)(row * HG_LDA + seg * 8) * 2,
                       Bp + (size_t)row * DHK + seg * 8);
        }
    };

    load_chunk(0, 0);
    CP_COMMIT();

    for (int c = 0; c < 18; c++) {
        if (c + 1 < 18) { load_chunk(c + 1, (c + 1) & 1); CP_COMMIT(); CP_WAIT1(); }
        else CP_WAIT0();
        __syncthreads();

        uint32_t sA = sbase + (c & 1) * D1_STG;
        uint32_t sB = sA + D1_A;
        #pragma unroll
        for (int ks = 0; ks < 4; ks++) {
            uint32_t bfr[2][4];
            #pragma unroll
            for (int nf2 = 0; nf2 < 2; nf2++)
                ldmatrix_x4(bfr[nf2], sB + (uint32_t)((wn*32 + nf2*16 + b_sub) * HG_LDA + ks*16 + b_colg) * 2);
            uint32_t afr[2][4];
            #pragma unroll
            for (int mf = 0; mf < 2; mf++)
                ldmatrix_x4(afr[mf], sA + (uint32_t)((a_row + mf*16) * HG_LDA + ks*16 + a_colg) * 2);
            #pragma unroll
            for (int mf = 0; mf < 2; mf++)
                #pragma unroll
                for (int nf = 0; nf < 4; nf++)
                    mma_f16(acc[mf][nf], afr[mf], bfr[nf>>1][(nf&1)*2], bfr[nf>>1][(nf&1)*2 + 1]);
        }
        __syncthreads();
    }

    #pragma unroll
    for (int mf = 0; mf < 2; mf++) {
        int R  = m0 + wm*32 + mf*16 + (lane >> 2);
        int R8 = R + 8;
        #pragma unroll
        for (int nf = 0; nf < 4; nf++) {
            int n = n0 + wn*32 + nf*8 + (lane & 3)*2;
            float b0 = bias[n], b1v = bias[n + 1];
            g_D1[(size_t)R  * MLPD + n]     = fmaxf(acc[mf][nf][0] + b0,  0.0f);
            g_D1[(size_t)R  * MLPD + n + 1] = fmaxf(acc[mf][nf][1] + b1v, 0.0f);
            g_D1[(size_t)R8 * MLPD + n]     = fmaxf(acc[mf][nf][2] + b0,  0.0f);
            g_D1[(size_t)R8 * MLPD + n + 1] = fmaxf(acc[mf][nf][3] + b1v, 0.0f);
        }
    }
}

// ---------------- launch ----------------
extern "C" void kernel_launch(void* const* d_in, const int* in_sizes, int n_in,
                              void* d_out, int out_size) {
    const float* last_pos      = (const float*)d_in[0];
    const float* last_pos_rel  = (const float*)d_in[1];
    const float* hh            = (const float*)d_in[2];
    const float* ch            = (const float*)d_in[3];
    const float* pred_traj_rel = (const float*)d_in[4];
    const float* W_ih = (const float*)d_in[6];
    const float* W_hh = (const float*)d_in[7];
    const float* b_ih = (const float*)d_in[8];
    const float* b_hh = (const float*)d_in[9];
    const float* Wse  = (const float*)d_in[10];
    const float* bse  = (const float*)d_in[11];
    const float* Wpos = (const float*)d_in[12];
    const float* bpos = (const float*)d_in[13];
    const float* Wp   = (const float*)d_in[14];
    const float* bp   = (const float*)d_in[15];
    const float* W1   = (const float*)d_in[16];
    const float* b1   = (const float*)d_in[17];
    const float* W2   = (const float*)d_in[18];
    const float* b2   = (const float*)d_in[19];
    const float* Wm1  = (const float*)d_in[20];
    const float* bm1  = (const float*)d_in[21];
    const float* Wm2  = (const float*)d_in[22];
    const float* bm2  = (const float*)d_in[23];

    float* out = (float*)d_out;

    float* p_hW1h  = nullptr; cudaGetSymbolAddress((void**)&p_hW1h,  g_hW1h);
    float* p_D1    = nullptr; cudaGetSymbolAddress((void**)&p_D1,    g_D1);

    cudaFuncSetAttribute(hgemm_gates, cudaFuncAttributeMaxDynamicSharedMemorySize, GT_DYN);
    cudaFuncSetAttribute(hgemm_hw1h,  cudaFuncAttributeMaxDynamicSharedMemorySize, HW_DYN);
    cudaFuncSetAttribute(hgemm_x1,    cudaFuncAttributeMaxDynamicSharedMemorySize, X1_DYN);
    cudaFuncSetAttribute(gemm2_f16,   cudaFuncAttributeMaxDynamicSharedMemorySize, G2_DYN);
    cudaFuncSetAttribute(hgemm_d1,    cudaFuncAttributeMaxDynamicSharedMemorySize, D1_DYN);

    init_kernel<<<(MLPD*DHK + 255)/256, 256>>>(hh, ch, last_pos,
                                               W_ih, W_hh, b_ih, b_hh, W1, W2, Wm1);
    decall_kernel<<<(SEQ_LEN*BATCH*ED + 255)/256, 256>>>(last_pos_rel, pred_traj_rel, Wse, bse);

    for (int t = 0; t < SEQ_LEN; t++) {
        const float* gt = pred_traj_rel + t * BATCH * 2;
        float* out_pred = out + t * BATCH * 2;

        // LSTM cell: HMMA gates (reads post-MLP h limbs) -> fused elementwise/pos/loss
        hgemm_gates<<<dim3(GATES/128, BATCH/64), 256, GT_DYN>>>(t);
        lstm_pos_kernel<<<BATCH, HD>>>(Wpos, bpos, gt, out_pred);

        // pool net (uses pre-MLP h limbs written by lstm_pos)
        emb_kernel<<<(ROWS_PN*ED + 255)/256, 256>>>(Wp, bp);
        hgemm_hw1h<<<dim3(PRE/128, BATCH/64), 256, HW_DYN>>>();
        hgemm_x1<<<dim3(PRE/128, ROWS_PN/256), 256, X1_DYN>>>(b1, p_hW1h);
        gemm2_f16<<<dim3(BOTTLE/128, ROWS_PN/256), 256, G2_DYN>>>(b2);

        // decoder MLP; D2 emits post-MLP h (fp32 + fp16 limbs) for next step's gates
        hgemm_d1<<<dim3(MLPD/128, BATCH/64), 256, D1_DYN>>>(bm1);
        d2_kernel<<<dim3(HD/64, BATCH/64), 256>>>(p_D1, Wm2, bm2);
    }

    finish_kernel<<<1, BATCH>>>(out, out_size);
}